// round 1
// baseline (speedup 1.0000x reference)
#include <cuda_runtime.h>

// Problem constants
#define B_  4
#define S_  2048
#define D_  1024
#define H_  16
#define DK_ 64

// Scratch: 4 x 32 MB device globals (no dynamic allocation allowed)
__device__ float g_Q[B_ * H_ * S_ * DK_];   // [B,H,S,DK]
__device__ float g_K[B_ * H_ * S_ * DK_];
__device__ float g_V[B_ * H_ * S_ * DK_];
__device__ float g_C[B_ * S_ * D_];         // context in [B,S,D]

// ---------------------------------------------------------------------------
// SGEMM: C = A @ W^T.  A [M,K] row-major, W [N,K] row-major.
// 128x128 tile, BK=8, 256 threads, 8x8 per thread.
// MODE 0: C row-major [M,N].
// MODE 1: split-heads write: row m=(b*S+s), col n=(h*DK+dk) -> C[b,h,s,dk].
// ---------------------------------------------------------------------------
template <int MODE>
__global__ __launch_bounds__(256) void sgemm_wt(
    const float* __restrict__ A, const float* __restrict__ W,
    float* __restrict__ C, int M, int N, int K)
{
    __shared__ float As[8][132];
    __shared__ float Bs[8][132];

    const int tid = threadIdx.x;
    const int bm  = blockIdx.y * 128;
    const int bn  = blockIdx.x * 128;
    const int tr  = (tid >> 4) << 3;     // 0..120
    const int tc  = (tid & 15) << 3;

    const int lr = tid >> 1;             // 0..127
    const int lc = (tid & 1) << 2;       // 0 or 4

    float acc[8][8];
#pragma unroll
    for (int i = 0; i < 8; ++i)
#pragma unroll
        for (int j = 0; j < 8; ++j) acc[i][j] = 0.f;

    const float* Ap = A + (size_t)(bm + lr) * K + lc;
    const float* Wp = W + (size_t)(bn + lr) * K + lc;

    for (int k0 = 0; k0 < K; k0 += 8) {
        float4 a4 = *(const float4*)(Ap + k0);
        float4 w4 = *(const float4*)(Wp + k0);
        As[lc + 0][lr] = a4.x; As[lc + 1][lr] = a4.y;
        As[lc + 2][lr] = a4.z; As[lc + 3][lr] = a4.w;
        Bs[lc + 0][lr] = w4.x; Bs[lc + 1][lr] = w4.y;
        Bs[lc + 2][lr] = w4.z; Bs[lc + 3][lr] = w4.w;
        __syncthreads();

#pragma unroll
        for (int k = 0; k < 8; ++k) {
            float4 a0 = *(const float4*)&As[k][tr];
            float4 a1 = *(const float4*)&As[k][tr + 4];
            float4 b0 = *(const float4*)&Bs[k][tc];
            float4 b1 = *(const float4*)&Bs[k][tc + 4];
            float ra[8] = {a0.x, a0.y, a0.z, a0.w, a1.x, a1.y, a1.z, a1.w};
            float rb[8] = {b0.x, b0.y, b0.z, b0.w, b1.x, b1.y, b1.z, b1.w};
#pragma unroll
            for (int i = 0; i < 8; ++i)
#pragma unroll
                for (int j = 0; j < 8; ++j)
                    acc[i][j] += ra[i] * rb[j];
        }
        __syncthreads();
    }

    if (MODE == 0) {
#pragma unroll
        for (int i = 0; i < 8; ++i) {
            float* cp = C + (size_t)(bm + tr + i) * N + bn + tc;
            *(float4*)(cp)     = make_float4(acc[i][0], acc[i][1], acc[i][2], acc[i][3]);
            *(float4*)(cp + 4) = make_float4(acc[i][4], acc[i][5], acc[i][6], acc[i][7]);
        }
    } else {
#pragma unroll
        for (int i = 0; i < 8; ++i) {
            const int m  = bm + tr + i;
            const int b  = m >> 11;            // / S_
            const int s  = m & (S_ - 1);
            const int n0 = bn + tc;
            const int h  = n0 >> 6;            // / DK_
            const int dk = n0 & (DK_ - 1);     // 8-aligned, stays inside one head
            float* cp = C + (((size_t)(b * H_ + h) * S_ + s) * DK_ + dk);
            *(float4*)(cp)     = make_float4(acc[i][0], acc[i][1], acc[i][2], acc[i][3]);
            *(float4*)(cp + 4) = make_float4(acc[i][4], acc[i][5], acc[i][6], acc[i][7]);
        }
    }
}

// ---------------------------------------------------------------------------
// Scores: attn_raw[bh, q, k] = Q[bh,q,:]·K[bh,k,:] * (1/8), causal tiles only.
// Grid: (S/64 kt, S/64 qt, B*H). 64x64 tile, 4x4 per thread.
// ---------------------------------------------------------------------------
__global__ __launch_bounds__(256) void scores_kernel(float* __restrict__ attn)
{
    const int kt = blockIdx.x, qt = blockIdx.y, bh = blockIdx.z;
    if (kt > qt) return;

    __shared__ float Qs[64][65];
    __shared__ float Ks[64][65];

    const int tid = threadIdx.x;
    const float* Qb = g_Q + (size_t)bh * S_ * DK_ + (size_t)qt * 64 * DK_;
    const float* Kb = g_K + (size_t)bh * S_ * DK_ + (size_t)kt * 64 * DK_;

#pragma unroll
    for (int t = 0; t < 4; ++t) {
        const int idx = tid + t * 256;       // 0..1023 float4 slots
        const int r = idx >> 4;              // 16 float4 per 64-float row
        const int c = (idx & 15) << 2;
        float4 q4 = *(const float4*)(Qb + r * DK_ + c);
        float4 k4 = *(const float4*)(Kb + r * DK_ + c);
        Qs[r][c] = q4.x; Qs[r][c + 1] = q4.y; Qs[r][c + 2] = q4.z; Qs[r][c + 3] = q4.w;
        Ks[r][c] = k4.x; Ks[r][c + 1] = k4.y; Ks[r][c + 2] = k4.z; Ks[r][c + 3] = k4.w;
    }
    __syncthreads();

    const int tr = (tid >> 4) << 2;
    const int tc = (tid & 15) << 2;
    float acc[4][4] = {};

#pragma unroll 8
    for (int k = 0; k < 64; ++k) {
        float ra[4], rb[4];
#pragma unroll
        for (int i = 0; i < 4; ++i) ra[i] = Qs[tr + i][k];
#pragma unroll
        for (int j = 0; j < 4; ++j) rb[j] = Ks[tc + j][k];
#pragma unroll
        for (int i = 0; i < 4; ++i)
#pragma unroll
            for (int j = 0; j < 4; ++j)
                acc[i][j] += ra[i] * rb[j];
    }

    const float scale = 0.125f;  // 1/sqrt(64)
#pragma unroll
    for (int i = 0; i < 4; ++i) {
        float* rowp = attn + ((size_t)bh * S_ + (size_t)qt * 64 + tr + i) * S_
                           + (size_t)kt * 64 + tc;
        *(float4*)rowp = make_float4(acc[i][0] * scale, acc[i][1] * scale,
                                     acc[i][2] * scale, acc[i][3] * scale);
    }
}

// ---------------------------------------------------------------------------
// Causal softmax in-place over attn rows. One block (256 thr) per row.
// Writes exact 0.0 for masked columns (matches exp(-1e9-max) underflow).
// ---------------------------------------------------------------------------
__global__ __launch_bounds__(256) void softmax_kernel(float* __restrict__ attn)
{
    const int ro = blockIdx.x;           // bh*S + q
    const int q  = ro & (S_ - 1);
    const int n  = q + 1;
    float* p = attn + (size_t)ro * S_;
    const int tid = threadIdx.x;

    __shared__ float sm[256];

    float m = -3.0e38f;
    for (int i = tid; i < n; i += 256) m = fmaxf(m, p[i]);
    sm[tid] = m; __syncthreads();
    for (int o = 128; o > 0; o >>= 1) {
        if (tid < o) sm[tid] = fmaxf(sm[tid], sm[tid + o]);
        __syncthreads();
    }
    const float rowmax = sm[0];
    __syncthreads();

    float sum = 0.f;
    for (int i = tid; i < n; i += 256) sum += __expf(p[i] - rowmax);
    sm[tid] = sum; __syncthreads();
    for (int o = 128; o > 0; o >>= 1) {
        if (tid < o) sm[tid] += sm[tid + o];
        __syncthreads();
    }
    const float inv = 1.f / sm[0];

    for (int i = tid; i < n; i += 256) p[i] = __expf(p[i] - rowmax) * inv;
    for (int i = n + tid; i < S_; i += 256) p[i] = 0.f;
}

// ---------------------------------------------------------------------------
// Context: Ctx[b, s, h*64+dk] = sum_k attn[bh,s,k] * V[bh,k,dk], causal k-range.
// Grid: (S/64 qt, B*H). 64 q-rows x 64 dk-cols per block, 4x4 per thread.
// ---------------------------------------------------------------------------
__global__ __launch_bounds__(256) void context_kernel(const float* __restrict__ attn)
{
    const int qt = blockIdx.x, bh = blockIdx.y;
    const int b = bh >> 4, h = bh & (H_ - 1);

    __shared__ float As[64][65];
    __shared__ float Vs[64][65];

    const int tid = threadIdx.x;
    const int tr = (tid >> 4) << 2;
    const int tc = (tid & 15) << 2;
    float acc[4][4] = {};

    const float* arow = attn + ((size_t)bh * S_ + (size_t)qt * 64) * S_;
    const float* Vb   = g_V + (size_t)bh * S_ * DK_;

    for (int kt = 0; kt <= qt; ++kt) {
#pragma unroll
        for (int t = 0; t < 4; ++t) {
            const int idx = tid + t * 256;
            const int r = idx >> 4;
            const int c = (idx & 15) << 2;
            float4 a4 = *(const float4*)(arow + (size_t)r * S_ + kt * 64 + c);
            float4 v4 = *(const float4*)(Vb + (size_t)(kt * 64 + r) * DK_ + c);
            As[r][c] = a4.x; As[r][c + 1] = a4.y; As[r][c + 2] = a4.z; As[r][c + 3] = a4.w;
            Vs[r][c] = v4.x; Vs[r][c + 1] = v4.y; Vs[r][c + 2] = v4.z; Vs[r][c + 3] = v4.w;
        }
        __syncthreads();

#pragma unroll 8
        for (int k = 0; k < 64; ++k) {
            float ra[4], rb[4];
#pragma unroll
            for (int i = 0; i < 4; ++i) ra[i] = As[tr + i][k];
#pragma unroll
            for (int j = 0; j < 4; ++j) rb[j] = Vs[k][tc + j];
#pragma unroll
            for (int i = 0; i < 4; ++i)
#pragma unroll
                for (int j = 0; j < 4; ++j)
                    acc[i][j] += ra[i] * rb[j];
        }
        __syncthreads();
    }

#pragma unroll
    for (int i = 0; i < 4; ++i) {
        const int s = qt * 64 + tr + i;
        float* cp = g_C + ((size_t)b * S_ + s) * D_ + h * DK_ + tc;
        *(float4*)cp = make_float4(acc[i][0], acc[i][1], acc[i][2], acc[i][3]);
    }
}

// ---------------------------------------------------------------------------
// Launch: proj Q/K/V -> scores -> softmax -> context -> output proj
// Inputs: query, key, value, mask(unused), W_q, W_k, W_v, W_o
// Output: [output (B*S*D) | attn (B*H*S*S)] fp32
// ---------------------------------------------------------------------------
extern "C" void kernel_launch(void* const* d_in, const int* in_sizes, int n_in,
                              void* d_out, int out_size)
{
    const float* q  = (const float*)d_in[0];
    const float* k  = (const float*)d_in[1];
    const float* v  = (const float*)d_in[2];
    const float* Wq = (const float*)d_in[4];
    const float* Wk = (const float*)d_in[5];
    const float* Wv = (const float*)d_in[6];
    const float* Wo = (const float*)d_in[7];

    float* out  = (float*)d_out;
    float* attn = out + (size_t)B_ * S_ * D_;

    float *gQ, *gK, *gV, *gC;
    cudaGetSymbolAddress((void**)&gQ, g_Q);
    cudaGetSymbolAddress((void**)&gK, g_K);
    cudaGetSymbolAddress((void**)&gV, g_V);
    cudaGetSymbolAddress((void**)&gC, g_C);

    const int M = B_ * S_;              // 8192
    dim3 gProj(D_ / 128, M / 128);      // (8, 64)
    dim3 blk(256);

    sgemm_wt<1><<<gProj, blk>>>(q, Wq, gQ, M, D_, D_);
    sgemm_wt<1><<<gProj, blk>>>(k, Wk, gK, M, D_, D_);
    sgemm_wt<1><<<gProj, blk>>>(v, Wv, gV, M, D_, D_);

    dim3 gScores(S_ / 64, S_ / 64, B_ * H_);   // (32, 32, 64)
    scores_kernel<<<gScores, blk>>>(attn);

    softmax_kernel<<<B_ * H_ * S_, blk>>>(attn);

    dim3 gCtx(S_ / 64, B_ * H_);               // (32, 64)
    context_kernel<<<gCtx, blk>>>(attn);

    sgemm_wt<0><<<gProj, blk>>>(gC, Wo, out, M, D_, D_);
}

// round 3
// speedup vs baseline: 1.9969x; 1.9969x over previous
#include <cuda_runtime.h>
#include <cuda_bf16.h>
#include <cstdint>

#define B_  4
#define S_  2048
#define D_  1024
#define H_  16
#define DK_ 64
#define MM_ (B_ * S_)          // 8192

// ---------------------------------------------------------------------------
// Scratch (device globals)
// ---------------------------------------------------------------------------
__device__ __nv_bfloat16 g_qhi[MM_ * D_], g_qlo[MM_ * D_];
__device__ __nv_bfloat16 g_khi[MM_ * D_], g_klo[MM_ * D_];
__device__ __nv_bfloat16 g_vhi[MM_ * D_], g_vlo[MM_ * D_];
__device__ __nv_bfloat16 g_whi[4][D_ * D_], g_wlo[4][D_ * D_];
__device__ __nv_bfloat16 g_Qhi[MM_ * D_], g_Qlo[MM_ * D_];   // [B,H,S,DK]
__device__ __nv_bfloat16 g_Khi[MM_ * D_], g_Klo[MM_ * D_];
__device__ __nv_bfloat16 g_Vhi[MM_ * D_], g_Vlo[MM_ * D_];
__device__ __nv_bfloat16 g_Chi[MM_ * D_], g_Clo[MM_ * D_];   // [B,S,D]

// ---------------------------------------------------------------------------
// MMA / ldmatrix helpers (sm_80-era PTX, valid on base sm_103)
// ---------------------------------------------------------------------------
__device__ __forceinline__ void ldsm4(uint32_t addr, uint32_t* r) {
    asm volatile("ldmatrix.sync.aligned.m8n8.x4.shared.b16 {%0,%1,%2,%3}, [%4];"
        : "=r"(r[0]), "=r"(r[1]), "=r"(r[2]), "=r"(r[3]) : "r"(addr));
}
__device__ __forceinline__ void ldsm4t(uint32_t addr, uint32_t* r) {
    asm volatile("ldmatrix.sync.aligned.m8n8.x4.trans.shared.b16 {%0,%1,%2,%3}, [%4];"
        : "=r"(r[0]), "=r"(r[1]), "=r"(r[2]), "=r"(r[3]) : "r"(addr));
}
__device__ __forceinline__ void mma_bf16(float* c, const uint32_t* a, uint32_t b0, uint32_t b1) {
    asm volatile("mma.sync.aligned.m16n8k16.row.col.f32.bf16.bf16.f32 "
        "{%0,%1,%2,%3}, {%4,%5,%6,%7}, {%8,%9}, {%0,%1,%2,%3};"
        : "+f"(c[0]), "+f"(c[1]), "+f"(c[2]), "+f"(c[3])
        : "r"(a[0]), "r"(a[1]), "r"(a[2]), "r"(a[3]), "r"(b0), "r"(b1));
}
__device__ __forceinline__ uint32_t sptr(const void* p) {
    return (uint32_t)__cvta_generic_to_shared(p);
}

// ---------------------------------------------------------------------------
// Split fp32 -> (hi, lo) bf16
// ---------------------------------------------------------------------------
__global__ __launch_bounds__(256) void split_kernel(
    const float* __restrict__ x, __nv_bfloat16* __restrict__ hi,
    __nv_bfloat16* __restrict__ lo, int n4)
{
    int i = blockIdx.x * blockDim.x + threadIdx.x;
    if (i >= n4) return;
    float4 v = ((const float4*)x)[i];
    __nv_bfloat16 h0 = __float2bfloat16(v.x), h1 = __float2bfloat16(v.y);
    __nv_bfloat16 h2 = __float2bfloat16(v.z), h3 = __float2bfloat16(v.w);
    __nv_bfloat162 ph0; ph0.x = h0; ph0.y = h1;
    __nv_bfloat162 ph1; ph1.x = h2; ph1.y = h3;
    __nv_bfloat162 pl0; pl0.x = __float2bfloat16(v.x - __bfloat162float(h0));
    pl0.y = __float2bfloat16(v.y - __bfloat162float(h1));
    __nv_bfloat162 pl1; pl1.x = __float2bfloat16(v.z - __bfloat162float(h2));
    pl1.y = __float2bfloat16(v.w - __bfloat162float(h3));
    ((__nv_bfloat162*)hi)[2 * i]     = ph0;
    ((__nv_bfloat162*)hi)[2 * i + 1] = ph1;
    ((__nv_bfloat162*)lo)[2 * i]     = pl0;
    ((__nv_bfloat162*)lo)[2 * i + 1] = pl1;
}

// ---------------------------------------------------------------------------
// bf16x3 GEMM via mma.sync: C = A @ W^T.  A [8192,1024], W [1024,1024].
// 128x128 tile, BK=32, 256 thr (8 warps, each 64x32).
// MODE 0: fp32 row-major out.  MODE 1: bf16 hi/lo out at [B,H,S,DK].
// ---------------------------------------------------------------------------
template <int MODE>
__global__ __launch_bounds__(256, 1) void mm_tc(
    const __nv_bfloat16* __restrict__ Ahi, const __nv_bfloat16* __restrict__ Alo,
    const __nv_bfloat16* __restrict__ Whi, const __nv_bfloat16* __restrict__ Wlo,
    float* __restrict__ Cf,
    __nv_bfloat16* __restrict__ Ohi, __nv_bfloat16* __restrict__ Olo)
{
    __shared__ __align__(16) __nv_bfloat16 sA[2][128 * 40];
    __shared__ __align__(16) __nv_bfloat16 sW[2][128 * 40];

    const int tid = threadIdx.x, lane = tid & 31, wid = tid >> 5;
    const int bm = blockIdx.y * 128, bn = blockIdx.x * 128;
    const int wm = (wid >> 2) * 64, wn = (wid & 3) * 32;

    float acc[4][4][4];
#pragma unroll
    for (int a = 0; a < 4; ++a)
#pragma unroll
        for (int b = 0; b < 4; ++b)
#pragma unroll
            for (int c = 0; c < 4; ++c) acc[a][b][c] = 0.f;

    const int grp = lane >> 3, koff = (grp & 1) << 3, nb = (grp >> 1) << 3, nr = lane & 7;

    for (int it = 0; it < 32; ++it) {
        const int k0 = it * 32;
#pragma unroll
        for (int t = 0; t < 2; ++t) {
            const int idx = tid + t * 256;
            const int row = idx >> 2, c8 = (idx & 3) << 3;
            const size_t ga = (size_t)(bm + row) * D_ + k0 + c8;
            const size_t gw = (size_t)(bn + row) * D_ + k0 + c8;
            const int so = row * 40 + c8;
            *(uint4*)&sA[0][so] = *(const uint4*)(Ahi + ga);
            *(uint4*)&sA[1][so] = *(const uint4*)(Alo + ga);
            *(uint4*)&sW[0][so] = *(const uint4*)(Whi + gw);
            *(uint4*)&sW[1][so] = *(const uint4*)(Wlo + gw);
        }
        __syncthreads();

#pragma unroll
        for (int kk = 0; kk < 2; ++kk) {
            uint32_t aH[4][4], aL[4][4];
#pragma unroll
            for (int mt = 0; mt < 4; ++mt) {
                const int r = wm + mt * 16 + (lane & 15);
                const int c = kk * 16 + ((lane >> 4) << 3);
                ldsm4(sptr(&sA[0][r * 40 + c]), aH[mt]);
                ldsm4(sptr(&sA[1][r * 40 + c]), aL[mt]);
            }
            uint32_t bH[2][4], bL[2][4];
#pragma unroll
            for (int np = 0; np < 2; ++np) {
                const int n = wn + np * 16 + nb + nr;
                const int c = kk * 16 + koff;
                ldsm4(sptr(&sW[0][n * 40 + c]), bH[np]);
                ldsm4(sptr(&sW[1][n * 40 + c]), bL[np]);
            }
#pragma unroll
            for (int mt = 0; mt < 4; ++mt)
#pragma unroll
                for (int np = 0; np < 2; ++np)
#pragma unroll
                    for (int j = 0; j < 2; ++j) {
                        const int nt = np * 2 + j;
                        mma_bf16(acc[mt][nt], aH[mt], bH[np][2 * j], bH[np][2 * j + 1]);
                        mma_bf16(acc[mt][nt], aH[mt], bL[np][2 * j], bL[np][2 * j + 1]);
                        mma_bf16(acc[mt][nt], aL[mt], bH[np][2 * j], bH[np][2 * j + 1]);
                    }
        }
        __syncthreads();
    }

#pragma unroll
    for (int mt = 0; mt < 4; ++mt)
#pragma unroll
        for (int nt = 0; nt < 4; ++nt) {
            const float* c = acc[mt][nt];
            const int n = bn + wn + nt * 8 + ((lane & 3) << 1);
#pragma unroll
            for (int hf = 0; hf < 2; ++hf) {
                const int m = bm + wm + mt * 16 + (lane >> 2) + hf * 8;
                const float x0 = c[hf * 2], x1 = c[hf * 2 + 1];
                if (MODE == 0) {
                    *(float2*)(Cf + (size_t)m * D_ + n) = make_float2(x0, x1);
                } else {
                    const int b = m >> 11, s = m & (S_ - 1);
                    const int h = n >> 6, dk = n & (DK_ - 1);
                    const size_t o = (((size_t)(b * H_ + h) * S_ + s) << 6) + dk;
                    __nv_bfloat16 h0 = __float2bfloat16(x0), h1 = __float2bfloat16(x1);
                    __nv_bfloat162 ph; ph.x = h0; ph.y = h1;
                    __nv_bfloat162 pl;
                    pl.x = __float2bfloat16(x0 - __bfloat162float(h0));
                    pl.y = __float2bfloat16(x1 - __bfloat162float(h1));
                    *(__nv_bfloat162*)(Ohi + o) = ph;
                    *(__nv_bfloat162*)(Olo + o) = pl;
                }
            }
        }
}

// ---------------------------------------------------------------------------
// Scores: attn[bh,q,k] = (Q·K)/8 on causal tiles, bf16x3 mma. Block 128 thr.
// ---------------------------------------------------------------------------
__global__ __launch_bounds__(128, 1) void scores_tc(float* __restrict__ attn)
{
    const int kt = blockIdx.x, qt = blockIdx.y, bh = blockIdx.z;
    if (kt > qt) return;

    __shared__ __align__(16) __nv_bfloat16 sQ[2][64 * 72];
    __shared__ __align__(16) __nv_bfloat16 sK[2][64 * 72];

    const int tid = threadIdx.x, lane = tid & 31, w = tid >> 5;

#pragma unroll
    for (int t = 0; t < 4; ++t) {
        const int idx = tid + t * 128;
        const int row = idx >> 3, c8 = (idx & 7) << 3;
        const size_t gq = ((size_t)(bh * S_ + qt * 64 + row) << 6) + c8;
        const size_t gk = ((size_t)(bh * S_ + kt * 64 + row) << 6) + c8;
        const int so = row * 72 + c8;
        *(uint4*)&sQ[0][so] = *(const uint4*)(g_Qhi + gq);
        *(uint4*)&sQ[1][so] = *(const uint4*)(g_Qlo + gq);
        *(uint4*)&sK[0][so] = *(const uint4*)(g_Khi + gk);
        *(uint4*)&sK[1][so] = *(const uint4*)(g_Klo + gk);
    }
    __syncthreads();

    float acc[8][4];
#pragma unroll
    for (int a = 0; a < 8; ++a)
#pragma unroll
        for (int b = 0; b < 4; ++b) acc[a][b] = 0.f;

    const int grp = lane >> 3, koff = (grp & 1) << 3, nb = (grp >> 1) << 3, nr = lane & 7;
    const int qw = w * 16;

#pragma unroll
    for (int kk = 0; kk < 4; ++kk) {
        uint32_t aH[4], aL[4];
        {
            const int r = qw + (lane & 15);
            const int c = kk * 16 + ((lane >> 4) << 3);
            ldsm4(sptr(&sQ[0][r * 72 + c]), aH);
            ldsm4(sptr(&sQ[1][r * 72 + c]), aL);
        }
#pragma unroll
        for (int np = 0; np < 4; ++np) {
            uint32_t bH[4], bL[4];
            const int n = np * 16 + nb + nr;
            const int c = kk * 16 + koff;
            ldsm4(sptr(&sK[0][n * 72 + c]), bH);
            ldsm4(sptr(&sK[1][n * 72 + c]), bL);
#pragma unroll
            for (int j = 0; j < 2; ++j) {
                const int nt = np * 2 + j;
                mma_bf16(acc[nt], aH, bH[2 * j], bH[2 * j + 1]);
                mma_bf16(acc[nt], aH, bL[2 * j], bL[2 * j + 1]);
                mma_bf16(acc[nt], aL, bH[2 * j], bH[2 * j + 1]);
            }
        }
    }

    const float sc = 0.125f;
#pragma unroll
    for (int nt = 0; nt < 8; ++nt) {
        const int kcol = kt * 64 + nt * 8 + ((lane & 3) << 1);
#pragma unroll
        for (int hf = 0; hf < 2; ++hf) {
            const int q = qt * 64 + qw + (lane >> 2) + hf * 8;
            float* p = attn + ((size_t)bh * S_ + q) * S_ + kcol;
            *(float2*)p = make_float2(acc[nt][hf * 2] * sc, acc[nt][hf * 2 + 1] * sc);
        }
    }
}

// ---------------------------------------------------------------------------
// Causal softmax, row cached in smem. One block (256 thr) per row.
// ---------------------------------------------------------------------------
__global__ __launch_bounds__(256) void softmax_kernel(float* __restrict__ attn)
{
    __shared__ float row[S_];
    __shared__ float red[256];

    const int ro = blockIdx.x;
    const int q  = ro & (S_ - 1);
    const int n  = q + 1;
    float* p = attn + (size_t)ro * S_;
    const int tid = threadIdx.x;

    float m = -3.0e38f;
    for (int i = tid; i < n; i += 256) { float x = p[i]; row[i] = x; m = fmaxf(m, x); }
    red[tid] = m; __syncthreads();
    for (int o = 128; o > 0; o >>= 1) {
        if (tid < o) red[tid] = fmaxf(red[tid], red[tid + o]);
        __syncthreads();
    }
    const float rowmax = red[0];
    __syncthreads();

    float sum = 0.f;
    for (int i = tid; i < n; i += 256) { float e = __expf(row[i] - rowmax); row[i] = e; sum += e; }
    red[tid] = sum; __syncthreads();
    for (int o = 128; o > 0; o >>= 1) {
        if (tid < o) red[tid] += red[tid + o];
        __syncthreads();
    }
    const float inv = 1.f / red[0];

    for (int i = tid; i < n; i += 256) p[i] = row[i] * inv;
    for (int i = n + tid; i < S_; i += 256) p[i] = 0.f;
}

// ---------------------------------------------------------------------------
// Context: C[q,dk] = sum_k attn[q,k] * V[k,dk], causal, bf16x3 mma.
// attn fp32 -> hi/lo in registers while staging smem. Block 128 thr.
// Output written directly as bf16 hi/lo at [B,S,D] for the final GEMM.
// ---------------------------------------------------------------------------
__global__ __launch_bounds__(128, 1) void context_tc(const float* __restrict__ attn)
{
    const int qt = blockIdx.x, bh = blockIdx.y;
    const int b = bh >> 4, h = bh & (H_ - 1);

    __shared__ __align__(16) __nv_bfloat16 sA[2][64 * 72];
    __shared__ __align__(16) __nv_bfloat16 sV[2][64 * 72];

    const int tid = threadIdx.x, lane = tid & 31, w = tid >> 5;
    const int grp = lane >> 3, koff = (grp & 1) << 3, nb = (grp >> 1) << 3, nr = lane & 7;
    const int qw = w * 16;

    float acc[8][4];
#pragma unroll
    for (int a = 0; a < 8; ++a)
#pragma unroll
        for (int c = 0; c < 4; ++c) acc[a][c] = 0.f;

    const float* arow = attn + ((size_t)bh * S_ + qt * 64) * S_;

    for (int kt = 0; kt <= qt; ++kt) {
#pragma unroll
        for (int t = 0; t < 8; ++t) {
            const int idx = tid + t * 128;            // 0..1023
            const int row = idx >> 4, c4 = (idx & 15) << 2;
            float4 v = *(const float4*)(arow + (size_t)row * S_ + kt * 64 + c4);
            __nv_bfloat162 h01, h23, l01, l23;
            h01.x = __float2bfloat16(v.x); h01.y = __float2bfloat16(v.y);
            h23.x = __float2bfloat16(v.z); h23.y = __float2bfloat16(v.w);
            l01.x = __float2bfloat16(v.x - __bfloat162float(h01.x));
            l01.y = __float2bfloat16(v.y - __bfloat162float(h01.y));
            l23.x = __float2bfloat16(v.z - __bfloat162float(h23.x));
            l23.y = __float2bfloat16(v.w - __bfloat162float(h23.y));
            const int so = row * 72 + c4;
            *(__nv_bfloat162*)&sA[0][so]     = h01;
            *(__nv_bfloat162*)&sA[0][so + 2] = h23;
            *(__nv_bfloat162*)&sA[1][so]     = l01;
            *(__nv_bfloat162*)&sA[1][so + 2] = l23;
        }
#pragma unroll
        for (int t = 0; t < 4; ++t) {
            const int idx = tid + t * 128;
            const int row = idx >> 3, c8 = (idx & 7) << 3;
            const size_t gv = ((size_t)(bh * S_ + kt * 64 + row) << 6) + c8;
            const int so = row * 72 + c8;
            *(uint4*)&sV[0][so] = *(const uint4*)(g_Vhi + gv);
            *(uint4*)&sV[1][so] = *(const uint4*)(g_Vlo + gv);
        }
        __syncthreads();

#pragma unroll
        for (int kk = 0; kk < 4; ++kk) {
            uint32_t aH[4], aL[4];
            {
                const int r = qw + (lane & 15);
                const int c = kk * 16 + ((lane >> 4) << 3);
                ldsm4(sptr(&sA[0][r * 72 + c]), aH);
                ldsm4(sptr(&sA[1][r * 72 + c]), aL);
            }
#pragma unroll
            for (int np = 0; np < 4; ++np) {
                uint32_t bH[4], bL[4];
                const int kr = kk * 16 + koff + nr;      // sV row = k
                const int nc = np * 16 + nb;             // sV col = dk
                ldsm4t(sptr(&sV[0][kr * 72 + nc]), bH);
                ldsm4t(sptr(&sV[1][kr * 72 + nc]), bL);
#pragma unroll
                for (int j = 0; j < 2; ++j) {
                    const int nt = np * 2 + j;
                    mma_bf16(acc[nt], aH, bH[2 * j], bH[2 * j + 1]);
                    mma_bf16(acc[nt], aH, bL[2 * j], bL[2 * j + 1]);
                    mma_bf16(acc[nt], aL, bH[2 * j], bH[2 * j + 1]);
                }
            }
        }
        __syncthreads();
    }

#pragma unroll
    for (int nt = 0; nt < 8; ++nt) {
        const int d = h * DK_ + nt * 8 + ((lane & 3) << 1);
#pragma unroll
        for (int hf = 0; hf < 2; ++hf) {
            const int s = qt * 64 + qw + (lane >> 2) + hf * 8;
            const float x0 = acc[nt][hf * 2], x1 = acc[nt][hf * 2 + 1];
            const size_t o = ((size_t)b * S_ + s) * D_ + d;
            __nv_bfloat162 ph, pl;
            ph.x = __float2bfloat16(x0); ph.y = __float2bfloat16(x1);
            pl.x = __float2bfloat16(x0 - __bfloat162float(ph.x));
            pl.y = __float2bfloat16(x1 - __bfloat162float(ph.y));
            *(__nv_bfloat162*)(g_Chi + o) = ph;
            *(__nv_bfloat162*)(g_Clo + o) = pl;
        }
    }
}

// ---------------------------------------------------------------------------
// Launch
// ---------------------------------------------------------------------------
extern "C" void kernel_launch(void* const* d_in, const int* in_sizes, int n_in,
                              void* d_out, int out_size)
{
    const float* q = (const float*)d_in[0];
    const float* k = (const float*)d_in[1];
    const float* v = (const float*)d_in[2];
    const float* W[4] = { (const float*)d_in[4], (const float*)d_in[5],
                          (const float*)d_in[6], (const float*)d_in[7] };

    float* out  = (float*)d_out;
    float* attn = out + (size_t)B_ * S_ * D_;

    __nv_bfloat16 *qhi, *qlo, *khi, *klo, *vhi, *vlo, *whi, *wlo;
    __nv_bfloat16 *Qhi, *Qlo, *Khi, *Klo, *Vhi, *Vlo, *Chi, *Clo;
    cudaGetSymbolAddress((void**)&qhi, g_qhi); cudaGetSymbolAddress((void**)&qlo, g_qlo);
    cudaGetSymbolAddress((void**)&khi, g_khi); cudaGetSymbolAddress((void**)&klo, g_klo);
    cudaGetSymbolAddress((void**)&vhi, g_vhi); cudaGetSymbolAddress((void**)&vlo, g_vlo);
    cudaGetSymbolAddress((void**)&whi, g_whi); cudaGetSymbolAddress((void**)&wlo, g_wlo);
    cudaGetSymbolAddress((void**)&Qhi, g_Qhi); cudaGetSymbolAddress((void**)&Qlo, g_Qlo);
    cudaGetSymbolAddress((void**)&Khi, g_Khi); cudaGetSymbolAddress((void**)&Klo, g_Klo);
    cudaGetSymbolAddress((void**)&Vhi, g_Vhi); cudaGetSymbolAddress((void**)&Vlo, g_Vlo);
    cudaGetSymbolAddress((void**)&Chi, g_Chi); cudaGetSymbolAddress((void**)&Clo, g_Clo);

    const int n4x = MM_ * D_ / 4;
    const int n4w = D_ * D_ / 4;
    split_kernel<<<(n4x + 255) / 256, 256>>>(q, qhi, qlo, n4x);
    split_kernel<<<(n4x + 255) / 256, 256>>>(k, khi, klo, n4x);
    split_kernel<<<(n4x + 255) / 256, 256>>>(v, vhi, vlo, n4x);
    for (int i = 0; i < 4; ++i)
        split_kernel<<<(n4w + 255) / 256, 256>>>(W[i], whi + (size_t)i * D_ * D_,
                                                 wlo + (size_t)i * D_ * D_, n4w);

    dim3 gG(D_ / 128, MM_ / 128);   // (8, 64)
    mm_tc<1><<<gG, 256>>>(qhi, qlo, whi + 0 * (size_t)D_ * D_, wlo + 0 * (size_t)D_ * D_,
                          nullptr, Qhi, Qlo);
    mm_tc<1><<<gG, 256>>>(khi, klo, whi + 1 * (size_t)D_ * D_, wlo + 1 * (size_t)D_ * D_,
                          nullptr, Khi, Klo);
    mm_tc<1><<<gG, 256>>>(vhi, vlo, whi + 2 * (size_t)D_ * D_, wlo + 2 * (size_t)D_ * D_,
                          nullptr, Vhi, Vlo);

    dim3 gScores(S_ / 64, S_ / 64, B_ * H_);
    scores_tc<<<gScores, 128>>>(attn);

    softmax_kernel<<<B_ * H_ * S_, 256>>>(attn);

    dim3 gCtx(S_ / 64, B_ * H_);
    context_tc<<<gCtx, 128>>>(attn);

    mm_tc<0><<<gG, 256>>>(Chi, Clo, whi + 3 * (size_t)D_ * D_, wlo + 3 * (size_t)D_ * D_,
                          out, nullptr, nullptr);
}

// round 4
// speedup vs baseline: 2.0487x; 1.0259x over previous
#include <cuda_runtime.h>
#include <cuda_bf16.h>
#include <cstdint>

#define B_  4
#define S_  2048
#define D_  1024
#define H_  16
#define DK_ 64
#define MM_ (B_ * S_)          // 8192

// ---------------------------------------------------------------------------
// Scratch (device globals)
// ---------------------------------------------------------------------------
__device__ __nv_bfloat16 g_qhi[MM_ * D_], g_qlo[MM_ * D_];
__device__ __nv_bfloat16 g_khi[MM_ * D_], g_klo[MM_ * D_];
__device__ __nv_bfloat16 g_vhi[MM_ * D_], g_vlo[MM_ * D_];
__device__ __nv_bfloat16 g_whi[4][D_ * D_], g_wlo[4][D_ * D_];
__device__ __nv_bfloat16 g_Qhi[MM_ * D_], g_Qlo[MM_ * D_];   // [B,H,S,DK]
__device__ __nv_bfloat16 g_Khi[MM_ * D_], g_Klo[MM_ * D_];
__device__ __nv_bfloat16 g_Vhi[MM_ * D_], g_Vlo[MM_ * D_];
__device__ __nv_bfloat16 g_Chi[MM_ * D_], g_Clo[MM_ * D_];   // [B,S,D]

// ---------------------------------------------------------------------------
// MMA / ldmatrix helpers (sm_80-era PTX, valid on base sm_103)
// ---------------------------------------------------------------------------
__device__ __forceinline__ void ldsm4(uint32_t addr, uint32_t* r) {
    asm volatile("ldmatrix.sync.aligned.m8n8.x4.shared.b16 {%0,%1,%2,%3}, [%4];"
        : "=r"(r[0]), "=r"(r[1]), "=r"(r[2]), "=r"(r[3]) : "r"(addr));
}
__device__ __forceinline__ void ldsm4t(uint32_t addr, uint32_t* r) {
    asm volatile("ldmatrix.sync.aligned.m8n8.x4.trans.shared.b16 {%0,%1,%2,%3}, [%4];"
        : "=r"(r[0]), "=r"(r[1]), "=r"(r[2]), "=r"(r[3]) : "r"(addr));
}
__device__ __forceinline__ void mma_bf16(float* c, const uint32_t* a, uint32_t b0, uint32_t b1) {
    asm volatile("mma.sync.aligned.m16n8k16.row.col.f32.bf16.bf16.f32 "
        "{%0,%1,%2,%3}, {%4,%5,%6,%7}, {%8,%9}, {%0,%1,%2,%3};"
        : "+f"(c[0]), "+f"(c[1]), "+f"(c[2]), "+f"(c[3])
        : "r"(a[0]), "r"(a[1]), "r"(a[2]), "r"(a[3]), "r"(b0), "r"(b1));
}
__device__ __forceinline__ uint32_t sptr(const void* p) {
    return (uint32_t)__cvta_generic_to_shared(p);
}
__device__ __forceinline__ uint32_t pack_bf16(float x, float y) {
    __nv_bfloat162 t; t.x = __float2bfloat16(x); t.y = __float2bfloat16(y);
    return *(uint32_t*)&t;
}

// ---------------------------------------------------------------------------
// Split fp32 -> (hi, lo) bf16
// ---------------------------------------------------------------------------
__global__ __launch_bounds__(256) void split_kernel(
    const float* __restrict__ x, __nv_bfloat16* __restrict__ hi,
    __nv_bfloat16* __restrict__ lo, int n4)
{
    int i = blockIdx.x * blockDim.x + threadIdx.x;
    if (i >= n4) return;
    float4 v = ((const float4*)x)[i];
    __nv_bfloat16 h0 = __float2bfloat16(v.x), h1 = __float2bfloat16(v.y);
    __nv_bfloat16 h2 = __float2bfloat16(v.z), h3 = __float2bfloat16(v.w);
    __nv_bfloat162 ph0; ph0.x = h0; ph0.y = h1;
    __nv_bfloat162 ph1; ph1.x = h2; ph1.y = h3;
    __nv_bfloat162 pl0; pl0.x = __float2bfloat16(v.x - __bfloat162float(h0));
    pl0.y = __float2bfloat16(v.y - __bfloat162float(h1));
    __nv_bfloat162 pl1; pl1.x = __float2bfloat16(v.z - __bfloat162float(h2));
    pl1.y = __float2bfloat16(v.w - __bfloat162float(h3));
    ((__nv_bfloat162*)hi)[2 * i]     = ph0;
    ((__nv_bfloat162*)hi)[2 * i + 1] = ph1;
    ((__nv_bfloat162*)lo)[2 * i]     = pl0;
    ((__nv_bfloat162*)lo)[2 * i + 1] = pl1;
}

// ---------------------------------------------------------------------------
// bf16x3 GEMM via mma.sync: C = A @ W^T (unchanged from R3)
// ---------------------------------------------------------------------------
template <int MODE>
__global__ __launch_bounds__(256, 1) void mm_tc(
    const __nv_bfloat16* __restrict__ Ahi, const __nv_bfloat16* __restrict__ Alo,
    const __nv_bfloat16* __restrict__ Whi, const __nv_bfloat16* __restrict__ Wlo,
    float* __restrict__ Cf,
    __nv_bfloat16* __restrict__ Ohi, __nv_bfloat16* __restrict__ Olo)
{
    __shared__ __align__(16) __nv_bfloat16 sA[2][128 * 40];
    __shared__ __align__(16) __nv_bfloat16 sW[2][128 * 40];

    const int tid = threadIdx.x, lane = tid & 31, wid = tid >> 5;
    const int bm = blockIdx.y * 128, bn = blockIdx.x * 128;
    const int wm = (wid >> 2) * 64, wn = (wid & 3) * 32;

    float acc[4][4][4];
#pragma unroll
    for (int a = 0; a < 4; ++a)
#pragma unroll
        for (int b = 0; b < 4; ++b)
#pragma unroll
            for (int c = 0; c < 4; ++c) acc[a][b][c] = 0.f;

    const int grp = lane >> 3, koff = (grp & 1) << 3, nb = (grp >> 1) << 3, nr = lane & 7;

    for (int it = 0; it < 32; ++it) {
        const int k0 = it * 32;
#pragma unroll
        for (int t = 0; t < 2; ++t) {
            const int idx = tid + t * 256;
            const int row = idx >> 2, c8 = (idx & 3) << 3;
            const size_t ga = (size_t)(bm + row) * D_ + k0 + c8;
            const size_t gw = (size_t)(bn + row) * D_ + k0 + c8;
            const int so = row * 40 + c8;
            *(uint4*)&sA[0][so] = *(const uint4*)(Ahi + ga);
            *(uint4*)&sA[1][so] = *(const uint4*)(Alo + ga);
            *(uint4*)&sW[0][so] = *(const uint4*)(Whi + gw);
            *(uint4*)&sW[1][so] = *(const uint4*)(Wlo + gw);
        }
        __syncthreads();

#pragma unroll
        for (int kk = 0; kk < 2; ++kk) {
            uint32_t aH[4][4], aL[4][4];
#pragma unroll
            for (int mt = 0; mt < 4; ++mt) {
                const int r = wm + mt * 16 + (lane & 15);
                const int c = kk * 16 + ((lane >> 4) << 3);
                ldsm4(sptr(&sA[0][r * 40 + c]), aH[mt]);
                ldsm4(sptr(&sA[1][r * 40 + c]), aL[mt]);
            }
            uint32_t bH[2][4], bL[2][4];
#pragma unroll
            for (int np = 0; np < 2; ++np) {
                const int n = wn + np * 16 + nb + nr;
                const int c = kk * 16 + koff;
                ldsm4(sptr(&sW[0][n * 40 + c]), bH[np]);
                ldsm4(sptr(&sW[1][n * 40 + c]), bL[np]);
            }
#pragma unroll
            for (int mt = 0; mt < 4; ++mt)
#pragma unroll
                for (int np = 0; np < 2; ++np)
#pragma unroll
                    for (int j = 0; j < 2; ++j) {
                        const int nt = np * 2 + j;
                        mma_bf16(acc[mt][nt], aH[mt], bH[np][2 * j], bH[np][2 * j + 1]);
                        mma_bf16(acc[mt][nt], aH[mt], bL[np][2 * j], bL[np][2 * j + 1]);
                        mma_bf16(acc[mt][nt], aL[mt], bH[np][2 * j], bH[np][2 * j + 1]);
                    }
        }
        __syncthreads();
    }

#pragma unroll
    for (int mt = 0; mt < 4; ++mt)
#pragma unroll
        for (int nt = 0; nt < 4; ++nt) {
            const float* c = acc[mt][nt];
            const int n = bn + wn + nt * 8 + ((lane & 3) << 1);
#pragma unroll
            for (int hf = 0; hf < 2; ++hf) {
                const int m = bm + wm + mt * 16 + (lane >> 2) + hf * 8;
                const float x0 = c[hf * 2], x1 = c[hf * 2 + 1];
                if (MODE == 0) {
                    *(float2*)(Cf + (size_t)m * D_ + n) = make_float2(x0, x1);
                } else {
                    const int b = m >> 11, s = m & (S_ - 1);
                    const int h = n >> 6, dk = n & (DK_ - 1);
                    const size_t o = (((size_t)(b * H_ + h) * S_ + s) << 6) + dk;
                    __nv_bfloat16 h0 = __float2bfloat16(x0), h1 = __float2bfloat16(x1);
                    __nv_bfloat162 ph; ph.x = h0; ph.y = h1;
                    __nv_bfloat162 pl;
                    pl.x = __float2bfloat16(x0 - __bfloat162float(h0));
                    pl.y = __float2bfloat16(x1 - __bfloat162float(h1));
                    *(__nv_bfloat162*)(Ohi + o) = ph;
                    *(__nv_bfloat162*)(Olo + o) = pl;
                }
            }
        }
}

// ---------------------------------------------------------------------------
// Fused flash attention: scores + softmax + context + attn output.
// Block: 256 thr (8 warps), 128 q-rows x (iterate 64-wide K tiles).
// Pass 1: online (m, l) stats. Pass 2: recompute S, write normalized P to
// attn (fp32), accumulate O += P @ V via bf16x3 mma (S-acc regs reused as
// A-fragments). O written as bf16 hi/lo to g_Chi/g_Clo [B,S,D].
// ---------------------------------------------------------------------------
struct SmemMap {
    __nv_bfloat16* Qh; __nv_bfloat16* Ql;
    __nv_bfloat16* Kh; __nv_bfloat16* Kl;
    __nv_bfloat16* Vh; __nv_bfloat16* Vl;
};

__device__ __forceinline__ void score_tile(
    const SmemMap& S, int lane, int wid, float acc[8][4])
{
#pragma unroll
    for (int a = 0; a < 8; ++a)
#pragma unroll
        for (int b = 0; b < 4; ++b) acc[a][b] = 0.f;

    const int grp = lane >> 3, koff = (grp & 1) << 3, nb = (grp >> 1) << 3, nr = lane & 7;
    const int r = wid * 16 + (lane & 15);
    const int ca = (lane >> 4) << 3;

#pragma unroll
    for (int kk = 0; kk < 4; ++kk) {
        uint32_t aH[4], aL[4];
        ldsm4(sptr(&S.Qh[r * 72 + kk * 16 + ca]), aH);
        ldsm4(sptr(&S.Ql[r * 72 + kk * 16 + ca]), aL);
#pragma unroll
        for (int np = 0; np < 4; ++np) {
            uint32_t bH[4], bL[4];
            const int n = np * 16 + nb + nr;
            const int cc = kk * 16 + koff;
            ldsm4(sptr(&S.Kh[n * 72 + cc]), bH);
            ldsm4(sptr(&S.Kl[n * 72 + cc]), bL);
#pragma unroll
            for (int j = 0; j < 2; ++j) {
                const int nt = np * 2 + j;
                mma_bf16(acc[nt], aH, bH[2 * j], bH[2 * j + 1]);
                mma_bf16(acc[nt], aH, bL[2 * j], bL[2 * j + 1]);
                mma_bf16(acc[nt], aL, bH[2 * j], bH[2 * j + 1]);
            }
        }
    }
}

__global__ __launch_bounds__(256, 1) void attn_fused(float* __restrict__ attn)
{
    extern __shared__ __nv_bfloat16 smraw[];
    SmemMap sm;
    sm.Qh = smraw;          sm.Ql = smraw + 9216;
    sm.Kh = smraw + 18432;  sm.Kl = smraw + 23040;
    sm.Vh = smraw + 27648;  sm.Vl = smraw + 32256;

    const int qt = gridDim.x - 1 - (int)blockIdx.x;   // big tiles first
    const int bh = blockIdx.y;
    const int tid = threadIdx.x, lane = tid & 31, wid = tid >> 5;
    const int q0 = qt * 128;
    const int nkt = 2 * qt + 2;
    const int grp = lane >> 3, koff = (grp & 1) << 3, nb = (grp >> 1) << 3, nr = lane & 7;

    // ---- load Q tile (128 x 64 hi/lo) ----
#pragma unroll
    for (int t = 0; t < 8; ++t) {
        const int idx = tid + t * 256;               // 0..2047
        const int buf = idx >> 10;
        const int r = (idx >> 3) & 127, c8 = (idx & 7) << 3;
        const __nv_bfloat16* src = buf ? g_Qlo : g_Qhi;
        __nv_bfloat16* dst = buf ? sm.Ql : sm.Qh;
        *(uint4*)&dst[r * 72 + c8] =
            *(const uint4*)(src + (((size_t)bh * S_ + q0 + r) << 6) + c8);
    }

    const int myrow0 = q0 + wid * 16 + (lane >> 2);  // hf=0 row; hf=1 adds 8

    // ================= PASS 1: (m, l) stats =================
    float m0 = -1e30f, m1 = -1e30f, l0 = 0.f, l1 = 0.f;

    for (int kt = 0; kt < nkt; ++kt) {
        __syncthreads();
#pragma unroll
        for (int t = 0; t < 4; ++t) {                // K tile hi/lo
            const int idx = tid + t * 256;           // 0..1023
            const int buf = idx >> 9;
            const int r = (idx >> 3) & 63, c8 = (idx & 7) << 3;
            const __nv_bfloat16* src = buf ? g_Klo : g_Khi;
            __nv_bfloat16* dst = buf ? sm.Kl : sm.Kh;
            *(uint4*)&dst[r * 72 + c8] =
                *(const uint4*)(src + (((size_t)bh * S_ + kt * 64 + r) << 6) + c8);
        }
        __syncthreads();

        float acc[8][4];
        score_tile(sm, lane, wid, acc);

        const bool need_mask = (kt * 64 + 63) > (q0 + wid * 16);
#pragma unroll
        for (int nt = 0; nt < 8; ++nt) {
            const int kc = kt * 64 + nt * 8 + ((lane & 3) << 1);
#pragma unroll
            for (int hf = 0; hf < 2; ++hf) {
                const int qr = myrow0 + hf * 8;
                float x0 = acc[nt][hf * 2] * 0.125f;
                float x1 = acc[nt][hf * 2 + 1] * 0.125f;
                if (need_mask) {
                    if (kc > qr)     x0 = -1e30f;
                    if (kc + 1 > qr) x1 = -1e30f;
                }
                acc[nt][hf * 2] = x0; acc[nt][hf * 2 + 1] = x1;
            }
        }
        // online update per thread (2 rows)
#pragma unroll
        for (int hf = 0; hf < 2; ++hf) {
            float tm = -1e30f;
#pragma unroll
            for (int nt = 0; nt < 8; ++nt)
                tm = fmaxf(tm, fmaxf(acc[nt][hf * 2], acc[nt][hf * 2 + 1]));
            float& m = hf ? m1 : m0;
            float& l = hf ? l1 : l0;
            const float mn = fmaxf(m, tm);
            float s = l * __expf(m - mn);
#pragma unroll
            for (int nt = 0; nt < 8; ++nt) {
                const float a0 = acc[nt][hf * 2], a1 = acc[nt][hf * 2 + 1];
                if (a0 > -1e29f) s += __expf(a0 - mn);
                if (a1 > -1e29f) s += __expf(a1 - mn);
            }
            m = mn; l = s;
        }
    }

    // merge (m,l) across the 4 lanes sharing each row
#pragma unroll
    for (int off = 1; off <= 2; off <<= 1) {
        float mo = __shfl_xor_sync(0xffffffffu, m0, off);
        float lo_ = __shfl_xor_sync(0xffffffffu, l0, off);
        float mn = fmaxf(m0, mo);
        l0 = l0 * __expf(m0 - mn) + lo_ * __expf(mo - mn);
        m0 = mn;
        mo = __shfl_xor_sync(0xffffffffu, m1, off);
        lo_ = __shfl_xor_sync(0xffffffffu, l1, off);
        mn = fmaxf(m1, mo);
        l1 = l1 * __expf(m1 - mn) + lo_ * __expf(mo - mn);
        m1 = mn;
    }
    const float il0 = 1.f / l0, il1 = 1.f / l1;

    // ================= PASS 2: P write + O accumulate =================
    float accO[8][4];
#pragma unroll
    for (int a = 0; a < 8; ++a)
#pragma unroll
        for (int b = 0; b < 4; ++b) accO[a][b] = 0.f;

    for (int kt = 0; kt < nkt; ++kt) {
        __syncthreads();
#pragma unroll
        for (int t = 0; t < 8; ++t) {                // K + V tiles hi/lo
            const int idx = tid + t * 256;           // 0..2047
            const int sel = idx >> 9;                // 0:Kh 1:Kl 2:Vh 3:Vl
            const int r = (idx >> 3) & 63, c8 = (idx & 7) << 3;
            const __nv_bfloat16* src = (sel == 0) ? g_Khi : (sel == 1) ? g_Klo
                                     : (sel == 2) ? g_Vhi : g_Vlo;
            __nv_bfloat16* dst = (sel == 0) ? sm.Kh : (sel == 1) ? sm.Kl
                               : (sel == 2) ? sm.Vh : sm.Vl;
            *(uint4*)&dst[r * 72 + c8] =
                *(const uint4*)(src + (((size_t)bh * S_ + kt * 64 + r) << 6) + c8);
        }
        __syncthreads();

        float acc[8][4];
        score_tile(sm, lane, wid, acc);

        const bool need_mask = (kt * 64 + 63) > (q0 + wid * 16);
        uint32_t ph[8][2], pl[8][2];
#pragma unroll
        for (int nt = 0; nt < 8; ++nt) {
            const int kc = kt * 64 + nt * 8 + ((lane & 3) << 1);
            float pv[4];
#pragma unroll
            for (int hf = 0; hf < 2; ++hf) {
                const int qr = myrow0 + hf * 8;
                float x0 = acc[nt][hf * 2] * 0.125f;
                float x1 = acc[nt][hf * 2 + 1] * 0.125f;
                if (need_mask) {
                    if (kc > qr)     x0 = -1e30f;
                    if (kc + 1 > qr) x1 = -1e30f;
                }
                const float mm = hf ? m1 : m0;
                const float ii = hf ? il1 : il0;
                const float p0 = __expf(x0 - mm) * ii;
                const float p1 = __expf(x1 - mm) * ii;
                pv[hf * 2] = p0; pv[hf * 2 + 1] = p1;
                // write attn
                float* dst = attn + ((size_t)bh * S_ + qr) * S_ + kc;
                *(float2*)dst = make_float2(p0, p1);
                // bf16 hi/lo split for P@V
                const uint32_t hpk = pack_bf16(p0, p1);
                __nv_bfloat162 hb = *(__nv_bfloat162*)&hpk;
                ph[nt][hf] = hpk;
                pl[nt][hf] = pack_bf16(p0 - __bfloat162float(hb.x),
                                       p1 - __bfloat162float(hb.y));
            }
        }

        // O += P @ V  (A-fragments from P regs, B from sV via ldmatrix.trans)
#pragma unroll
        for (int t = 0; t < 4; ++t) {
            uint32_t aH[4] = { ph[2 * t][0], ph[2 * t][1], ph[2 * t + 1][0], ph[2 * t + 1][1] };
            uint32_t aL[4] = { pl[2 * t][0], pl[2 * t][1], pl[2 * t + 1][0], pl[2 * t + 1][1] };
#pragma unroll
            for (int np = 0; np < 4; ++np) {
                uint32_t bH[4], bL[4];
                const int kr = t * 16 + koff + nr;
                const int nc = np * 16 + nb;
                ldsm4t(sptr(&sm.Vh[kr * 72 + nc]), bH);
                ldsm4t(sptr(&sm.Vl[kr * 72 + nc]), bL);
#pragma unroll
                for (int j = 0; j < 2; ++j) {
                    const int nt = np * 2 + j;
                    mma_bf16(accO[nt], aH, bH[2 * j], bH[2 * j + 1]);
                    mma_bf16(accO[nt], aH, bL[2 * j], bL[2 * j + 1]);
                    mma_bf16(accO[nt], aL, bH[2 * j], bH[2 * j + 1]);
                }
            }
        }
    }

    // ---- zero-fill attn cols beyond causal range ----
    {
        const int coff4 = (nkt * 64) >> 2;           // first zero col / 4
        const float4 z = make_float4(0.f, 0.f, 0.f, 0.f);
        for (int r = 0; r < 128; ++r) {
            float* rowp = attn + ((size_t)bh * S_ + q0 + r) * S_;
            for (int c = coff4 + tid; c < S_ / 4; c += 256)
                ((float4*)rowp)[c] = z;
        }
    }

    // ---- write O as bf16 hi/lo to g_Chi/g_Clo [B,S,D] ----
    const int b = bh >> 4, h = bh & (H_ - 1);
#pragma unroll
    for (int nt = 0; nt < 8; ++nt) {
        const int d = h * DK_ + nt * 8 + ((lane & 3) << 1);
#pragma unroll
        for (int hf = 0; hf < 2; ++hf) {
            const int s = q0 + wid * 16 + (lane >> 2) + hf * 8;
            const float x0 = accO[nt][hf * 2], x1 = accO[nt][hf * 2 + 1];
            const size_t o = ((size_t)b * S_ + s) * D_ + d;
            __nv_bfloat162 phh, pll;
            phh.x = __float2bfloat16(x0); phh.y = __float2bfloat16(x1);
            pll.x = __float2bfloat16(x0 - __bfloat162float(phh.x));
            pll.y = __float2bfloat16(x1 - __bfloat162float(phh.y));
            *(__nv_bfloat162*)(g_Chi + o) = phh;
            *(__nv_bfloat162*)(g_Clo + o) = pll;
        }
    }
}

// ---------------------------------------------------------------------------
// Launch
// ---------------------------------------------------------------------------
extern "C" void kernel_launch(void* const* d_in, const int* in_sizes, int n_in,
                              void* d_out, int out_size)
{
    const float* q = (const float*)d_in[0];
    const float* k = (const float*)d_in[1];
    const float* v = (const float*)d_in[2];
    const float* W[4] = { (const float*)d_in[4], (const float*)d_in[5],
                          (const float*)d_in[6], (const float*)d_in[7] };

    float* out  = (float*)d_out;
    float* attn = out + (size_t)B_ * S_ * D_;

    __nv_bfloat16 *qhi, *qlo, *khi, *klo, *vhi, *vlo, *whi, *wlo;
    __nv_bfloat16 *Qhi, *Qlo, *Khi, *Klo, *Vhi, *Vlo, *Chi, *Clo;
    cudaGetSymbolAddress((void**)&qhi, g_qhi); cudaGetSymbolAddress((void**)&qlo, g_qlo);
    cudaGetSymbolAddress((void**)&khi, g_khi); cudaGetSymbolAddress((void**)&klo, g_klo);
    cudaGetSymbolAddress((void**)&vhi, g_vhi); cudaGetSymbolAddress((void**)&vlo, g_vlo);
    cudaGetSymbolAddress((void**)&whi, g_whi); cudaGetSymbolAddress((void**)&wlo, g_wlo);
    cudaGetSymbolAddress((void**)&Qhi, g_Qhi); cudaGetSymbolAddress((void**)&Qlo, g_Qlo);
    cudaGetSymbolAddress((void**)&Khi, g_Khi); cudaGetSymbolAddress((void**)&Klo, g_Klo);
    cudaGetSymbolAddress((void**)&Vhi, g_Vhi); cudaGetSymbolAddress((void**)&Vlo, g_Vlo);
    cudaGetSymbolAddress((void**)&Chi, g_Chi); cudaGetSymbolAddress((void**)&Clo, g_Clo);

    static bool attr_set = false;
    if (!attr_set) {
        cudaFuncSetAttribute(attn_fused, cudaFuncAttributeMaxDynamicSharedMemorySize, 73728);
        attr_set = true;
    }

    const int n4x = MM_ * D_ / 4;
    const int n4w = D_ * D_ / 4;
    split_kernel<<<(n4x + 255) / 256, 256>>>(q, qhi, qlo, n4x);
    split_kernel<<<(n4x + 255) / 256, 256>>>(k, khi, klo, n4x);
    split_kernel<<<(n4x + 255) / 256, 256>>>(v, vhi, vlo, n4x);
    for (int i = 0; i < 4; ++i)
        split_kernel<<<(n4w + 255) / 256, 256>>>(W[i], whi + (size_t)i * D_ * D_,
                                                 wlo + (size_t)i * D_ * D_, n4w);

    dim3 gG(D_ / 128, MM_ / 128);   // (8, 64)
    mm_tc<1><<<gG, 256>>>(qhi, qlo, whi + 0 * (size_t)D_ * D_, wlo + 0 * (size_t)D_ * D_,
                          nullptr, Qhi, Qlo);
    mm_tc<1><<<gG, 256>>>(khi, klo, whi + 1 * (size_t)D_ * D_, wlo + 1 * (size_t)D_ * D_,
                          nullptr, Khi, Klo);
    mm_tc<1><<<gG, 256>>>(vhi, vlo, whi + 2 * (size_t)D_ * D_, wlo + 2 * (size_t)D_ * D_,
                          nullptr, Vhi, Vlo);

    dim3 gA(S_ / 128, B_ * H_);     // (16, 64)
    attn_fused<<<gA, 256, 73728>>>(attn);

    mm_tc<0><<<gG, 256>>>(Chi, Clo, whi + 3 * (size_t)D_ * D_, wlo + 3 * (size_t)D_ * D_,
                          out, nullptr, nullptr);
}

// round 5
// speedup vs baseline: 2.5690x; 1.2540x over previous
#include <cuda_runtime.h>
#include <cuda_bf16.h>
#include <cstdint>

#define B_  4
#define S_  2048
#define D_  1024
#define H_  16
#define DK_ 64
#define MM_ (B_ * S_)          // 8192

// ---------------------------------------------------------------------------
// Scratch (device globals)
// ---------------------------------------------------------------------------
__device__ __nv_bfloat16 g_qhi[MM_ * D_], g_qlo[MM_ * D_];
__device__ __nv_bfloat16 g_khi[MM_ * D_], g_klo[MM_ * D_];
__device__ __nv_bfloat16 g_vhi[MM_ * D_], g_vlo[MM_ * D_];
__device__ __nv_bfloat16 g_whi[4][D_ * D_], g_wlo[4][D_ * D_];
__device__ __nv_bfloat16 g_Qhi[MM_ * D_], g_Qlo[MM_ * D_];   // [B,H,S,DK]
__device__ __nv_bfloat16 g_Khi[MM_ * D_], g_Klo[MM_ * D_];
__device__ __nv_bfloat16 g_Vhi[MM_ * D_], g_Vlo[MM_ * D_];
__device__ __nv_bfloat16 g_Chi[MM_ * D_], g_Clo[MM_ * D_];   // [B,S,D]

// ---------------------------------------------------------------------------
// PTX helpers
// ---------------------------------------------------------------------------
__device__ __forceinline__ void ldsm4(uint32_t addr, uint32_t* r) {
    asm volatile("ldmatrix.sync.aligned.m8n8.x4.shared.b16 {%0,%1,%2,%3}, [%4];"
        : "=r"(r[0]), "=r"(r[1]), "=r"(r[2]), "=r"(r[3]) : "r"(addr));
}
__device__ __forceinline__ void ldsm4t(uint32_t addr, uint32_t* r) {
    asm volatile("ldmatrix.sync.aligned.m8n8.x4.trans.shared.b16 {%0,%1,%2,%3}, [%4];"
        : "=r"(r[0]), "=r"(r[1]), "=r"(r[2]), "=r"(r[3]) : "r"(addr));
}
__device__ __forceinline__ void mma_bf16(float* c, const uint32_t* a, uint32_t b0, uint32_t b1) {
    asm volatile("mma.sync.aligned.m16n8k16.row.col.f32.bf16.bf16.f32 "
        "{%0,%1,%2,%3}, {%4,%5,%6,%7}, {%8,%9}, {%0,%1,%2,%3};"
        : "+f"(c[0]), "+f"(c[1]), "+f"(c[2]), "+f"(c[3])
        : "r"(a[0]), "r"(a[1]), "r"(a[2]), "r"(a[3]), "r"(b0), "r"(b1));
}
__device__ __forceinline__ uint32_t sptr(const void* p) {
    return (uint32_t)__cvta_generic_to_shared(p);
}
__device__ __forceinline__ void cpa16(uint32_t s, const void* g) {
    asm volatile("cp.async.cg.shared.global [%0], [%1], 16;" :: "r"(s), "l"(g));
}
#define CPA_COMMIT() asm volatile("cp.async.commit_group;" ::: "memory")
#define CPA_WAIT(n)  asm volatile("cp.async.wait_group %0;" :: "n"(n) : "memory")
__device__ __forceinline__ uint32_t pack_bf16(float x, float y) {
    __nv_bfloat162 t; t.x = __float2bfloat16(x); t.y = __float2bfloat16(y);
    return *(uint32_t*)&t;
}

// ---------------------------------------------------------------------------
// Split fp32 -> (hi, lo) bf16
// ---------------------------------------------------------------------------
__global__ __launch_bounds__(256) void split_kernel(
    const float* __restrict__ x, __nv_bfloat16* __restrict__ hi,
    __nv_bfloat16* __restrict__ lo, int n4)
{
    int i = blockIdx.x * blockDim.x + threadIdx.x;
    if (i >= n4) return;
    float4 v = ((const float4*)x)[i];
    __nv_bfloat16 h0 = __float2bfloat16(v.x), h1 = __float2bfloat16(v.y);
    __nv_bfloat16 h2 = __float2bfloat16(v.z), h3 = __float2bfloat16(v.w);
    __nv_bfloat162 ph0; ph0.x = h0; ph0.y = h1;
    __nv_bfloat162 ph1; ph1.x = h2; ph1.y = h3;
    __nv_bfloat162 pl0; pl0.x = __float2bfloat16(v.x - __bfloat162float(h0));
    pl0.y = __float2bfloat16(v.y - __bfloat162float(h1));
    __nv_bfloat162 pl1; pl1.x = __float2bfloat16(v.z - __bfloat162float(h2));
    pl1.y = __float2bfloat16(v.w - __bfloat162float(h3));
    ((__nv_bfloat162*)hi)[2 * i]     = ph0;
    ((__nv_bfloat162*)hi)[2 * i + 1] = ph1;
    ((__nv_bfloat162*)lo)[2 * i]     = pl0;
    ((__nv_bfloat162*)lo)[2 * i + 1] = pl1;
}

// ---------------------------------------------------------------------------
// bf16x3 GEMM, cp.async 2-stage pipeline. C = A @ W^T.
// 128x128 tile, BK=32, 256 thr. Dynamic smem: 2 stages x 4 comps x 5120 elems.
// ---------------------------------------------------------------------------
template <int MODE>
__global__ __launch_bounds__(256, 1) void mm_tc(
    const __nv_bfloat16* __restrict__ Ahi, const __nv_bfloat16* __restrict__ Alo,
    const __nv_bfloat16* __restrict__ Whi, const __nv_bfloat16* __restrict__ Wlo,
    float* __restrict__ Cf,
    __nv_bfloat16* __restrict__ Ohi, __nv_bfloat16* __restrict__ Olo)
{
    extern __shared__ __nv_bfloat16 dsm[];   // 2*20480 elems = 81920 B

    const int tid = threadIdx.x, lane = tid & 31, wid = tid >> 5;
    const int bm = blockIdx.y * 128, bn = blockIdx.x * 128;
    const int wm = (wid >> 2) * 64, wn = (wid & 3) * 32;

    float acc[4][4][4];
#pragma unroll
    for (int a = 0; a < 4; ++a)
#pragma unroll
        for (int b = 0; b < 4; ++b)
#pragma unroll
            for (int c = 0; c < 4; ++c) acc[a][b][c] = 0.f;

    const int grp = lane >> 3, koff = (grp & 1) << 3, nb = (grp >> 1) << 3, nr = lane & 7;

#define MM_LOAD(it, st) do {                                                     \
    const int _k0 = (it) * 32;                                                   \
    __nv_bfloat16* _bb = dsm + (st) * 20480;                                     \
    _Pragma("unroll")                                                            \
    for (int _t = 0; _t < 2; ++_t) {                                             \
        const int _idx = tid + _t * 256;                                         \
        const int _row = _idx >> 2, _c8 = (_idx & 3) << 3;                       \
        const int _so = _row * 40 + _c8;                                         \
        cpa16(sptr(_bb + _so),         Ahi + (size_t)(bm + _row) * D_ + _k0 + _c8); \
        cpa16(sptr(_bb + 5120 + _so),  Alo + (size_t)(bm + _row) * D_ + _k0 + _c8); \
        cpa16(sptr(_bb + 10240 + _so), Whi + (size_t)(bn + _row) * D_ + _k0 + _c8); \
        cpa16(sptr(_bb + 15360 + _so), Wlo + (size_t)(bn + _row) * D_ + _k0 + _c8); \
    } } while (0)

    MM_LOAD(0, 0); CPA_COMMIT();

    for (int it = 0; it < 32; ++it) {
        if (it + 1 < 32) { MM_LOAD(it + 1, (it + 1) & 1); CPA_COMMIT(); CPA_WAIT(1); }
        else             { CPA_WAIT(0); }
        __syncthreads();

        const __nv_bfloat16* sAh = dsm + (it & 1) * 20480;
        const __nv_bfloat16* sAl = sAh + 5120;
        const __nv_bfloat16* sWh = sAh + 10240;
        const __nv_bfloat16* sWl = sAh + 15360;

#pragma unroll
        for (int kk = 0; kk < 2; ++kk) {
            uint32_t aH[4][4], aL[4][4];
#pragma unroll
            for (int mt = 0; mt < 4; ++mt) {
                const int r = wm + mt * 16 + (lane & 15);
                const int c = kk * 16 + ((lane >> 4) << 3);
                ldsm4(sptr(sAh + r * 40 + c), aH[mt]);
                ldsm4(sptr(sAl + r * 40 + c), aL[mt]);
            }
            uint32_t bH[2][4], bL[2][4];
#pragma unroll
            for (int np = 0; np < 2; ++np) {
                const int n = wn + np * 16 + nb + nr;
                const int c = kk * 16 + koff;
                ldsm4(sptr(sWh + n * 40 + c), bH[np]);
                ldsm4(sptr(sWl + n * 40 + c), bL[np]);
            }
#pragma unroll
            for (int mt = 0; mt < 4; ++mt)
#pragma unroll
                for (int np = 0; np < 2; ++np)
#pragma unroll
                    for (int j = 0; j < 2; ++j) {
                        const int nt = np * 2 + j;
                        mma_bf16(acc[mt][nt], aH[mt], bH[np][2 * j], bH[np][2 * j + 1]);
                        mma_bf16(acc[mt][nt], aH[mt], bL[np][2 * j], bL[np][2 * j + 1]);
                        mma_bf16(acc[mt][nt], aL[mt], bH[np][2 * j], bH[np][2 * j + 1]);
                    }
        }
        __syncthreads();
    }
#undef MM_LOAD

#pragma unroll
    for (int mt = 0; mt < 4; ++mt)
#pragma unroll
        for (int nt = 0; nt < 4; ++nt) {
            const float* c = acc[mt][nt];
            const int n = bn + wn + nt * 8 + ((lane & 3) << 1);
#pragma unroll
            for (int hf = 0; hf < 2; ++hf) {
                const int m = bm + wm + mt * 16 + (lane >> 2) + hf * 8;
                const float x0 = c[hf * 2], x1 = c[hf * 2 + 1];
                if (MODE == 0) {
                    *(float2*)(Cf + (size_t)m * D_ + n) = make_float2(x0, x1);
                } else {
                    const int b = m >> 11, s = m & (S_ - 1);
                    const int h = n >> 6, dk = n & (DK_ - 1);
                    const size_t o = (((size_t)(b * H_ + h) * S_ + s) << 6) + dk;
                    __nv_bfloat16 h0 = __float2bfloat16(x0), h1 = __float2bfloat16(x1);
                    __nv_bfloat162 ph; ph.x = h0; ph.y = h1;
                    __nv_bfloat162 pl;
                    pl.x = __float2bfloat16(x0 - __bfloat162float(h0));
                    pl.y = __float2bfloat16(x1 - __bfloat162float(h1));
                    *(__nv_bfloat162*)(Ohi + o) = ph;
                    *(__nv_bfloat162*)(Olo + o) = pl;
                }
            }
        }
}

// ---------------------------------------------------------------------------
// Fused flash attention with cp.async pipelines.
// smem elems: Qh@0 Ql@9216; stage st: base 18432+st*18432, Kh+0 Kl+4608
// Vh+9216 Vl+13824. Total 55296 elems = 110592 B.
// ---------------------------------------------------------------------------
__device__ __forceinline__ void score_tile(
    const __nv_bfloat16* Qh, const __nv_bfloat16* Ql,
    const __nv_bfloat16* Kh, const __nv_bfloat16* Kl,
    int lane, int wid, float acc[8][4])
{
#pragma unroll
    for (int a = 0; a < 8; ++a)
#pragma unroll
        for (int b = 0; b < 4; ++b) acc[a][b] = 0.f;

    const int grp = lane >> 3, koff = (grp & 1) << 3, nb = (grp >> 1) << 3, nr = lane & 7;
    const int r = wid * 16 + (lane & 15);
    const int ca = (lane >> 4) << 3;

#pragma unroll
    for (int kk = 0; kk < 4; ++kk) {
        uint32_t aH[4], aL[4];
        ldsm4(sptr(Qh + r * 72 + kk * 16 + ca), aH);
        ldsm4(sptr(Ql + r * 72 + kk * 16 + ca), aL);
#pragma unroll
        for (int np = 0; np < 4; ++np) {
            uint32_t bH[4], bL[4];
            const int n = np * 16 + nb + nr;
            const int cc = kk * 16 + koff;
            ldsm4(sptr(Kh + n * 72 + cc), bH);
            ldsm4(sptr(Kl + n * 72 + cc), bL);
#pragma unroll
            for (int j = 0; j < 2; ++j) {
                const int nt = np * 2 + j;
                mma_bf16(acc[nt], aH, bH[2 * j], bH[2 * j + 1]);
                mma_bf16(acc[nt], aH, bL[2 * j], bL[2 * j + 1]);
                mma_bf16(acc[nt], aL, bH[2 * j], bH[2 * j + 1]);
            }
        }
    }
}

__global__ __launch_bounds__(256, 1) void attn_fused(float* __restrict__ attn)
{
    extern __shared__ __nv_bfloat16 sm[];
    __nv_bfloat16* Qh = sm;
    __nv_bfloat16* Ql = sm + 9216;

    const int qt = gridDim.x - 1 - (int)blockIdx.x;   // big tiles first
    const int bh = blockIdx.y;
    const int tid = threadIdx.x, lane = tid & 31, wid = tid >> 5;
    const int q0 = qt * 128;
    const int nkt = 2 * qt + 2;
    const int grp = lane >> 3, koff = (grp & 1) << 3, nb = (grp >> 1) << 3, nr = lane & 7;

    // ---- load Q tile (plain loads, once) ----
#pragma unroll
    for (int t = 0; t < 8; ++t) {
        const int idx = tid + t * 256;
        const int buf = idx >> 10;
        const int r = (idx >> 3) & 127, c8 = (idx & 7) << 3;
        const __nv_bfloat16* src = buf ? g_Qlo : g_Qhi;
        __nv_bfloat16* dst = buf ? Ql : Qh;
        *(uint4*)&dst[r * 72 + c8] =
            *(const uint4*)(src + (((size_t)bh * S_ + q0 + r) << 6) + c8);
    }

    const int myrow0 = q0 + wid * 16 + (lane >> 2);

#define AT_LOADK(kt, st) do {                                                    \
    __nv_bfloat16* _bb = sm + 18432 + (st) * 18432;                              \
    _Pragma("unroll")                                                            \
    for (int _t = 0; _t < 2; ++_t) {                                             \
        const int _idx = tid + _t * 256;                                         \
        const int _r = _idx >> 3, _c8 = (_idx & 7) << 3;                         \
        const size_t _g = (((size_t)bh * S_ + (kt) * 64 + _r) << 6) + _c8;       \
        const int _so = _r * 72 + _c8;                                           \
        cpa16(sptr(_bb + _so),        g_Khi + _g);                               \
        cpa16(sptr(_bb + 4608 + _so), g_Klo + _g);                               \
    } } while (0)

#define AT_LOADKV(kt, st) do {                                                   \
    __nv_bfloat16* _bb = sm + 18432 + (st) * 18432;                              \
    _Pragma("unroll")                                                            \
    for (int _t = 0; _t < 2; ++_t) {                                             \
        const int _idx = tid + _t * 256;                                         \
        const int _r = _idx >> 3, _c8 = (_idx & 7) << 3;                         \
        const size_t _g = (((size_t)bh * S_ + (kt) * 64 + _r) << 6) + _c8;       \
        const int _so = _r * 72 + _c8;                                           \
        cpa16(sptr(_bb + _so),         g_Khi + _g);                              \
        cpa16(sptr(_bb + 4608 + _so),  g_Klo + _g);                              \
        cpa16(sptr(_bb + 9216 + _so),  g_Vhi + _g);                              \
        cpa16(sptr(_bb + 13824 + _so), g_Vlo + _g);                              \
    } } while (0)

    // ================= PASS 1: (m, l) stats =================
    float m0 = -1e30f, m1 = -1e30f, l0 = 0.f, l1 = 0.f;

    AT_LOADK(0, 0); CPA_COMMIT();
    for (int kt = 0; kt < nkt; ++kt) {
        if (kt + 1 < nkt) { AT_LOADK(kt + 1, (kt + 1) & 1); CPA_COMMIT(); CPA_WAIT(1); }
        else              { CPA_WAIT(0); }
        __syncthreads();

        const __nv_bfloat16* Kh = sm + 18432 + (kt & 1) * 18432;
        const __nv_bfloat16* Kl = Kh + 4608;

        float acc[8][4];
        score_tile(Qh, Ql, Kh, Kl, lane, wid, acc);

        const bool need_mask = (kt * 64 + 63) > (q0 + wid * 16);
#pragma unroll
        for (int nt = 0; nt < 8; ++nt) {
            const int kc = kt * 64 + nt * 8 + ((lane & 3) << 1);
#pragma unroll
            for (int hf = 0; hf < 2; ++hf) {
                const int qr = myrow0 + hf * 8;
                float x0 = acc[nt][hf * 2] * 0.125f;
                float x1 = acc[nt][hf * 2 + 1] * 0.125f;
                if (need_mask) {
                    if (kc > qr)     x0 = -1e30f;
                    if (kc + 1 > qr) x1 = -1e30f;
                }
                acc[nt][hf * 2] = x0; acc[nt][hf * 2 + 1] = x1;
            }
        }
#pragma unroll
        for (int hf = 0; hf < 2; ++hf) {
            float tm = -1e30f;
#pragma unroll
            for (int nt = 0; nt < 8; ++nt)
                tm = fmaxf(tm, fmaxf(acc[nt][hf * 2], acc[nt][hf * 2 + 1]));
            float& m = hf ? m1 : m0;
            float& l = hf ? l1 : l0;
            const float mn = fmaxf(m, tm);
            float s = l * __expf(m - mn);
#pragma unroll
            for (int nt = 0; nt < 8; ++nt)
                s += __expf(acc[nt][hf * 2] - mn) + __expf(acc[nt][hf * 2 + 1] - mn);
            m = mn; l = s;
        }
        __syncthreads();
    }

    // merge (m,l) across the 4 lanes sharing each row
#pragma unroll
    for (int off = 1; off <= 2; off <<= 1) {
        float mo = __shfl_xor_sync(0xffffffffu, m0, off);
        float lo_ = __shfl_xor_sync(0xffffffffu, l0, off);
        float mn = fmaxf(m0, mo);
        l0 = l0 * __expf(m0 - mn) + lo_ * __expf(mo - mn);
        m0 = mn;
        mo = __shfl_xor_sync(0xffffffffu, m1, off);
        lo_ = __shfl_xor_sync(0xffffffffu, l1, off);
        mn = fmaxf(m1, mo);
        l1 = l1 * __expf(m1 - mn) + lo_ * __expf(mo - mn);
        m1 = mn;
    }
    const float il0 = 1.f / l0, il1 = 1.f / l1;

    // ================= PASS 2: P write + O accumulate =================
    float accO[8][4];
#pragma unroll
    for (int a = 0; a < 8; ++a)
#pragma unroll
        for (int b = 0; b < 4; ++b) accO[a][b] = 0.f;

    AT_LOADKV(0, 0); CPA_COMMIT();
    for (int kt = 0; kt < nkt; ++kt) {
        if (kt + 1 < nkt) { AT_LOADKV(kt + 1, (kt + 1) & 1); CPA_COMMIT(); CPA_WAIT(1); }
        else              { CPA_WAIT(0); }
        __syncthreads();

        const __nv_bfloat16* Kh = sm + 18432 + (kt & 1) * 18432;
        const __nv_bfloat16* Kl = Kh + 4608;
        const __nv_bfloat16* Vh = Kh + 9216;
        const __nv_bfloat16* Vl = Kh + 13824;

        float acc[8][4];
        score_tile(Qh, Ql, Kh, Kl, lane, wid, acc);

        const bool need_mask = (kt * 64 + 63) > (q0 + wid * 16);
        uint32_t ph[8][2], pl[8][2];
#pragma unroll
        for (int nt = 0; nt < 8; ++nt) {
            const int kc = kt * 64 + nt * 8 + ((lane & 3) << 1);
#pragma unroll
            for (int hf = 0; hf < 2; ++hf) {
                const int qr = myrow0 + hf * 8;
                float x0 = acc[nt][hf * 2] * 0.125f;
                float x1 = acc[nt][hf * 2 + 1] * 0.125f;
                if (need_mask) {
                    if (kc > qr)     x0 = -1e30f;
                    if (kc + 1 > qr) x1 = -1e30f;
                }
                const float mm = hf ? m1 : m0;
                const float ii = hf ? il1 : il0;
                const float p0 = __expf(x0 - mm) * ii;
                const float p1 = __expf(x1 - mm) * ii;
                float* dst = attn + ((size_t)bh * S_ + qr) * S_ + kc;
                *(float2*)dst = make_float2(p0, p1);
                const uint32_t hpk = pack_bf16(p0, p1);
                __nv_bfloat162 hb = *(__nv_bfloat162*)&hpk;
                ph[nt][hf] = hpk;
                pl[nt][hf] = pack_bf16(p0 - __bfloat162float(hb.x),
                                       p1 - __bfloat162float(hb.y));
            }
        }

#pragma unroll
        for (int t = 0; t < 4; ++t) {
            uint32_t aH[4] = { ph[2 * t][0], ph[2 * t][1], ph[2 * t + 1][0], ph[2 * t + 1][1] };
            uint32_t aL[4] = { pl[2 * t][0], pl[2 * t][1], pl[2 * t + 1][0], pl[2 * t + 1][1] };
#pragma unroll
            for (int np = 0; np < 4; ++np) {
                uint32_t bH[4], bL[4];
                const int kr = t * 16 + koff + nr;
                const int nc = np * 16 + nb;
                ldsm4t(sptr(Vh + kr * 72 + nc), bH);
                ldsm4t(sptr(Vl + kr * 72 + nc), bL);
#pragma unroll
                for (int j = 0; j < 2; ++j) {
                    const int nt = np * 2 + j;
                    mma_bf16(accO[nt], aH, bH[2 * j], bH[2 * j + 1]);
                    mma_bf16(accO[nt], aH, bL[2 * j], bL[2 * j + 1]);
                    mma_bf16(accO[nt], aL, bH[2 * j], bH[2 * j + 1]);
                }
            }
        }
        __syncthreads();
    }
#undef AT_LOADK
#undef AT_LOADKV

    // ---- zero-fill attn cols beyond causal range ----
    {
        const int coff4 = (nkt * 64) >> 2;
        const float4 z = make_float4(0.f, 0.f, 0.f, 0.f);
        for (int r = 0; r < 128; ++r) {
            float* rowp = attn + ((size_t)bh * S_ + q0 + r) * S_;
            for (int c = coff4 + tid; c < S_ / 4; c += 256)
                ((float4*)rowp)[c] = z;
        }
    }

    // ---- write O as bf16 hi/lo to g_Chi/g_Clo [B,S,D] ----
    const int b = bh >> 4, h = bh & (H_ - 1);
#pragma unroll
    for (int nt = 0; nt < 8; ++nt) {
        const int d = h * DK_ + nt * 8 + ((lane & 3) << 1);
#pragma unroll
        for (int hf = 0; hf < 2; ++hf) {
            const int s = q0 + wid * 16 + (lane >> 2) + hf * 8;
            const float x0 = accO[nt][hf * 2], x1 = accO[nt][hf * 2 + 1];
            const size_t o = ((size_t)b * S_ + s) * D_ + d;
            __nv_bfloat162 phh, pll;
            phh.x = __float2bfloat16(x0); phh.y = __float2bfloat16(x1);
            pll.x = __float2bfloat16(x0 - __bfloat162float(phh.x));
            pll.y = __float2bfloat16(x1 - __bfloat162float(phh.y));
            *(__nv_bfloat162*)(g_Chi + o) = phh;
            *(__nv_bfloat162*)(g_Clo + o) = pll;
        }
    }
}

// ---------------------------------------------------------------------------
// Launch (ordered so launch index 5 = mm_tc Q for ncu -s 5 -c 1)
// ---------------------------------------------------------------------------
extern "C" void kernel_launch(void* const* d_in, const int* in_sizes, int n_in,
                              void* d_out, int out_size)
{
    const float* q = (const float*)d_in[0];
    const float* k = (const float*)d_in[1];
    const float* v = (const float*)d_in[2];
    const float* W[4] = { (const float*)d_in[4], (const float*)d_in[5],
                          (const float*)d_in[6], (const float*)d_in[7] };

    float* out  = (float*)d_out;
    float* attn = out + (size_t)B_ * S_ * D_;

    __nv_bfloat16 *qhi, *qlo, *khi, *klo, *vhi, *vlo, *whi, *wlo;
    __nv_bfloat16 *Qhi, *Qlo, *Khi, *Klo, *Vhi, *Vlo, *Chi, *Clo;
    cudaGetSymbolAddress((void**)&qhi, g_qhi); cudaGetSymbolAddress((void**)&qlo, g_qlo);
    cudaGetSymbolAddress((void**)&khi, g_khi); cudaGetSymbolAddress((void**)&klo, g_klo);
    cudaGetSymbolAddress((void**)&vhi, g_vhi); cudaGetSymbolAddress((void**)&vlo, g_vlo);
    cudaGetSymbolAddress((void**)&whi, g_whi); cudaGetSymbolAddress((void**)&wlo, g_wlo);
    cudaGetSymbolAddress((void**)&Qhi, g_Qhi); cudaGetSymbolAddress((void**)&Qlo, g_Qlo);
    cudaGetSymbolAddress((void**)&Khi, g_Khi); cudaGetSymbolAddress((void**)&Klo, g_Klo);
    cudaGetSymbolAddress((void**)&Vhi, g_Vhi); cudaGetSymbolAddress((void**)&Vlo, g_Vlo);
    cudaGetSymbolAddress((void**)&Chi, g_Chi); cudaGetSymbolAddress((void**)&Clo, g_Clo);

    static bool attr_set = false;
    if (!attr_set) {
        cudaFuncSetAttribute(mm_tc<0>, cudaFuncAttributeMaxDynamicSharedMemorySize, 81920);
        cudaFuncSetAttribute(mm_tc<1>, cudaFuncAttributeMaxDynamicSharedMemorySize, 81920);
        cudaFuncSetAttribute(attn_fused, cudaFuncAttributeMaxDynamicSharedMemorySize, 110592);
        attr_set = true;
    }

    const int n4x = MM_ * D_ / 4;
    const int n4w = D_ * D_ / 4;
    dim3 gG(D_ / 128, MM_ / 128);   // (8, 64)
    dim3 gA(S_ / 128, B_ * H_);     // (16, 64)

    // 0..4: splits
    split_kernel<<<(n4x + 255) / 256, 256>>>(q, qhi, qlo, n4x);
    split_kernel<<<(n4x + 255) / 256, 256>>>(k, khi, klo, n4x);
    split_kernel<<<(n4x + 255) / 256, 256>>>(v, vhi, vlo, n4x);
    split_kernel<<<(n4w + 255) / 256, 256>>>(W[0], whi + 0 * (size_t)D_ * D_, wlo + 0 * (size_t)D_ * D_, n4w);
    split_kernel<<<(n4w + 255) / 256, 256>>>(W[1], whi + 1 * (size_t)D_ * D_, wlo + 1 * (size_t)D_ * D_, n4w);
    // 5: Q projection (profiled by ncu -s 5 -c 1)
    mm_tc<1><<<gG, 256, 81920>>>(qhi, qlo, whi + 0 * (size_t)D_ * D_, wlo + 0 * (size_t)D_ * D_,
                                 nullptr, Qhi, Qlo);
    // 6..7: remaining weight splits
    split_kernel<<<(n4w + 255) / 256, 256>>>(W[2], whi + 2 * (size_t)D_ * D_, wlo + 2 * (size_t)D_ * D_, n4w);
    split_kernel<<<(n4w + 255) / 256, 256>>>(W[3], whi + 3 * (size_t)D_ * D_, wlo + 3 * (size_t)D_ * D_, n4w);
    // 8..9: K, V projections
    mm_tc<1><<<gG, 256, 81920>>>(khi, klo, whi + 1 * (size_t)D_ * D_, wlo + 1 * (size_t)D_ * D_,
                                 nullptr, Khi, Klo);
    mm_tc<1><<<gG, 256, 81920>>>(vhi, vlo, whi + 2 * (size_t)D_ * D_, wlo + 2 * (size_t)D_ * D_,
                                 nullptr, Vhi, Vlo);
    // 10: fused attention
    attn_fused<<<gA, 256, 110592>>>(attn);
    // 11: output projection
    mm_tc<0><<<gG, 256, 81920>>>(Chi, Clo, whi + 3 * (size_t)D_ * D_, wlo + 3 * (size_t)D_ * D_,
                                 out, nullptr, nullptr);
}

// round 6
// speedup vs baseline: 2.6379x; 1.0268x over previous
#include <cuda_runtime.h>
#include <cuda_bf16.h>
#include <cstdint>

#define B_  4
#define S_  2048
#define D_  1024
#define H_  16
#define DK_ 64
#define MM_ (B_ * S_)          // 8192

// ---------------------------------------------------------------------------
// Scratch (device globals)
// ---------------------------------------------------------------------------
__device__ __nv_bfloat16 g_qhi[MM_ * D_], g_qlo[MM_ * D_];
__device__ __nv_bfloat16 g_khi[MM_ * D_], g_klo[MM_ * D_];
__device__ __nv_bfloat16 g_vhi[MM_ * D_], g_vlo[MM_ * D_];
__device__ __nv_bfloat16 g_whi[4][D_ * D_], g_wlo[4][D_ * D_];
__device__ __nv_bfloat16 g_Qhi[MM_ * D_], g_Qlo[MM_ * D_];   // [B,H,S,DK]
__device__ __nv_bfloat16 g_Khi[MM_ * D_], g_Klo[MM_ * D_];
__device__ __nv_bfloat16 g_Vhi[MM_ * D_], g_Vlo[MM_ * D_];
__device__ __nv_bfloat16 g_Chi[MM_ * D_], g_Clo[MM_ * D_];   // [B,S,D]
__device__ float g_linv[B_ * H_ * S_];                        // 1/rowsum

// ---------------------------------------------------------------------------
// PTX helpers
// ---------------------------------------------------------------------------
__device__ __forceinline__ void ldsm4(uint32_t addr, uint32_t* r) {
    asm volatile("ldmatrix.sync.aligned.m8n8.x4.shared.b16 {%0,%1,%2,%3}, [%4];"
        : "=r"(r[0]), "=r"(r[1]), "=r"(r[2]), "=r"(r[3]) : "r"(addr));
}
__device__ __forceinline__ void ldsm4t(uint32_t addr, uint32_t* r) {
    asm volatile("ldmatrix.sync.aligned.m8n8.x4.trans.shared.b16 {%0,%1,%2,%3}, [%4];"
        : "=r"(r[0]), "=r"(r[1]), "=r"(r[2]), "=r"(r[3]) : "r"(addr));
}
__device__ __forceinline__ void mma_bf16(float* c, const uint32_t* a, uint32_t b0, uint32_t b1) {
    asm volatile("mma.sync.aligned.m16n8k16.row.col.f32.bf16.bf16.f32 "
        "{%0,%1,%2,%3}, {%4,%5,%6,%7}, {%8,%9}, {%0,%1,%2,%3};"
        : "+f"(c[0]), "+f"(c[1]), "+f"(c[2]), "+f"(c[3])
        : "r"(a[0]), "r"(a[1]), "r"(a[2]), "r"(a[3]), "r"(b0), "r"(b1));
}
__device__ __forceinline__ uint32_t sptr(const void* p) {
    return (uint32_t)__cvta_generic_to_shared(p);
}
__device__ __forceinline__ void cpa16(uint32_t s, const void* g) {
    asm volatile("cp.async.cg.shared.global [%0], [%1], 16;" :: "r"(s), "l"(g));
}
#define CPA_COMMIT() asm volatile("cp.async.commit_group;" ::: "memory")
#define CPA_WAIT(n)  asm volatile("cp.async.wait_group %0;" :: "n"(n) : "memory")
__device__ __forceinline__ uint32_t pack_bf16(float x, float y) {
    __nv_bfloat162 t; t.x = __float2bfloat16(x); t.y = __float2bfloat16(y);
    return *(uint32_t*)&t;
}

// ---------------------------------------------------------------------------
// Split fp32 -> (hi, lo) bf16. Batched variants.
// ---------------------------------------------------------------------------
__device__ __forceinline__ void split4(const float* __restrict__ x,
    __nv_bfloat16* __restrict__ hi, __nv_bfloat16* __restrict__ lo, int i)
{
    float4 v = ((const float4*)x)[i];
    __nv_bfloat16 h0 = __float2bfloat16(v.x), h1 = __float2bfloat16(v.y);
    __nv_bfloat16 h2 = __float2bfloat16(v.z), h3 = __float2bfloat16(v.w);
    __nv_bfloat162 ph0; ph0.x = h0; ph0.y = h1;
    __nv_bfloat162 ph1; ph1.x = h2; ph1.y = h3;
    __nv_bfloat162 pl0; pl0.x = __float2bfloat16(v.x - __bfloat162float(h0));
    pl0.y = __float2bfloat16(v.y - __bfloat162float(h1));
    __nv_bfloat162 pl1; pl1.x = __float2bfloat16(v.z - __bfloat162float(h2));
    pl1.y = __float2bfloat16(v.w - __bfloat162float(h3));
    ((__nv_bfloat162*)hi)[2 * i]     = ph0;
    ((__nv_bfloat162*)hi)[2 * i + 1] = ph1;
    ((__nv_bfloat162*)lo)[2 * i]     = pl0;
    ((__nv_bfloat162*)lo)[2 * i + 1] = pl1;
}

__global__ __launch_bounds__(256) void split_acts(
    const float* q, const float* k, const float* v,
    __nv_bfloat16* qh, __nv_bfloat16* ql, __nv_bfloat16* kh, __nv_bfloat16* kl,
    __nv_bfloat16* vh, __nv_bfloat16* vl, int n4)
{
    int i = blockIdx.x * blockDim.x + threadIdx.x;
    if (i >= n4) return;
    const int z = blockIdx.y;
    const float* x = (z == 0) ? q : (z == 1) ? k : v;
    __nv_bfloat16* hi = (z == 0) ? qh : (z == 1) ? kh : vh;
    __nv_bfloat16* lo = (z == 0) ? ql : (z == 1) ? kl : vl;
    split4(x, hi, lo, i);
}

__global__ __launch_bounds__(256) void split_wts(
    const float* w0, const float* w1, const float* w2, const float* w3,
    __nv_bfloat16* hi, __nv_bfloat16* lo, int n4)
{
    int i = blockIdx.x * blockDim.x + threadIdx.x;
    if (i >= n4) return;
    const int z = blockIdx.y;
    const float* x = (z == 0) ? w0 : (z == 1) ? w1 : (z == 2) ? w2 : w3;
    split4(x, hi + (size_t)z * D_ * D_, lo + (size_t)z * D_ * D_, i);
}

// ---------------------------------------------------------------------------
// bf16x3 GEMM, cp.async 2-stage pipeline (unchanged from R5). C = A @ W^T.
// ---------------------------------------------------------------------------
template <int MODE>
__global__ __launch_bounds__(256, 1) void mm_tc(
    const __nv_bfloat16* __restrict__ Ahi, const __nv_bfloat16* __restrict__ Alo,
    const __nv_bfloat16* __restrict__ Whi, const __nv_bfloat16* __restrict__ Wlo,
    float* __restrict__ Cf,
    __nv_bfloat16* __restrict__ Ohi, __nv_bfloat16* __restrict__ Olo)
{
    extern __shared__ __nv_bfloat16 dsm[];   // 2*20480 elems = 81920 B

    const int tid = threadIdx.x, lane = tid & 31, wid = tid >> 5;
    const int bm = blockIdx.y * 128, bn = blockIdx.x * 128;
    const int wm = (wid >> 2) * 64, wn = (wid & 3) * 32;

    float acc[4][4][4];
#pragma unroll
    for (int a = 0; a < 4; ++a)
#pragma unroll
        for (int b = 0; b < 4; ++b)
#pragma unroll
            for (int c = 0; c < 4; ++c) acc[a][b][c] = 0.f;

    const int grp = lane >> 3, koff = (grp & 1) << 3, nb = (grp >> 1) << 3, nr = lane & 7;

#define MM_LOAD(it, st) do {                                                     \
    const int _k0 = (it) * 32;                                                   \
    __nv_bfloat16* _bb = dsm + (st) * 20480;                                     \
    _Pragma("unroll")                                                            \
    for (int _t = 0; _t < 2; ++_t) {                                             \
        const int _idx = tid + _t * 256;                                         \
        const int _row = _idx >> 2, _c8 = (_idx & 3) << 3;                       \
        const int _so = _row * 40 + _c8;                                         \
        cpa16(sptr(_bb + _so),         Ahi + (size_t)(bm + _row) * D_ + _k0 + _c8); \
        cpa16(sptr(_bb + 5120 + _so),  Alo + (size_t)(bm + _row) * D_ + _k0 + _c8); \
        cpa16(sptr(_bb + 10240 + _so), Whi + (size_t)(bn + _row) * D_ + _k0 + _c8); \
        cpa16(sptr(_bb + 15360 + _so), Wlo + (size_t)(bn + _row) * D_ + _k0 + _c8); \
    } } while (0)

    MM_LOAD(0, 0); CPA_COMMIT();

    for (int it = 0; it < 32; ++it) {
        if (it + 1 < 32) { MM_LOAD(it + 1, (it + 1) & 1); CPA_COMMIT(); CPA_WAIT(1); }
        else             { CPA_WAIT(0); }
        __syncthreads();

        const __nv_bfloat16* sAh = dsm + (it & 1) * 20480;
        const __nv_bfloat16* sAl = sAh + 5120;
        const __nv_bfloat16* sWh = sAh + 10240;
        const __nv_bfloat16* sWl = sAh + 15360;

#pragma unroll
        for (int kk = 0; kk < 2; ++kk) {
            uint32_t aH[4][4], aL[4][4];
#pragma unroll
            for (int mt = 0; mt < 4; ++mt) {
                const int r = wm + mt * 16 + (lane & 15);
                const int c = kk * 16 + ((lane >> 4) << 3);
                ldsm4(sptr(sAh + r * 40 + c), aH[mt]);
                ldsm4(sptr(sAl + r * 40 + c), aL[mt]);
            }
            uint32_t bH[2][4], bL[2][4];
#pragma unroll
            for (int np = 0; np < 2; ++np) {
                const int n = wn + np * 16 + nb + nr;
                const int c = kk * 16 + koff;
                ldsm4(sptr(sWh + n * 40 + c), bH[np]);
                ldsm4(sptr(sWl + n * 40 + c), bL[np]);
            }
#pragma unroll
            for (int mt = 0; mt < 4; ++mt)
#pragma unroll
                for (int np = 0; np < 2; ++np)
#pragma unroll
                    for (int j = 0; j < 2; ++j) {
                        const int nt = np * 2 + j;
                        mma_bf16(acc[mt][nt], aH[mt], bH[np][2 * j], bH[np][2 * j + 1]);
                        mma_bf16(acc[mt][nt], aH[mt], bL[np][2 * j], bL[np][2 * j + 1]);
                        mma_bf16(acc[mt][nt], aL[mt], bH[np][2 * j], bH[np][2 * j + 1]);
                    }
        }
        __syncthreads();
    }
#undef MM_LOAD

#pragma unroll
    for (int mt = 0; mt < 4; ++mt)
#pragma unroll
        for (int nt = 0; nt < 4; ++nt) {
            const float* c = acc[mt][nt];
            const int n = bn + wn + nt * 8 + ((lane & 3) << 1);
#pragma unroll
            for (int hf = 0; hf < 2; ++hf) {
                const int m = bm + wm + mt * 16 + (lane >> 2) + hf * 8;
                const float x0 = c[hf * 2], x1 = c[hf * 2 + 1];
                if (MODE == 0) {
                    *(float2*)(Cf + (size_t)m * D_ + n) = make_float2(x0, x1);
                } else {
                    const int b = m >> 11, s = m & (S_ - 1);
                    const int h = n >> 6, dk = n & (DK_ - 1);
                    const size_t o = (((size_t)(b * H_ + h) * S_ + s) << 6) + dk;
                    __nv_bfloat16 h0 = __float2bfloat16(x0), h1 = __float2bfloat16(x1);
                    __nv_bfloat162 ph; ph.x = h0; ph.y = h1;
                    __nv_bfloat162 pl;
                    pl.x = __float2bfloat16(x0 - __bfloat162float(h0));
                    pl.y = __float2bfloat16(x1 - __bfloat162float(h1));
                    *(__nv_bfloat162*)(Ohi + o) = ph;
                    *(__nv_bfloat162*)(Olo + o) = pl;
                }
            }
        }
}

// ---------------------------------------------------------------------------
// Single-pass attention (shift c=0). Writes unnormalized E=exp(s) to attn,
// accumulates l = rowsum(E) and O += E@V (bf16x3), stores 1/l, O normalized
// in epilogue. Grid (16, 64), 256 thr, smem 110592 B.
// ---------------------------------------------------------------------------
__device__ __forceinline__ void score_tile(
    const __nv_bfloat16* Qh, const __nv_bfloat16* Ql,
    const __nv_bfloat16* Kh, const __nv_bfloat16* Kl,
    int lane, int wid, float acc[8][4])
{
#pragma unroll
    for (int a = 0; a < 8; ++a)
#pragma unroll
        for (int b = 0; b < 4; ++b) acc[a][b] = 0.f;

    const int grp = lane >> 3, koff = (grp & 1) << 3, nb = (grp >> 1) << 3, nr = lane & 7;
    const int r = wid * 16 + (lane & 15);
    const int ca = (lane >> 4) << 3;

#pragma unroll
    for (int kk = 0; kk < 4; ++kk) {
        uint32_t aH[4], aL[4];
        ldsm4(sptr(Qh + r * 72 + kk * 16 + ca), aH);
        ldsm4(sptr(Ql + r * 72 + kk * 16 + ca), aL);
#pragma unroll
        for (int np = 0; np < 4; ++np) {
            uint32_t bH[4], bL[4];
            const int n = np * 16 + nb + nr;
            const int cc = kk * 16 + koff;
            ldsm4(sptr(Kh + n * 72 + cc), bH);
            ldsm4(sptr(Kl + n * 72 + cc), bL);
#pragma unroll
            for (int j = 0; j < 2; ++j) {
                const int nt = np * 2 + j;
                mma_bf16(acc[nt], aH, bH[2 * j], bH[2 * j + 1]);
                mma_bf16(acc[nt], aH, bL[2 * j], bL[2 * j + 1]);
                mma_bf16(acc[nt], aL, bH[2 * j], bH[2 * j + 1]);
            }
        }
    }
}

__global__ __launch_bounds__(256, 1) void attn_single(float* __restrict__ attn)
{
    extern __shared__ __nv_bfloat16 sm[];
    __nv_bfloat16* Qh = sm;
    __nv_bfloat16* Ql = sm + 9216;

    const int qt = gridDim.x - 1 - (int)blockIdx.x;   // big tiles first
    const int bh = blockIdx.y;
    const int tid = threadIdx.x, lane = tid & 31, wid = tid >> 5;
    const int q0 = qt * 128;
    const int nkt = 2 * qt + 2;
    const int grp = lane >> 3, koff = (grp & 1) << 3, nb = (grp >> 1) << 3, nr = lane & 7;

    // ---- load Q tile ----
#pragma unroll
    for (int t = 0; t < 8; ++t) {
        const int idx = tid + t * 256;
        const int buf = idx >> 10;
        const int r = (idx >> 3) & 127, c8 = (idx & 7) << 3;
        const __nv_bfloat16* src = buf ? g_Qlo : g_Qhi;
        __nv_bfloat16* dst = buf ? Ql : Qh;
        *(uint4*)&dst[r * 72 + c8] =
            *(const uint4*)(src + (((size_t)bh * S_ + q0 + r) << 6) + c8);
    }

    const int myrow0 = q0 + wid * 16 + (lane >> 2);

#define AT_LOADKV(kt, st) do {                                                   \
    __nv_bfloat16* _bb = sm + 18432 + (st) * 18432;                              \
    _Pragma("unroll")                                                            \
    for (int _t = 0; _t < 2; ++_t) {                                             \
        const int _idx = tid + _t * 256;                                         \
        const int _r = _idx >> 3, _c8 = (_idx & 7) << 3;                         \
        const size_t _g = (((size_t)bh * S_ + (kt) * 64 + _r) << 6) + _c8;       \
        const int _so = _r * 72 + _c8;                                           \
        cpa16(sptr(_bb + _so),         g_Khi + _g);                              \
        cpa16(sptr(_bb + 4608 + _so),  g_Klo + _g);                              \
        cpa16(sptr(_bb + 9216 + _so),  g_Vhi + _g);                              \
        cpa16(sptr(_bb + 13824 + _so), g_Vlo + _g);                              \
    } } while (0)

    float accO[8][4];
#pragma unroll
    for (int a = 0; a < 8; ++a)
#pragma unroll
        for (int b = 0; b < 4; ++b) accO[a][b] = 0.f;
    float l0 = 0.f, l1 = 0.f;

    AT_LOADKV(0, 0); CPA_COMMIT();
    for (int kt = 0; kt < nkt; ++kt) {
        if (kt + 1 < nkt) { AT_LOADKV(kt + 1, (kt + 1) & 1); CPA_COMMIT(); CPA_WAIT(1); }
        else              { CPA_WAIT(0); }
        __syncthreads();

        const __nv_bfloat16* Kh = sm + 18432 + (kt & 1) * 18432;
        const __nv_bfloat16* Kl = Kh + 4608;
        const __nv_bfloat16* Vh = Kh + 9216;
        const __nv_bfloat16* Vl = Kh + 13824;

        float acc[8][4];
        score_tile(Qh, Ql, Kh, Kl, lane, wid, acc);

        const bool need_mask = (kt * 64 + 63) > (q0 + wid * 16);

        // process 2 nt groups at a time: exp + E write + l accum + pack + PV MMA
#pragma unroll
        for (int t = 0; t < 4; ++t) {
            uint32_t aH[4], aL[4];
#pragma unroll
            for (int g = 0; g < 2; ++g) {
                const int nt = 2 * t + g;
                const int kc = kt * 64 + nt * 8 + ((lane & 3) << 1);
#pragma unroll
                for (int hf = 0; hf < 2; ++hf) {
                    const int qr = myrow0 + hf * 8;
                    float x0 = acc[nt][hf * 2] * 0.125f;
                    float x1 = acc[nt][hf * 2 + 1] * 0.125f;
                    if (need_mask) {
                        if (kc > qr)     x0 = -1e30f;
                        if (kc + 1 > qr) x1 = -1e30f;
                    }
                    const float e0 = __expf(x0);
                    const float e1 = __expf(x1);
                    if (hf) l1 += e0 + e1; else l0 += e0 + e1;
                    float* dst = attn + ((size_t)bh * S_ + qr) * S_ + kc;
                    *(float2*)dst = make_float2(e0, e1);
                    const uint32_t hpk = pack_bf16(e0, e1);
                    __nv_bfloat162 hb = *(__nv_bfloat162*)&hpk;
                    aH[g * 2 + hf] = hpk;
                    aL[g * 2 + hf] = pack_bf16(e0 - __bfloat162float(hb.x),
                                               e1 - __bfloat162float(hb.y));
                }
            }
#pragma unroll
            for (int np = 0; np < 4; ++np) {
                uint32_t bH[4], bL[4];
                const int kr = t * 16 + koff + nr;
                const int nc = np * 16 + nb;
                ldsm4t(sptr(Vh + kr * 72 + nc), bH);
                ldsm4t(sptr(Vl + kr * 72 + nc), bL);
#pragma unroll
                for (int j = 0; j < 2; ++j) {
                    const int nt = np * 2 + j;
                    mma_bf16(accO[nt], aH, bH[2 * j], bH[2 * j + 1]);
                    mma_bf16(accO[nt], aH, bL[2 * j], bL[2 * j + 1]);
                    mma_bf16(accO[nt], aL, bH[2 * j], bH[2 * j + 1]);
                }
            }
        }
        __syncthreads();
    }
#undef AT_LOADKV

    // merge l across the 4 lanes sharing each row
#pragma unroll
    for (int off = 1; off <= 2; off <<= 1) {
        l0 += __shfl_xor_sync(0xffffffffu, l0, off);
        l1 += __shfl_xor_sync(0xffffffffu, l1, off);
    }
    const float il0 = 1.f / l0, il1 = 1.f / l1;

    if ((lane & 3) == 0) {
        g_linv[(size_t)bh * S_ + myrow0]     = il0;
        g_linv[(size_t)bh * S_ + myrow0 + 8] = il1;
    }

    // ---- write O = accO / l as bf16 hi/lo to g_Chi/g_Clo [B,S,D] ----
    const int b = bh >> 4, h = bh & (H_ - 1);
#pragma unroll
    for (int nt = 0; nt < 8; ++nt) {
        const int d = h * DK_ + nt * 8 + ((lane & 3) << 1);
#pragma unroll
        for (int hf = 0; hf < 2; ++hf) {
            const int s = q0 + wid * 16 + (lane >> 2) + hf * 8;
            const float ii = hf ? il1 : il0;
            const float x0 = accO[nt][hf * 2] * ii, x1 = accO[nt][hf * 2 + 1] * ii;
            const size_t o = ((size_t)b * S_ + s) * D_ + d;
            __nv_bfloat162 phh, pll;
            phh.x = __float2bfloat16(x0); phh.y = __float2bfloat16(x1);
            pll.x = __float2bfloat16(x0 - __bfloat162float(phh.x));
            pll.y = __float2bfloat16(x1 - __bfloat162float(phh.y));
            *(__nv_bfloat162*)(g_Chi + o) = phh;
            *(__nv_bfloat162*)(g_Clo + o) = pll;
        }
    }
}

// ---------------------------------------------------------------------------
// Normalize + zero-fill: attn[row, c] = (c <= row) ? E*linv : 0.
// Grid (S_, B*H), 128 thr per row. Fully coalesced float4.
// ---------------------------------------------------------------------------
__global__ __launch_bounds__(128) void scale_zero(float* __restrict__ attn)
{
    const int row = blockIdx.x, bh = blockIdx.y;
    const float s = g_linv[(size_t)bh * S_ + row];
    float* p = attn + ((size_t)bh * S_ + row) * S_;
    const int tid = threadIdx.x;
    const int qw = row >> 2;                 // float4 index containing diag

    for (int i = tid; i < S_ / 4; i += 128) {
        if (i < qw) {
            float4 v = ((const float4*)p)[i];
            v.x *= s; v.y *= s; v.z *= s; v.w *= s;
            ((float4*)p)[i] = v;
        } else if (i == qw) {
            float4 v = ((const float4*)p)[i];
            const int c = i * 4;
            v.x = (c     <= row) ? v.x * s : 0.f;
            v.y = (c + 1 <= row) ? v.y * s : 0.f;
            v.z = (c + 2 <= row) ? v.z * s : 0.f;
            v.w = (c + 3 <= row) ? v.w * s : 0.f;
            ((float4*)p)[i] = v;
        } else {
            ((float4*)p)[i] = make_float4(0.f, 0.f, 0.f, 0.f);
        }
    }
}

// ---------------------------------------------------------------------------
// Launch
// ---------------------------------------------------------------------------
extern "C" void kernel_launch(void* const* d_in, const int* in_sizes, int n_in,
                              void* d_out, int out_size)
{
    const float* q = (const float*)d_in[0];
    const float* k = (const float*)d_in[1];
    const float* v = (const float*)d_in[2];
    const float* W[4] = { (const float*)d_in[4], (const float*)d_in[5],
                          (const float*)d_in[6], (const float*)d_in[7] };

    float* out  = (float*)d_out;
    float* attn = out + (size_t)B_ * S_ * D_;

    __nv_bfloat16 *qhi, *qlo, *khi, *klo, *vhi, *vlo, *whi, *wlo;
    __nv_bfloat16 *Qhi, *Qlo, *Khi, *Klo, *Vhi, *Vlo, *Chi, *Clo;
    cudaGetSymbolAddress((void**)&qhi, g_qhi); cudaGetSymbolAddress((void**)&qlo, g_qlo);
    cudaGetSymbolAddress((void**)&khi, g_khi); cudaGetSymbolAddress((void**)&klo, g_klo);
    cudaGetSymbolAddress((void**)&vhi, g_vhi); cudaGetSymbolAddress((void**)&vlo, g_vlo);
    cudaGetSymbolAddress((void**)&whi, g_whi); cudaGetSymbolAddress((void**)&wlo, g_wlo);
    cudaGetSymbolAddress((void**)&Qhi, g_Qhi); cudaGetSymbolAddress((void**)&Qlo, g_Qlo);
    cudaGetSymbolAddress((void**)&Khi, g_Khi); cudaGetSymbolAddress((void**)&Klo, g_Klo);
    cudaGetSymbolAddress((void**)&Vhi, g_Vhi); cudaGetSymbolAddress((void**)&Vlo, g_Vlo);
    cudaGetSymbolAddress((void**)&Chi, g_Chi); cudaGetSymbolAddress((void**)&Clo, g_Clo);

    static bool attr_set = false;
    if (!attr_set) {
        cudaFuncSetAttribute(mm_tc<0>, cudaFuncAttributeMaxDynamicSharedMemorySize, 81920);
        cudaFuncSetAttribute(mm_tc<1>, cudaFuncAttributeMaxDynamicSharedMemorySize, 81920);
        cudaFuncSetAttribute(attn_single, cudaFuncAttributeMaxDynamicSharedMemorySize, 110592);
        attr_set = true;
    }

    const int n4x = MM_ * D_ / 4;
    const int n4w = D_ * D_ / 4;
    dim3 gG(D_ / 128, MM_ / 128);   // (8, 64)
    dim3 gA(S_ / 128, B_ * H_);     // (16, 64)

    dim3 gSa((n4x + 255) / 256, 3);
    split_acts<<<gSa, 256>>>(q, k, v, qhi, qlo, khi, klo, vhi, vlo, n4x);
    dim3 gSw((n4w + 255) / 256, 4);
    split_wts<<<gSw, 256>>>(W[0], W[1], W[2], W[3], whi, wlo, n4w);

    mm_tc<1><<<gG, 256, 81920>>>(qhi, qlo, whi + 0 * (size_t)D_ * D_, wlo + 0 * (size_t)D_ * D_,
                                 nullptr, Qhi, Qlo);
    mm_tc<1><<<gG, 256, 81920>>>(khi, klo, whi + 1 * (size_t)D_ * D_, wlo + 1 * (size_t)D_ * D_,
                                 nullptr, Khi, Klo);
    mm_tc<1><<<gG, 256, 81920>>>(vhi, vlo, whi + 2 * (size_t)D_ * D_, wlo + 2 * (size_t)D_ * D_,
                                 nullptr, Vhi, Vlo);

    attn_single<<<gA, 256, 110592>>>(attn);

    dim3 gZ(S_, B_ * H_);
    scale_zero<<<gZ, 128>>>(attn);

    mm_tc<0><<<gG, 256, 81920>>>(Chi, Clo, whi + 3 * (size_t)D_ * D_, wlo + 3 * (size_t)D_ * D_,
                                 out, nullptr, nullptr);
}

// round 7
// speedup vs baseline: 2.6480x; 1.0038x over previous
#include <cuda_runtime.h>
#include <cuda_bf16.h>
#include <cstdint>

#define B_  4
#define S_  2048
#define D_  1024
#define H_  16
#define DK_ 64
#define MM_ (B_ * S_)          // 8192

// ---------------------------------------------------------------------------
// Scratch (device globals)
// ---------------------------------------------------------------------------
__device__ __nv_bfloat16 g_qhi[MM_ * D_], g_qlo[MM_ * D_];
__device__ __nv_bfloat16 g_khi[MM_ * D_], g_klo[MM_ * D_];
__device__ __nv_bfloat16 g_vhi[MM_ * D_], g_vlo[MM_ * D_];
__device__ __nv_bfloat16 g_whi[4][D_ * D_], g_wlo[4][D_ * D_];
__device__ __nv_bfloat16 g_Qhi[MM_ * D_], g_Qlo[MM_ * D_];   // [B,H,S,DK]
__device__ __nv_bfloat16 g_Khi[MM_ * D_], g_Klo[MM_ * D_];
__device__ __nv_bfloat16 g_Vhi[MM_ * D_], g_Vlo[MM_ * D_];
__device__ __nv_bfloat16 g_Chi[MM_ * D_], g_Clo[MM_ * D_];   // [B,S,D]
__device__ float g_linv[B_ * H_ * S_];                        // 1/rowsum

// ---------------------------------------------------------------------------
// PTX helpers
// ---------------------------------------------------------------------------
__device__ __forceinline__ void ldsm4(uint32_t addr, uint32_t* r) {
    asm volatile("ldmatrix.sync.aligned.m8n8.x4.shared.b16 {%0,%1,%2,%3}, [%4];"
        : "=r"(r[0]), "=r"(r[1]), "=r"(r[2]), "=r"(r[3]) : "r"(addr));
}
__device__ __forceinline__ void ldsm4t(uint32_t addr, uint32_t* r) {
    asm volatile("ldmatrix.sync.aligned.m8n8.x4.trans.shared.b16 {%0,%1,%2,%3}, [%4];"
        : "=r"(r[0]), "=r"(r[1]), "=r"(r[2]), "=r"(r[3]) : "r"(addr));
}
__device__ __forceinline__ void mma_bf16(float* c, const uint32_t* a, uint32_t b0, uint32_t b1) {
    asm volatile("mma.sync.aligned.m16n8k16.row.col.f32.bf16.bf16.f32 "
        "{%0,%1,%2,%3}, {%4,%5,%6,%7}, {%8,%9}, {%0,%1,%2,%3};"
        : "+f"(c[0]), "+f"(c[1]), "+f"(c[2]), "+f"(c[3])
        : "r"(a[0]), "r"(a[1]), "r"(a[2]), "r"(a[3]), "r"(b0), "r"(b1));
}
__device__ __forceinline__ uint32_t sptr(const void* p) {
    return (uint32_t)__cvta_generic_to_shared(p);
}
__device__ __forceinline__ void cpa16(uint32_t s, const void* g) {
    asm volatile("cp.async.cg.shared.global [%0], [%1], 16;" :: "r"(s), "l"(g));
}
#define CPA_COMMIT() asm volatile("cp.async.commit_group;" ::: "memory")
#define CPA_WAIT(n)  asm volatile("cp.async.wait_group %0;" :: "n"(n) : "memory")
__device__ __forceinline__ uint32_t pack_bf16(float x, float y) {
    __nv_bfloat162 t; t.x = __float2bfloat16(x); t.y = __float2bfloat16(y);
    return *(uint32_t*)&t;
}

// ---------------------------------------------------------------------------
// Split fp32 -> (hi, lo) bf16. Batched variants.
// ---------------------------------------------------------------------------
__device__ __forceinline__ void split4(const float* __restrict__ x,
    __nv_bfloat16* __restrict__ hi, __nv_bfloat16* __restrict__ lo, int i)
{
    float4 v = ((const float4*)x)[i];
    __nv_bfloat16 h0 = __float2bfloat16(v.x), h1 = __float2bfloat16(v.y);
    __nv_bfloat16 h2 = __float2bfloat16(v.z), h3 = __float2bfloat16(v.w);
    __nv_bfloat162 ph0; ph0.x = h0; ph0.y = h1;
    __nv_bfloat162 ph1; ph1.x = h2; ph1.y = h3;
    __nv_bfloat162 pl0; pl0.x = __float2bfloat16(v.x - __bfloat162float(h0));
    pl0.y = __float2bfloat16(v.y - __bfloat162float(h1));
    __nv_bfloat162 pl1; pl1.x = __float2bfloat16(v.z - __bfloat162float(h2));
    pl1.y = __float2bfloat16(v.w - __bfloat162float(h3));
    ((__nv_bfloat162*)hi)[2 * i]     = ph0;
    ((__nv_bfloat162*)hi)[2 * i + 1] = ph1;
    ((__nv_bfloat162*)lo)[2 * i]     = pl0;
    ((__nv_bfloat162*)lo)[2 * i + 1] = pl1;
}

__global__ __launch_bounds__(256) void split_acts(
    const float* q, const float* k, const float* v,
    __nv_bfloat16* qh, __nv_bfloat16* ql, __nv_bfloat16* kh, __nv_bfloat16* kl,
    __nv_bfloat16* vh, __nv_bfloat16* vl, int n4)
{
    int i = blockIdx.x * blockDim.x + threadIdx.x;
    if (i >= n4) return;
    const int z = blockIdx.y;
    const float* x = (z == 0) ? q : (z == 1) ? k : v;
    __nv_bfloat16* hi = (z == 0) ? qh : (z == 1) ? kh : vh;
    __nv_bfloat16* lo = (z == 0) ? ql : (z == 1) ? kl : vl;
    split4(x, hi, lo, i);
}

__global__ __launch_bounds__(256) void split_wts(
    const float* w0, const float* w1, const float* w2, const float* w3,
    __nv_bfloat16* hi, __nv_bfloat16* lo, int n4)
{
    int i = blockIdx.x * blockDim.x + threadIdx.x;
    if (i >= n4) return;
    const int z = blockIdx.y;
    const float* x = (z == 0) ? w0 : (z == 1) ? w1 : (z == 2) ? w2 : w3;
    split4(x, hi + (size_t)z * D_ * D_, lo + (size_t)z * D_ * D_, i);
}

// ---------------------------------------------------------------------------
// bf16x3 GEMM, cp.async 2-stage pipeline. C = A @ W^T.
// 256x128 tile, BK=32, 512 thr (16 warps, each 64x32).
// smem/stage: Ah 10240, Al 10240, Wh 5120, Wl 5120 elems = 30720 (61440 B);
// 2 stages = 122880 B.
// ---------------------------------------------------------------------------
template <int MODE>
__global__ __launch_bounds__(512, 1) void mm_tc(
    const __nv_bfloat16* __restrict__ Ahi, const __nv_bfloat16* __restrict__ Alo,
    const __nv_bfloat16* __restrict__ Whi, const __nv_bfloat16* __restrict__ Wlo,
    float* __restrict__ Cf,
    __nv_bfloat16* __restrict__ Ohi, __nv_bfloat16* __restrict__ Olo)
{
    extern __shared__ __nv_bfloat16 dsm[];

    const int tid = threadIdx.x, lane = tid & 31, wid = tid >> 5;
    const int bm = blockIdx.y * 256, bn = blockIdx.x * 128;
    const int wm = (wid >> 2) * 64, wn = (wid & 3) * 32;

    float acc[4][4][4];
#pragma unroll
    for (int a = 0; a < 4; ++a)
#pragma unroll
        for (int b = 0; b < 4; ++b)
#pragma unroll
            for (int c = 0; c < 4; ++c) acc[a][b][c] = 0.f;

    const int grp = lane >> 3, koff = (grp & 1) << 3, nb = (grp >> 1) << 3, nr = lane & 7;

#define MM_LOAD(it, st) do {                                                     \
    const int _k0 = (it) * 32;                                                   \
    __nv_bfloat16* _bb = dsm + (st) * 30720;                                     \
    _Pragma("unroll")                                                            \
    for (int _t = 0; _t < 2; ++_t) {                                             \
        const int _idx = tid + _t * 512;          /* 0..1023 over 256 rows */    \
        const int _row = _idx >> 2, _c8 = (_idx & 3) << 3;                       \
        const int _so = _row * 40 + _c8;                                         \
        cpa16(sptr(_bb + _so),         Ahi + (size_t)(bm + _row) * D_ + _k0 + _c8); \
        cpa16(sptr(_bb + 10240 + _so), Alo + (size_t)(bm + _row) * D_ + _k0 + _c8); \
    }                                                                            \
    {                                                                            \
        const int _row = tid >> 2, _c8 = (tid & 3) << 3;  /* 128 rows */         \
        const int _so = _row * 40 + _c8;                                         \
        cpa16(sptr(_bb + 20480 + _so), Whi + (size_t)(bn + _row) * D_ + _k0 + _c8); \
        cpa16(sptr(_bb + 25600 + _so), Wlo + (size_t)(bn + _row) * D_ + _k0 + _c8); \
    } } while (0)

    MM_LOAD(0, 0); CPA_COMMIT();

    for (int it = 0; it < 32; ++it) {
        if (it + 1 < 32) { MM_LOAD(it + 1, (it + 1) & 1); CPA_COMMIT(); CPA_WAIT(1); }
        else             { CPA_WAIT(0); }
        __syncthreads();

        const __nv_bfloat16* sAh = dsm + (it & 1) * 30720;
        const __nv_bfloat16* sAl = sAh + 10240;
        const __nv_bfloat16* sWh = sAh + 20480;
        const __nv_bfloat16* sWl = sAh + 25600;

#pragma unroll
        for (int kk = 0; kk < 2; ++kk) {
            uint32_t aH[4][4], aL[4][4];
#pragma unroll
            for (int mt = 0; mt < 4; ++mt) {
                const int r = wm + mt * 16 + (lane & 15);
                const int c = kk * 16 + ((lane >> 4) << 3);
                ldsm4(sptr(sAh + r * 40 + c), aH[mt]);
                ldsm4(sptr(sAl + r * 40 + c), aL[mt]);
            }
            uint32_t bH[2][4], bL[2][4];
#pragma unroll
            for (int np = 0; np < 2; ++np) {
                const int n = wn + np * 16 + nb + nr;
                const int c = kk * 16 + koff;
                ldsm4(sptr(sWh + n * 40 + c), bH[np]);
                ldsm4(sptr(sWl + n * 40 + c), bL[np]);
            }
#pragma unroll
            for (int mt = 0; mt < 4; ++mt)
#pragma unroll
                for (int np = 0; np < 2; ++np)
#pragma unroll
                    for (int j = 0; j < 2; ++j) {
                        const int nt = np * 2 + j;
                        mma_bf16(acc[mt][nt], aH[mt], bH[np][2 * j], bH[np][2 * j + 1]);
                        mma_bf16(acc[mt][nt], aH[mt], bL[np][2 * j], bL[np][2 * j + 1]);
                        mma_bf16(acc[mt][nt], aL[mt], bH[np][2 * j], bH[np][2 * j + 1]);
                    }
        }
        __syncthreads();
    }
#undef MM_LOAD

#pragma unroll
    for (int mt = 0; mt < 4; ++mt)
#pragma unroll
        for (int nt = 0; nt < 4; ++nt) {
            const float* c = acc[mt][nt];
            const int n = bn + wn + nt * 8 + ((lane & 3) << 1);
#pragma unroll
            for (int hf = 0; hf < 2; ++hf) {
                const int m = bm + wm + mt * 16 + (lane >> 2) + hf * 8;
                const float x0 = c[hf * 2], x1 = c[hf * 2 + 1];
                if (MODE == 0) {
                    *(float2*)(Cf + (size_t)m * D_ + n) = make_float2(x0, x1);
                } else {
                    const int b = m >> 11, s = m & (S_ - 1);
                    const int h = n >> 6, dk = n & (DK_ - 1);
                    const size_t o = (((size_t)(b * H_ + h) * S_ + s) << 6) + dk;
                    __nv_bfloat16 h0 = __float2bfloat16(x0), h1 = __float2bfloat16(x1);
                    __nv_bfloat162 ph; ph.x = h0; ph.y = h1;
                    __nv_bfloat162 pl;
                    pl.x = __float2bfloat16(x0 - __bfloat162float(h0));
                    pl.y = __float2bfloat16(x1 - __bfloat162float(h1));
                    *(__nv_bfloat162*)(Ohi + o) = ph;
                    *(__nv_bfloat162*)(Olo + o) = pl;
                }
            }
        }
}

// ---------------------------------------------------------------------------
// Single-pass attention (shift c=0), 512 thr, q-tile 256.
// smem elems: Qh@0 (18432), Ql@18432; stage st @36864+st*18432:
// Kh+0, Kl+4608, Vh+9216, Vl+13824. Total 73728 elems = 147456 B.
// ---------------------------------------------------------------------------
__device__ __forceinline__ void score_tile(
    const __nv_bfloat16* Qh, const __nv_bfloat16* Ql,
    const __nv_bfloat16* Kh, const __nv_bfloat16* Kl,
    int lane, int wid, float acc[8][4])
{
#pragma unroll
    for (int a = 0; a < 8; ++a)
#pragma unroll
        for (int b = 0; b < 4; ++b) acc[a][b] = 0.f;

    const int grp = lane >> 3, koff = (grp & 1) << 3, nb = (grp >> 1) << 3, nr = lane & 7;
    const int r = wid * 16 + (lane & 15);
    const int ca = (lane >> 4) << 3;

#pragma unroll
    for (int kk = 0; kk < 4; ++kk) {
        uint32_t aH[4], aL[4];
        ldsm4(sptr(Qh + r * 72 + kk * 16 + ca), aH);
        ldsm4(sptr(Ql + r * 72 + kk * 16 + ca), aL);
#pragma unroll
        for (int np = 0; np < 4; ++np) {
            uint32_t bH[4], bL[4];
            const int n = np * 16 + nb + nr;
            const int cc = kk * 16 + koff;
            ldsm4(sptr(Kh + n * 72 + cc), bH);
            ldsm4(sptr(Kl + n * 72 + cc), bL);
#pragma unroll
            for (int j = 0; j < 2; ++j) {
                const int nt = np * 2 + j;
                mma_bf16(acc[nt], aH, bH[2 * j], bH[2 * j + 1]);
                mma_bf16(acc[nt], aH, bL[2 * j], bL[2 * j + 1]);
                mma_bf16(acc[nt], aL, bH[2 * j], bH[2 * j + 1]);
            }
        }
    }
}

__global__ __launch_bounds__(512, 1) void attn_single(float* __restrict__ attn)
{
    extern __shared__ __nv_bfloat16 sm[];
    __nv_bfloat16* Qh = sm;
    __nv_bfloat16* Ql = sm + 18432;

    const int qt = gridDim.x - 1 - (int)blockIdx.x;   // big tiles first
    const int bh = blockIdx.y;
    const int tid = threadIdx.x, lane = tid & 31, wid = tid >> 5;
    const int q0 = qt * 256;
    const int nkt = 4 * qt + 4;
    const int grp = lane >> 3, koff = (grp & 1) << 3, nb = (grp >> 1) << 3, nr = lane & 7;

    // ---- load Q tile (256 x 64 hi/lo) ----
#pragma unroll
    for (int t = 0; t < 8; ++t) {
        const int idx = tid + t * 512;               // 0..4095
        const int buf = idx >> 11;
        const int r = (idx >> 3) & 255, c8 = (idx & 7) << 3;
        const __nv_bfloat16* src = buf ? g_Qlo : g_Qhi;
        __nv_bfloat16* dst = buf ? Ql : Qh;
        *(uint4*)&dst[r * 72 + c8] =
            *(const uint4*)(src + (((size_t)bh * S_ + q0 + r) << 6) + c8);
    }

    const int myrow0 = q0 + wid * 16 + (lane >> 2);

#define AT_LOADKV(kt, st) do {                                                   \
    __nv_bfloat16* _bb = sm + 36864 + (st) * 18432;                              \
    const int _r = tid >> 3, _c8 = (tid & 7) << 3;   /* 512 thr, 64 rows */      \
    const size_t _g = (((size_t)bh * S_ + (kt) * 64 + _r) << 6) + _c8;           \
    const int _so = _r * 72 + _c8;                                               \
    cpa16(sptr(_bb + _so),         g_Khi + _g);                                  \
    cpa16(sptr(_bb + 4608 + _so),  g_Klo + _g);                                  \
    cpa16(sptr(_bb + 9216 + _so),  g_Vhi + _g);                                  \
    cpa16(sptr(_bb + 13824 + _so), g_Vlo + _g);                                  \
    } while (0)

    float accO[8][4];
#pragma unroll
    for (int a = 0; a < 8; ++a)
#pragma unroll
        for (int b = 0; b < 4; ++b) accO[a][b] = 0.f;
    float l0 = 0.f, l1 = 0.f;

    AT_LOADKV(0, 0); CPA_COMMIT();
    for (int kt = 0; kt < nkt; ++kt) {
        if (kt + 1 < nkt) { AT_LOADKV(kt + 1, (kt + 1) & 1); CPA_COMMIT(); CPA_WAIT(1); }
        else              { CPA_WAIT(0); }
        __syncthreads();

        const __nv_bfloat16* Kh = sm + 36864 + (kt & 1) * 18432;
        const __nv_bfloat16* Kl = Kh + 4608;
        const __nv_bfloat16* Vh = Kh + 9216;
        const __nv_bfloat16* Vl = Kh + 13824;

        float acc[8][4];
        score_tile(Qh, Ql, Kh, Kl, lane, wid, acc);

        const bool need_mask = (kt * 64 + 63) > (q0 + wid * 16);

#pragma unroll
        for (int t = 0; t < 4; ++t) {
            uint32_t aH[4], aL[4];
#pragma unroll
            for (int g = 0; g < 2; ++g) {
                const int nt = 2 * t + g;
                const int kc = kt * 64 + nt * 8 + ((lane & 3) << 1);
#pragma unroll
                for (int hf = 0; hf < 2; ++hf) {
                    const int qr = myrow0 + hf * 8;
                    float x0 = acc[nt][hf * 2] * 0.125f;
                    float x1 = acc[nt][hf * 2 + 1] * 0.125f;
                    if (need_mask) {
                        if (kc > qr)     x0 = -1e30f;
                        if (kc + 1 > qr) x1 = -1e30f;
                    }
                    const float e0 = __expf(x0);
                    const float e1 = __expf(x1);
                    if (hf) l1 += e0 + e1; else l0 += e0 + e1;
                    float* dst = attn + ((size_t)bh * S_ + qr) * S_ + kc;
                    *(float2*)dst = make_float2(e0, e1);
                    const uint32_t hpk = pack_bf16(e0, e1);
                    __nv_bfloat162 hb = *(__nv_bfloat162*)&hpk;
                    aH[g * 2 + hf] = hpk;
                    aL[g * 2 + hf] = pack_bf16(e0 - __bfloat162float(hb.x),
                                               e1 - __bfloat162float(hb.y));
                }
            }
#pragma unroll
            for (int np = 0; np < 4; ++np) {
                uint32_t bH[4], bL[4];
                const int kr = t * 16 + koff + nr;
                const int nc = np * 16 + nb;
                ldsm4t(sptr(Vh + kr * 72 + nc), bH);
                ldsm4t(sptr(Vl + kr * 72 + nc), bL);
#pragma unroll
                for (int j = 0; j < 2; ++j) {
                    const int nt = np * 2 + j;
                    mma_bf16(accO[nt], aH, bH[2 * j], bH[2 * j + 1]);
                    mma_bf16(accO[nt], aH, bL[2 * j], bL[2 * j + 1]);
                    mma_bf16(accO[nt], aL, bH[2 * j], bH[2 * j + 1]);
                }
            }
        }
        __syncthreads();
    }
#undef AT_LOADKV

    // merge l across the 4 lanes sharing each row
#pragma unroll
    for (int off = 1; off <= 2; off <<= 1) {
        l0 += __shfl_xor_sync(0xffffffffu, l0, off);
        l1 += __shfl_xor_sync(0xffffffffu, l1, off);
    }
    const float il0 = 1.f / l0, il1 = 1.f / l1;

    if ((lane & 3) == 0) {
        g_linv[(size_t)bh * S_ + myrow0]     = il0;
        g_linv[(size_t)bh * S_ + myrow0 + 8] = il1;
    }

    // ---- write O = accO / l as bf16 hi/lo to g_Chi/g_Clo [B,S,D] ----
    const int b = bh >> 4, h = bh & (H_ - 1);
#pragma unroll
    for (int nt = 0; nt < 8; ++nt) {
        const int d = h * DK_ + nt * 8 + ((lane & 3) << 1);
#pragma unroll
        for (int hf = 0; hf < 2; ++hf) {
            const int s = q0 + wid * 16 + (lane >> 2) + hf * 8;
            const float ii = hf ? il1 : il0;
            const float x0 = accO[nt][hf * 2] * ii, x1 = accO[nt][hf * 2 + 1] * ii;
            const size_t o = ((size_t)b * S_ + s) * D_ + d;
            __nv_bfloat162 phh, pll;
            phh.x = __float2bfloat16(x0); phh.y = __float2bfloat16(x1);
            pll.x = __float2bfloat16(x0 - __bfloat162float(phh.x));
            pll.y = __float2bfloat16(x1 - __bfloat162float(phh.y));
            *(__nv_bfloat162*)(g_Chi + o) = phh;
            *(__nv_bfloat162*)(g_Clo + o) = pll;
        }
    }
}

// ---------------------------------------------------------------------------
// Normalize + zero-fill: attn[row, c] = (c <= row) ? E*linv : 0.
// ---------------------------------------------------------------------------
__global__ __launch_bounds__(128) void scale_zero(float* __restrict__ attn)
{
    const int row = blockIdx.x, bh = blockIdx.y;
    const float s = g_linv[(size_t)bh * S_ + row];
    float* p = attn + ((size_t)bh * S_ + row) * S_;
    const int tid = threadIdx.x;
    const int qw = row >> 2;

    for (int i = tid; i < S_ / 4; i += 128) {
        if (i < qw) {
            float4 v = ((const float4*)p)[i];
            v.x *= s; v.y *= s; v.z *= s; v.w *= s;
            ((float4*)p)[i] = v;
        } else if (i == qw) {
            float4 v = ((const float4*)p)[i];
            const int c = i * 4;
            v.x = (c     <= row) ? v.x * s : 0.f;
            v.y = (c + 1 <= row) ? v.y * s : 0.f;
            v.z = (c + 2 <= row) ? v.z * s : 0.f;
            v.w = (c + 3 <= row) ? v.w * s : 0.f;
            ((float4*)p)[i] = v;
        } else {
            ((float4*)p)[i] = make_float4(0.f, 0.f, 0.f, 0.f);
        }
    }
}

// ---------------------------------------------------------------------------
// Launch
// ---------------------------------------------------------------------------
extern "C" void kernel_launch(void* const* d_in, const int* in_sizes, int n_in,
                              void* d_out, int out_size)
{
    const float* q = (const float*)d_in[0];
    const float* k = (const float*)d_in[1];
    const float* v = (const float*)d_in[2];
    const float* W[4] = { (const float*)d_in[4], (const float*)d_in[5],
                          (const float*)d_in[6], (const float*)d_in[7] };

    float* out  = (float*)d_out;
    float* attn = out + (size_t)B_ * S_ * D_;

    __nv_bfloat16 *qhi, *qlo, *khi, *klo, *vhi, *vlo, *whi, *wlo;
    __nv_bfloat16 *Qhi, *Qlo, *Khi, *Klo, *Vhi, *Vlo, *Chi, *Clo;
    cudaGetSymbolAddress((void**)&qhi, g_qhi); cudaGetSymbolAddress((void**)&qlo, g_qlo);
    cudaGetSymbolAddress((void**)&khi, g_khi); cudaGetSymbolAddress((void**)&klo, g_klo);
    cudaGetSymbolAddress((void**)&vhi, g_vhi); cudaGetSymbolAddress((void**)&vlo, g_vlo);
    cudaGetSymbolAddress((void**)&whi, g_whi); cudaGetSymbolAddress((void**)&wlo, g_wlo);
    cudaGetSymbolAddress((void**)&Qhi, g_Qhi); cudaGetSymbolAddress((void**)&Qlo, g_Qlo);
    cudaGetSymbolAddress((void**)&Khi, g_Khi); cudaGetSymbolAddress((void**)&Klo, g_Klo);
    cudaGetSymbolAddress((void**)&Vhi, g_Vhi); cudaGetSymbolAddress((void**)&Vlo, g_Vlo);
    cudaGetSymbolAddress((void**)&Chi, g_Chi); cudaGetSymbolAddress((void**)&Clo, g_Clo);

    static bool attr_set = false;
    if (!attr_set) {
        cudaFuncSetAttribute(mm_tc<0>, cudaFuncAttributeMaxDynamicSharedMemorySize, 122880);
        cudaFuncSetAttribute(mm_tc<1>, cudaFuncAttributeMaxDynamicSharedMemorySize, 122880);
        cudaFuncSetAttribute(attn_single, cudaFuncAttributeMaxDynamicSharedMemorySize, 147456);
        attr_set = true;
    }

    const int n4x = MM_ * D_ / 4;
    const int n4w = D_ * D_ / 4;
    dim3 gG(D_ / 128, MM_ / 256);   // (8, 32)
    dim3 gA(S_ / 256, B_ * H_);     // (8, 64)

    dim3 gSa((n4x + 255) / 256, 3);
    split_acts<<<gSa, 256>>>(q, k, v, qhi, qlo, khi, klo, vhi, vlo, n4x);
    dim3 gSw((n4w + 255) / 256, 4);
    split_wts<<<gSw, 256>>>(W[0], W[1], W[2], W[3], whi, wlo, n4w);

    mm_tc<1><<<gG, 512, 122880>>>(qhi, qlo, whi + 0 * (size_t)D_ * D_, wlo + 0 * (size_t)D_ * D_,
                                  nullptr, Qhi, Qlo);
    mm_tc<1><<<gG, 512, 122880>>>(khi, klo, whi + 1 * (size_t)D_ * D_, wlo + 1 * (size_t)D_ * D_,
                                  nullptr, Khi, Klo);
    mm_tc<1><<<gG, 512, 122880>>>(vhi, vlo, whi + 2 * (size_t)D_ * D_, wlo + 2 * (size_t)D_ * D_,
                                  nullptr, Vhi, Vlo);

    attn_single<<<gA, 512, 147456>>>(attn);

    dim3 gZ(S_, B_ * H_);
    scale_zero<<<gZ, 128>>>(attn);

    mm_tc<0><<<gG, 512, 122880>>>(Chi, Clo, whi + 3 * (size_t)D_ * D_, wlo + 3 * (size_t)D_ * D_,
                                  out, nullptr, nullptr);
}

// round 8
// speedup vs baseline: 2.6797x; 1.0120x over previous
#include <cuda_runtime.h>
#include <cuda_bf16.h>
#include <cstdint>

#define B_  4
#define S_  2048
#define D_  1024
#define H_  16
#define DK_ 64
#define MM_ (B_ * S_)          // 8192

// ---------------------------------------------------------------------------
// Scratch (device globals)
// ---------------------------------------------------------------------------
__device__ __nv_bfloat16 g_qhi[MM_ * D_], g_qlo[MM_ * D_];
__device__ __nv_bfloat16 g_khi[MM_ * D_], g_klo[MM_ * D_];
__device__ __nv_bfloat16 g_vhi[MM_ * D_], g_vlo[MM_ * D_];
__device__ __nv_bfloat16 g_whi[4][D_ * D_], g_wlo[4][D_ * D_];
__device__ __nv_bfloat16 g_Qhi[MM_ * D_], g_Qlo[MM_ * D_];   // [B,H,S,DK]
__device__ __nv_bfloat16 g_Khi[MM_ * D_], g_Klo[MM_ * D_];
__device__ __nv_bfloat16 g_Vhi[MM_ * D_], g_Vlo[MM_ * D_];
__device__ __nv_bfloat16 g_Chi[MM_ * D_], g_Clo[MM_ * D_];   // [B,S,D]
__device__ float g_linv[B_ * H_ * S_];                        // 1/rowsum

// ---------------------------------------------------------------------------
// PTX helpers
// ---------------------------------------------------------------------------
__device__ __forceinline__ void ldsm4(uint32_t addr, uint32_t* r) {
    asm volatile("ldmatrix.sync.aligned.m8n8.x4.shared.b16 {%0,%1,%2,%3}, [%4];"
        : "=r"(r[0]), "=r"(r[1]), "=r"(r[2]), "=r"(r[3]) : "r"(addr));
}
__device__ __forceinline__ void ldsm4t(uint32_t addr, uint32_t* r) {
    asm volatile("ldmatrix.sync.aligned.m8n8.x4.trans.shared.b16 {%0,%1,%2,%3}, [%4];"
        : "=r"(r[0]), "=r"(r[1]), "=r"(r[2]), "=r"(r[3]) : "r"(addr));
}
__device__ __forceinline__ void mma_bf16(float* c, const uint32_t* a, uint32_t b0, uint32_t b1) {
    asm volatile("mma.sync.aligned.m16n8k16.row.col.f32.bf16.bf16.f32 "
        "{%0,%1,%2,%3}, {%4,%5,%6,%7}, {%8,%9}, {%0,%1,%2,%3};"
        : "+f"(c[0]), "+f"(c[1]), "+f"(c[2]), "+f"(c[3])
        : "r"(a[0]), "r"(a[1]), "r"(a[2]), "r"(a[3]), "r"(b0), "r"(b1));
}
__device__ __forceinline__ uint32_t sptr(const void* p) {
    return (uint32_t)__cvta_generic_to_shared(p);
}
__device__ __forceinline__ void cpa16(uint32_t s, const void* g) {
    asm volatile("cp.async.cg.shared.global [%0], [%1], 16;" :: "r"(s), "l"(g));
}
#define CPA_COMMIT() asm volatile("cp.async.commit_group;" ::: "memory")
#define CPA_WAIT(n)  asm volatile("cp.async.wait_group %0;" :: "n"(n) : "memory")
__device__ __forceinline__ uint32_t pack_bf16(float x, float y) {
    __nv_bfloat162 t; t.x = __float2bfloat16(x); t.y = __float2bfloat16(y);
    return *(uint32_t*)&t;
}

// ---------------------------------------------------------------------------
// Split fp32 -> (hi, lo) bf16. Batched variants.
// ---------------------------------------------------------------------------
__device__ __forceinline__ void split4(const float* __restrict__ x,
    __nv_bfloat16* __restrict__ hi, __nv_bfloat16* __restrict__ lo, int i)
{
    float4 v = ((const float4*)x)[i];
    __nv_bfloat16 h0 = __float2bfloat16(v.x), h1 = __float2bfloat16(v.y);
    __nv_bfloat16 h2 = __float2bfloat16(v.z), h3 = __float2bfloat16(v.w);
    __nv_bfloat162 ph0; ph0.x = h0; ph0.y = h1;
    __nv_bfloat162 ph1; ph1.x = h2; ph1.y = h3;
    __nv_bfloat162 pl0; pl0.x = __float2bfloat16(v.x - __bfloat162float(h0));
    pl0.y = __float2bfloat16(v.y - __bfloat162float(h1));
    __nv_bfloat162 pl1; pl1.x = __float2bfloat16(v.z - __bfloat162float(h2));
    pl1.y = __float2bfloat16(v.w - __bfloat162float(h3));
    ((__nv_bfloat162*)hi)[2 * i]     = ph0;
    ((__nv_bfloat162*)hi)[2 * i + 1] = ph1;
    ((__nv_bfloat162*)lo)[2 * i]     = pl0;
    ((__nv_bfloat162*)lo)[2 * i + 1] = pl1;
}

__global__ __launch_bounds__(256) void split_acts(
    const float* q, const float* k, const float* v,
    __nv_bfloat16* qh, __nv_bfloat16* ql, __nv_bfloat16* kh, __nv_bfloat16* kl,
    __nv_bfloat16* vh, __nv_bfloat16* vl, int n4)
{
    int i = blockIdx.x * blockDim.x + threadIdx.x;
    if (i >= n4) return;
    const int z = blockIdx.y;
    const float* x = (z == 0) ? q : (z == 1) ? k : v;
    __nv_bfloat16* hi = (z == 0) ? qh : (z == 1) ? kh : vh;
    __nv_bfloat16* lo = (z == 0) ? ql : (z == 1) ? kl : vl;
    split4(x, hi, lo, i);
}

__global__ __launch_bounds__(256) void split_wts(
    const float* w0, const float* w1, const float* w2, const float* w3,
    __nv_bfloat16* hi, __nv_bfloat16* lo, int n4)
{
    int i = blockIdx.x * blockDim.x + threadIdx.x;
    if (i >= n4) return;
    const int z = blockIdx.y;
    const float* x = (z == 0) ? w0 : (z == 1) ? w1 : (z == 2) ? w2 : w3;
    split4(x, hi + (size_t)z * D_ * D_, lo + (size_t)z * D_ * D_, i);
}

// ---------------------------------------------------------------------------
// bf16x3 GEMM, cp.async 2-stage pipeline. C = A @ W^T.
// Block tile 256x128, BK=32, 256 thr (8 warps), warp tile 64x64.
// smem/stage: Ah 10240, Al 10240, Wh 5120, Wl 5120 elems; 2 stages = 122880 B.
// ---------------------------------------------------------------------------
template <int MODE>
__global__ __launch_bounds__(256, 1) void mm_tc(
    const __nv_bfloat16* __restrict__ Ahi, const __nv_bfloat16* __restrict__ Alo,
    const __nv_bfloat16* __restrict__ Whi, const __nv_bfloat16* __restrict__ Wlo,
    float* __restrict__ Cf,
    __nv_bfloat16* __restrict__ Ohi, __nv_bfloat16* __restrict__ Olo)
{
    extern __shared__ __nv_bfloat16 dsm[];

    const int tid = threadIdx.x, lane = tid & 31, wid = tid >> 5;
    const int bm = blockIdx.y * 256, bn = blockIdx.x * 128;
    const int wm = (wid >> 1) * 64, wn = (wid & 1) * 64;

    float acc[4][8][4];      // mt, nt, frag
#pragma unroll
    for (int a = 0; a < 4; ++a)
#pragma unroll
        for (int b = 0; b < 8; ++b)
#pragma unroll
            for (int c = 0; c < 4; ++c) acc[a][b][c] = 0.f;

    const int grp = lane >> 3, koff = (grp & 1) << 3, nb = (grp >> 1) << 3, nr = lane & 7;

#define MM_LOAD(it, st) do {                                                     \
    const int _k0 = (it) * 32;                                                   \
    __nv_bfloat16* _bb = dsm + (st) * 30720;                                     \
    _Pragma("unroll")                                                            \
    for (int _t = 0; _t < 4; ++_t) {          /* A: 256 rows */                  \
        const int _idx = tid + _t * 256;                                         \
        const int _row = _idx >> 2, _c8 = (_idx & 3) << 3;                       \
        const int _so = _row * 40 + _c8;                                         \
        cpa16(sptr(_bb + _so),         Ahi + (size_t)(bm + _row) * D_ + _k0 + _c8); \
        cpa16(sptr(_bb + 10240 + _so), Alo + (size_t)(bm + _row) * D_ + _k0 + _c8); \
    }                                                                            \
    _Pragma("unroll")                                                            \
    for (int _t = 0; _t < 2; ++_t) {          /* W: 128 rows */                  \
        const int _idx = tid + _t * 256;                                         \
        const int _row = _idx >> 2, _c8 = (_idx & 3) << 3;                       \
        const int _so = _row * 40 + _c8;                                         \
        cpa16(sptr(_bb + 20480 + _so), Whi + (size_t)(bn + _row) * D_ + _k0 + _c8); \
        cpa16(sptr(_bb + 25600 + _so), Wlo + (size_t)(bn + _row) * D_ + _k0 + _c8); \
    } } while (0)

    MM_LOAD(0, 0); CPA_COMMIT();

    for (int it = 0; it < 32; ++it) {
        if (it + 1 < 32) { MM_LOAD(it + 1, (it + 1) & 1); CPA_COMMIT(); CPA_WAIT(1); }
        else             { CPA_WAIT(0); }
        __syncthreads();

        const __nv_bfloat16* sAh = dsm + (it & 1) * 30720;
        const __nv_bfloat16* sAl = sAh + 10240;
        const __nv_bfloat16* sWh = sAh + 20480;
        const __nv_bfloat16* sWl = sAh + 25600;

#pragma unroll
        for (int kk = 0; kk < 2; ++kk) {
            uint32_t aH[4][4], aL[4][4];
#pragma unroll
            for (int mt = 0; mt < 4; ++mt) {
                const int r = wm + mt * 16 + (lane & 15);
                const int c = kk * 16 + ((lane >> 4) << 3);
                ldsm4(sptr(sAh + r * 40 + c), aH[mt]);
                ldsm4(sptr(sAl + r * 40 + c), aL[mt]);
            }
#pragma unroll
            for (int np = 0; np < 4; ++np) {
                uint32_t bH[4], bL[4];
                const int n = wn + np * 16 + nb + nr;
                const int c = kk * 16 + koff;
                ldsm4(sptr(sWh + n * 40 + c), bH);
                ldsm4(sptr(sWl + n * 40 + c), bL);
#pragma unroll
                for (int mt = 0; mt < 4; ++mt)
#pragma unroll
                    for (int j = 0; j < 2; ++j) {
                        const int nt = np * 2 + j;
                        mma_bf16(acc[mt][nt], aH[mt], bH[2 * j], bH[2 * j + 1]);
                        mma_bf16(acc[mt][nt], aH[mt], bL[2 * j], bL[2 * j + 1]);
                        mma_bf16(acc[mt][nt], aL[mt], bH[2 * j], bH[2 * j + 1]);
                    }
            }
        }
        __syncthreads();
    }
#undef MM_LOAD

#pragma unroll
    for (int mt = 0; mt < 4; ++mt)
#pragma unroll
        for (int nt = 0; nt < 8; ++nt) {
            const float* c = acc[mt][nt];
            const int n = bn + wn + nt * 8 + ((lane & 3) << 1);
#pragma unroll
            for (int hf = 0; hf < 2; ++hf) {
                const int m = bm + wm + mt * 16 + (lane >> 2) + hf * 8;
                const float x0 = c[hf * 2], x1 = c[hf * 2 + 1];
                if (MODE == 0) {
                    *(float2*)(Cf + (size_t)m * D_ + n) = make_float2(x0, x1);
                } else {
                    const int b = m >> 11, s = m & (S_ - 1);
                    const int h = n >> 6, dk = n & (DK_ - 1);
                    const size_t o = (((size_t)(b * H_ + h) * S_ + s) << 6) + dk;
                    __nv_bfloat16 h0 = __float2bfloat16(x0), h1 = __float2bfloat16(x1);
                    __nv_bfloat162 ph; ph.x = h0; ph.y = h1;
                    __nv_bfloat162 pl;
                    pl.x = __float2bfloat16(x0 - __bfloat162float(h0));
                    pl.y = __float2bfloat16(x1 - __bfloat162float(h1));
                    *(__nv_bfloat162*)(Ohi + o) = ph;
                    *(__nv_bfloat162*)(Olo + o) = pl;
                }
            }
        }
}

// ---------------------------------------------------------------------------
// Single-pass attention (shift c=0), 256 thr (8 warps), q-tile 256,
// warp tile 32 q-rows x 64 k-cols.
// smem elems: Qh@0 (18432), Ql@18432; stage st @36864+st*18432:
// Kh+0, Kl+4608, Vh+9216, Vl+13824. Total 73728 elems = 147456 B.
// ---------------------------------------------------------------------------
__global__ __launch_bounds__(256, 1) void attn_single(float* __restrict__ attn)
{
    extern __shared__ __nv_bfloat16 sm[];
    __nv_bfloat16* Qh = sm;
    __nv_bfloat16* Ql = sm + 18432;

    const int qt = gridDim.x - 1 - (int)blockIdx.x;   // big tiles first
    const int bh = blockIdx.y;
    const int tid = threadIdx.x, lane = tid & 31, wid = tid >> 5;
    const int q0 = qt * 256;
    const int nkt = 4 * qt + 4;
    const int grp = lane >> 3, koff = (grp & 1) << 3, nb = (grp >> 1) << 3, nr = lane & 7;
    const int wrow = wid * 32;

    // ---- load Q tile (256 x 64 hi/lo) ----
#pragma unroll
    for (int t = 0; t < 16; ++t) {
        const int idx = tid + t * 256;               // 0..4095 uint4 slots
        const int buf = idx >> 11;
        const int r = (idx >> 3) & 255, c8 = (idx & 7) << 3;
        const __nv_bfloat16* src = buf ? g_Qlo : g_Qhi;
        __nv_bfloat16* dst = buf ? Ql : Qh;
        *(uint4*)&dst[r * 72 + c8] =
            *(const uint4*)(src + (((size_t)bh * S_ + q0 + r) << 6) + c8);
    }

    const int lrow = lane >> 2;                      // 0..7

#define AT_LOADKV(kt, st) do {                                                   \
    __nv_bfloat16* _bb = sm + 36864 + (st) * 18432;                              \
    _Pragma("unroll")                                                            \
    for (int _t = 0; _t < 2; ++_t) {                                             \
        const int _idx = tid + _t * 256;             /* 64 rows x 8 chunks */    \
        const int _r = _idx >> 3, _c8 = (_idx & 7) << 3;                         \
        const size_t _g = (((size_t)bh * S_ + (kt) * 64 + _r) << 6) + _c8;       \
        const int _so = _r * 72 + _c8;                                           \
        cpa16(sptr(_bb + _so),         g_Khi + _g);                              \
        cpa16(sptr(_bb + 4608 + _so),  g_Klo + _g);                              \
        cpa16(sptr(_bb + 9216 + _so),  g_Vhi + _g);                              \
        cpa16(sptr(_bb + 13824 + _so), g_Vlo + _g);                              \
    } } while (0)

    float accO[2][8][4];
#pragma unroll
    for (int a = 0; a < 2; ++a)
#pragma unroll
        for (int b = 0; b < 8; ++b)
#pragma unroll
            for (int c = 0; c < 4; ++c) accO[a][b][c] = 0.f;
    float lsum[2][2] = {{0.f, 0.f}, {0.f, 0.f}};

    AT_LOADKV(0, 0); CPA_COMMIT();
    for (int kt = 0; kt < nkt; ++kt) {
        if (kt + 1 < nkt) { AT_LOADKV(kt + 1, (kt + 1) & 1); CPA_COMMIT(); CPA_WAIT(1); }
        else              { CPA_WAIT(0); }
        __syncthreads();

        const __nv_bfloat16* Kh = sm + 36864 + (kt & 1) * 18432;
        const __nv_bfloat16* Kl = Kh + 4608;
        const __nv_bfloat16* Vh = Kh + 9216;
        const __nv_bfloat16* Vl = Kh + 13824;

        // ---- scores: 32x64 per warp ----
        float acc[2][8][4];
#pragma unroll
        for (int a = 0; a < 2; ++a)
#pragma unroll
            for (int b = 0; b < 8; ++b)
#pragma unroll
                for (int c = 0; c < 4; ++c) acc[a][b][c] = 0.f;

#pragma unroll
        for (int kk = 0; kk < 4; ++kk) {
            uint32_t aH[2][4], aL[2][4];
#pragma unroll
            for (int mt = 0; mt < 2; ++mt) {
                const int r = wrow + mt * 16 + (lane & 15);
                const int c = kk * 16 + ((lane >> 4) << 3);
                ldsm4(sptr(Qh + r * 72 + c), aH[mt]);
                ldsm4(sptr(Ql + r * 72 + c), aL[mt]);
            }
#pragma unroll
            for (int np = 0; np < 4; ++np) {
                uint32_t bH[4], bL[4];
                const int n = np * 16 + nb + nr;
                const int cc = kk * 16 + koff;
                ldsm4(sptr(Kh + n * 72 + cc), bH);
                ldsm4(sptr(Kl + n * 72 + cc), bL);
#pragma unroll
                for (int mt = 0; mt < 2; ++mt)
#pragma unroll
                    for (int j = 0; j < 2; ++j) {
                        const int nt = np * 2 + j;
                        mma_bf16(acc[mt][nt], aH[mt], bH[2 * j], bH[2 * j + 1]);
                        mma_bf16(acc[mt][nt], aH[mt], bL[2 * j], bL[2 * j + 1]);
                        mma_bf16(acc[mt][nt], aL[mt], bH[2 * j], bH[2 * j + 1]);
                    }
            }
        }

        // ---- exp + E write + l accum + pack + PV MMA, per 16-wide k slice ----
#pragma unroll
        for (int t = 0; t < 4; ++t) {
            uint32_t pH[2][4], pL[2][4];
#pragma unroll
            for (int mt = 0; mt < 2; ++mt) {
                const bool need_mask = (kt * 64 + 63) > (q0 + wrow + mt * 16);
#pragma unroll
                for (int g = 0; g < 2; ++g) {
                    const int nt = 2 * t + g;
                    const int kc = kt * 64 + nt * 8 + ((lane & 3) << 1);
#pragma unroll
                    for (int hf = 0; hf < 2; ++hf) {
                        const int qr = q0 + wrow + mt * 16 + lrow + hf * 8;
                        float x0 = acc[mt][nt][hf * 2] * 0.125f;
                        float x1 = acc[mt][nt][hf * 2 + 1] * 0.125f;
                        if (need_mask) {
                            if (kc > qr)     x0 = -1e30f;
                            if (kc + 1 > qr) x1 = -1e30f;
                        }
                        const float e0 = __expf(x0);
                        const float e1 = __expf(x1);
                        lsum[mt][hf] += e0 + e1;
                        float* dst = attn + ((size_t)bh * S_ + qr) * S_ + kc;
                        *(float2*)dst = make_float2(e0, e1);
                        const uint32_t hpk = pack_bf16(e0, e1);
                        __nv_bfloat162 hb = *(__nv_bfloat162*)&hpk;
                        pH[mt][g * 2 + hf] = hpk;
                        pL[mt][g * 2 + hf] = pack_bf16(e0 - __bfloat162float(hb.x),
                                                       e1 - __bfloat162float(hb.y));
                    }
                }
            }
#pragma unroll
            for (int np = 0; np < 4; ++np) {
                uint32_t bH[4], bL[4];
                const int kr = t * 16 + koff + nr;
                const int nc = np * 16 + nb;
                ldsm4t(sptr(Vh + kr * 72 + nc), bH);
                ldsm4t(sptr(Vl + kr * 72 + nc), bL);
#pragma unroll
                for (int mt = 0; mt < 2; ++mt)
#pragma unroll
                    for (int j = 0; j < 2; ++j) {
                        const int nt = np * 2 + j;
                        mma_bf16(accO[mt][nt], pH[mt], bH[2 * j], bH[2 * j + 1]);
                        mma_bf16(accO[mt][nt], pH[mt], bL[2 * j], bL[2 * j + 1]);
                        mma_bf16(accO[mt][nt], pL[mt], bH[2 * j], bH[2 * j + 1]);
                    }
            }
        }
        __syncthreads();
    }
#undef AT_LOADKV

    // merge l across the 4 lanes sharing each row
    float il[2][2];
#pragma unroll
    for (int mt = 0; mt < 2; ++mt)
#pragma unroll
        for (int hf = 0; hf < 2; ++hf) {
            float l = lsum[mt][hf];
#pragma unroll
            for (int off = 1; off <= 2; off <<= 1)
                l += __shfl_xor_sync(0xffffffffu, l, off);
            il[mt][hf] = 1.f / l;
        }

    if ((lane & 3) == 0) {
#pragma unroll
        for (int mt = 0; mt < 2; ++mt)
#pragma unroll
            for (int hf = 0; hf < 2; ++hf)
                g_linv[(size_t)bh * S_ + q0 + wrow + mt * 16 + lrow + hf * 8] = il[mt][hf];
    }

    // ---- write O = accO / l as bf16 hi/lo to g_Chi/g_Clo [B,S,D] ----
    const int b = bh >> 4, h = bh & (H_ - 1);
#pragma unroll
    for (int mt = 0; mt < 2; ++mt)
#pragma unroll
        for (int nt = 0; nt < 8; ++nt) {
            const int d = h * DK_ + nt * 8 + ((lane & 3) << 1);
#pragma unroll
            for (int hf = 0; hf < 2; ++hf) {
                const int s = q0 + wrow + mt * 16 + lrow + hf * 8;
                const float ii = il[mt][hf];
                const float x0 = accO[mt][nt][hf * 2] * ii;
                const float x1 = accO[mt][nt][hf * 2 + 1] * ii;
                const size_t o = ((size_t)b * S_ + s) * D_ + d;
                __nv_bfloat162 phh, pll;
                phh.x = __float2bfloat16(x0); phh.y = __float2bfloat16(x1);
                pll.x = __float2bfloat16(x0 - __bfloat162float(phh.x));
                pll.y = __float2bfloat16(x1 - __bfloat162float(phh.y));
                *(__nv_bfloat162*)(g_Chi + o) = phh;
                *(__nv_bfloat162*)(g_Clo + o) = pll;
            }
        }
}

// ---------------------------------------------------------------------------
// Normalize + zero-fill: attn[row, c] = (c <= row) ? E*linv : 0.
// ---------------------------------------------------------------------------
__global__ __launch_bounds__(128) void scale_zero(float* __restrict__ attn)
{
    const int row = blockIdx.x, bh = blockIdx.y;
    const float s = g_linv[(size_t)bh * S_ + row];
    float* p = attn + ((size_t)bh * S_ + row) * S_;
    const int tid = threadIdx.x;
    const int qw = row >> 2;

    for (int i = tid; i < S_ / 4; i += 128) {
        if (i < qw) {
            float4 v = ((const float4*)p)[i];
            v.x *= s; v.y *= s; v.z *= s; v.w *= s;
            ((float4*)p)[i] = v;
        } else if (i == qw) {
            float4 v = ((const float4*)p)[i];
            const int c = i * 4;
            v.x = (c     <= row) ? v.x * s : 0.f;
            v.y = (c + 1 <= row) ? v.y * s : 0.f;
            v.z = (c + 2 <= row) ? v.z * s : 0.f;
            v.w = (c + 3 <= row) ? v.w * s : 0.f;
            ((float4*)p)[i] = v;
        } else {
            ((float4*)p)[i] = make_float4(0.f, 0.f, 0.f, 0.f);
        }
    }
}

// ---------------------------------------------------------------------------
// Launch
// ---------------------------------------------------------------------------
extern "C" void kernel_launch(void* const* d_in, const int* in_sizes, int n_in,
                              void* d_out, int out_size)
{
    const float* q = (const float*)d_in[0];
    const float* k = (const float*)d_in[1];
    const float* v = (const float*)d_in[2];
    const float* W[4] = { (const float*)d_in[4], (const float*)d_in[5],
                          (const float*)d_in[6], (const float*)d_in[7] };

    float* out  = (float*)d_out;
    float* attn = out + (size_t)B_ * S_ * D_;

    __nv_bfloat16 *qhi, *qlo, *khi, *klo, *vhi, *vlo, *whi, *wlo;
    __nv_bfloat16 *Qhi, *Qlo, *Khi, *Klo, *Vhi, *Vlo, *Chi, *Clo;
    cudaGetSymbolAddress((void**)&qhi, g_qhi); cudaGetSymbolAddress((void**)&qlo, g_qlo);
    cudaGetSymbolAddress((void**)&khi, g_khi); cudaGetSymbolAddress((void**)&klo, g_klo);
    cudaGetSymbolAddress((void**)&vhi, g_vhi); cudaGetSymbolAddress((void**)&vlo, g_vlo);
    cudaGetSymbolAddress((void**)&whi, g_whi); cudaGetSymbolAddress((void**)&wlo, g_wlo);
    cudaGetSymbolAddress((void**)&Qhi, g_Qhi); cudaGetSymbolAddress((void**)&Qlo, g_Qlo);
    cudaGetSymbolAddress((void**)&Khi, g_Khi); cudaGetSymbolAddress((void**)&Klo, g_Klo);
    cudaGetSymbolAddress((void**)&Vhi, g_Vhi); cudaGetSymbolAddress((void**)&Vlo, g_Vlo);
    cudaGetSymbolAddress((void**)&Chi, g_Chi); cudaGetSymbolAddress((void**)&Clo, g_Clo);

    static bool attr_set = false;
    if (!attr_set) {
        cudaFuncSetAttribute(mm_tc<0>, cudaFuncAttributeMaxDynamicSharedMemorySize, 122880);
        cudaFuncSetAttribute(mm_tc<1>, cudaFuncAttributeMaxDynamicSharedMemorySize, 122880);
        cudaFuncSetAttribute(attn_single, cudaFuncAttributeMaxDynamicSharedMemorySize, 147456);
        attr_set = true;
    }

    const int n4x = MM_ * D_ / 4;
    const int n4w = D_ * D_ / 4;
    dim3 gG(D_ / 128, MM_ / 256);   // (8, 32)
    dim3 gA(S_ / 256, B_ * H_);     // (8, 64)

    dim3 gSa((n4x + 255) / 256, 3);
    split_acts<<<gSa, 256>>>(q, k, v, qhi, qlo, khi, klo, vhi, vlo, n4x);
    dim3 gSw((n4w + 255) / 256, 4);
    split_wts<<<gSw, 256>>>(W[0], W[1], W[2], W[3], whi, wlo, n4w);

    mm_tc<1><<<gG, 256, 122880>>>(qhi, qlo, whi + 0 * (size_t)D_ * D_, wlo + 0 * (size_t)D_ * D_,
                                  nullptr, Qhi, Qlo);
    mm_tc<1><<<gG, 256, 122880>>>(khi, klo, whi + 1 * (size_t)D_ * D_, wlo + 1 * (size_t)D_ * D_,
                                  nullptr, Khi, Klo);
    mm_tc<1><<<gG, 256, 122880>>>(vhi, vlo, whi + 2 * (size_t)D_ * D_, wlo + 2 * (size_t)D_ * D_,
                                  nullptr, Vhi, Vlo);

    attn_single<<<gA, 256, 147456>>>(attn);

    dim3 gZ(S_, B_ * H_);
    scale_zero<<<gZ, 128>>>(attn);

    mm_tc<0><<<gG, 256, 122880>>>(Chi, Clo, whi + 3 * (size_t)D_ * D_, wlo + 3 * (size_t)D_ * D_,
                                  out, nullptr, nullptr);
}

// round 9
// speedup vs baseline: 2.7221x; 1.0158x over previous
#include <cuda_runtime.h>
#include <cuda_bf16.h>
#include <cstdint>

#define B_  4
#define S_  2048
#define D_  1024
#define H_  16
#define DK_ 64
#define MM_ (B_ * S_)          // 8192

// ---------------------------------------------------------------------------
// Scratch (device globals)
// ---------------------------------------------------------------------------
__device__ __nv_bfloat16 g_qhi[MM_ * D_], g_qlo[MM_ * D_];
__device__ __nv_bfloat16 g_khi[MM_ * D_], g_klo[MM_ * D_];
__device__ __nv_bfloat16 g_vhi[MM_ * D_], g_vlo[MM_ * D_];
__device__ __nv_bfloat16 g_whi[4][D_ * D_], g_wlo[4][D_ * D_];
__device__ __nv_bfloat16 g_Qhi[MM_ * D_], g_Qlo[MM_ * D_];   // [B,H,S,DK]
__device__ __nv_bfloat16 g_Khi[MM_ * D_], g_Klo[MM_ * D_];
__device__ __nv_bfloat16 g_Vhi[MM_ * D_], g_Vlo[MM_ * D_];
__device__ __nv_bfloat16 g_Chi[MM_ * D_], g_Clo[MM_ * D_];   // [B,S,D]

// ---------------------------------------------------------------------------
// PTX helpers
// ---------------------------------------------------------------------------
__device__ __forceinline__ void ldsm4(uint32_t addr, uint32_t* r) {
    asm volatile("ldmatrix.sync.aligned.m8n8.x4.shared.b16 {%0,%1,%2,%3}, [%4];"
        : "=r"(r[0]), "=r"(r[1]), "=r"(r[2]), "=r"(r[3]) : "r"(addr));
}
__device__ __forceinline__ void ldsm4t(uint32_t addr, uint32_t* r) {
    asm volatile("ldmatrix.sync.aligned.m8n8.x4.trans.shared.b16 {%0,%1,%2,%3}, [%4];"
        : "=r"(r[0]), "=r"(r[1]), "=r"(r[2]), "=r"(r[3]) : "r"(addr));
}
__device__ __forceinline__ void mma_bf16(float* c, const uint32_t* a, uint32_t b0, uint32_t b1) {
    asm volatile("mma.sync.aligned.m16n8k16.row.col.f32.bf16.bf16.f32 "
        "{%0,%1,%2,%3}, {%4,%5,%6,%7}, {%8,%9}, {%0,%1,%2,%3};"
        : "+f"(c[0]), "+f"(c[1]), "+f"(c[2]), "+f"(c[3])
        : "r"(a[0]), "r"(a[1]), "r"(a[2]), "r"(a[3]), "r"(b0), "r"(b1));
}
__device__ __forceinline__ uint32_t sptr(const void* p) {
    return (uint32_t)__cvta_generic_to_shared(p);
}
__device__ __forceinline__ void cpa16(uint32_t s, const void* g) {
    asm volatile("cp.async.cg.shared.global [%0], [%1], 16;" :: "r"(s), "l"(g));
}
#define CPA_COMMIT() asm volatile("cp.async.commit_group;" ::: "memory")
#define CPA_WAIT(n)  asm volatile("cp.async.wait_group %0;" :: "n"(n) : "memory")
__device__ __forceinline__ uint32_t pack_bf16(float x, float y) {
    __nv_bfloat162 t; t.x = __float2bfloat16(x); t.y = __float2bfloat16(y);
    return *(uint32_t*)&t;
}

// ---------------------------------------------------------------------------
// Split fp32 -> (hi, lo) bf16
// ---------------------------------------------------------------------------
__device__ __forceinline__ void split4(const float* __restrict__ x,
    __nv_bfloat16* __restrict__ hi, __nv_bfloat16* __restrict__ lo, int i)
{
    float4 v = ((const float4*)x)[i];
    __nv_bfloat16 h0 = __float2bfloat16(v.x), h1 = __float2bfloat16(v.y);
    __nv_bfloat16 h2 = __float2bfloat16(v.z), h3 = __float2bfloat16(v.w);
    __nv_bfloat162 ph0; ph0.x = h0; ph0.y = h1;
    __nv_bfloat162 ph1; ph1.x = h2; ph1.y = h3;
    __nv_bfloat162 pl0; pl0.x = __float2bfloat16(v.x - __bfloat162float(h0));
    pl0.y = __float2bfloat16(v.y - __bfloat162float(h1));
    __nv_bfloat162 pl1; pl1.x = __float2bfloat16(v.z - __bfloat162float(h2));
    pl1.y = __float2bfloat16(v.w - __bfloat162float(h3));
    ((__nv_bfloat162*)hi)[2 * i]     = ph0;
    ((__nv_bfloat162*)hi)[2 * i + 1] = ph1;
    ((__nv_bfloat162*)lo)[2 * i]     = pl0;
    ((__nv_bfloat162*)lo)[2 * i + 1] = pl1;
}

__global__ __launch_bounds__(256) void split_kernel(
    const float* __restrict__ x, __nv_bfloat16* __restrict__ hi,
    __nv_bfloat16* __restrict__ lo, int n4)
{
    int i = blockIdx.x * blockDim.x + threadIdx.x;
    if (i < n4) split4(x, hi, lo, i);
}

__global__ __launch_bounds__(256) void split_wts2(
    const float* wa, const float* wb,
    __nv_bfloat16* hi, __nv_bfloat16* lo, int n4)
{
    int i = blockIdx.x * blockDim.x + threadIdx.x;
    if (i >= n4) return;
    const int z = blockIdx.y;
    split4(z ? wb : wa, hi + (size_t)z * D_ * D_, lo + (size_t)z * D_ * D_, i);
}

// ---------------------------------------------------------------------------
// bf16x3 GEMM, cp.async 2-stage pipeline, 2 CTAs/SM target.
// 128x128 tile, BK=32, 256 thr (8 warps, warp tile 64x32), regs capped 128.
// smem/stage 20480 elems; 2 stages = 81920 B.
// MODE 1: merged QKV (grid.x = 24, wsel = bx>>3), split-head bf16 hi/lo out.
// MODE 0: single GEMM (grid.x = 8), fp32 row-major out.
// ---------------------------------------------------------------------------
template <int MODE>
__global__ __launch_bounds__(256, 2) void mm_tc(
    const __nv_bfloat16* __restrict__ A0h, const __nv_bfloat16* __restrict__ A0l,
    const __nv_bfloat16* __restrict__ A1h, const __nv_bfloat16* __restrict__ A1l,
    const __nv_bfloat16* __restrict__ A2h, const __nv_bfloat16* __restrict__ A2l,
    const __nv_bfloat16* __restrict__ Wbh, const __nv_bfloat16* __restrict__ Wbl,
    float* __restrict__ Cf,
    __nv_bfloat16* __restrict__ O0h, __nv_bfloat16* __restrict__ O0l,
    __nv_bfloat16* __restrict__ O1h, __nv_bfloat16* __restrict__ O1l,
    __nv_bfloat16* __restrict__ O2h, __nv_bfloat16* __restrict__ O2l)
{
    extern __shared__ __nv_bfloat16 dsm[];

    const int tid = threadIdx.x, lane = tid & 31, wid = tid >> 5;
    const int wsel = (MODE == 1) ? (blockIdx.x >> 3) : 0;
    const int bn = (MODE == 1) ? ((blockIdx.x & 7) * 128) : (blockIdx.x * 128);
    const int bm = blockIdx.y * 128;
    const int wm = (wid >> 2) * 64, wn = (wid & 3) * 32;

    const __nv_bfloat16* Ah = (MODE == 1) ? (wsel == 0 ? A0h : wsel == 1 ? A1h : A2h) : A0h;
    const __nv_bfloat16* Al = (MODE == 1) ? (wsel == 0 ? A0l : wsel == 1 ? A1l : A2l) : A0l;
    const __nv_bfloat16* Whi = Wbh + (size_t)wsel * D_ * D_;
    const __nv_bfloat16* Wlo = Wbl + (size_t)wsel * D_ * D_;
    __nv_bfloat16* Ohi = (wsel == 0) ? O0h : (wsel == 1) ? O1h : O2h;
    __nv_bfloat16* Olo = (wsel == 0) ? O0l : (wsel == 1) ? O1l : O2l;

    float acc[4][4][4];
#pragma unroll
    for (int a = 0; a < 4; ++a)
#pragma unroll
        for (int b = 0; b < 4; ++b)
#pragma unroll
            for (int c = 0; c < 4; ++c) acc[a][b][c] = 0.f;

    const int grp = lane >> 3, koff = (grp & 1) << 3, nb = (grp >> 1) << 3, nr = lane & 7;

#define MM_LOAD(it, st) do {                                                     \
    const int _k0 = (it) * 32;                                                   \
    __nv_bfloat16* _bb = dsm + (st) * 20480;                                     \
    _Pragma("unroll")                                                            \
    for (int _t = 0; _t < 2; ++_t) {                                             \
        const int _idx = tid + _t * 256;                                         \
        const int _row = _idx >> 2, _c8 = (_idx & 3) << 3;                       \
        const int _so = _row * 40 + _c8;                                         \
        cpa16(sptr(_bb + _so),         Ah + (size_t)(bm + _row) * D_ + _k0 + _c8); \
        cpa16(sptr(_bb + 5120 + _so),  Al + (size_t)(bm + _row) * D_ + _k0 + _c8); \
        cpa16(sptr(_bb + 10240 + _so), Whi + (size_t)(bn + _row) * D_ + _k0 + _c8); \
        cpa16(sptr(_bb + 15360 + _so), Wlo + (size_t)(bn + _row) * D_ + _k0 + _c8); \
    } } while (0)

    MM_LOAD(0, 0); CPA_COMMIT();

    for (int it = 0; it < 32; ++it) {
        if (it + 1 < 32) { MM_LOAD(it + 1, (it + 1) & 1); CPA_COMMIT(); CPA_WAIT(1); }
        else             { CPA_WAIT(0); }
        __syncthreads();

        const __nv_bfloat16* sAh = dsm + (it & 1) * 20480;
        const __nv_bfloat16* sAl = sAh + 5120;
        const __nv_bfloat16* sWh = sAh + 10240;
        const __nv_bfloat16* sWl = sAh + 15360;

#pragma unroll
        for (int kk = 0; kk < 2; ++kk) {
            uint32_t aH[4][4], aL[4][4];
#pragma unroll
            for (int mt = 0; mt < 4; ++mt) {
                const int r = wm + mt * 16 + (lane & 15);
                const int c = kk * 16 + ((lane >> 4) << 3);
                ldsm4(sptr(sAh + r * 40 + c), aH[mt]);
                ldsm4(sptr(sAl + r * 40 + c), aL[mt]);
            }
#pragma unroll
            for (int np = 0; np < 2; ++np) {
                uint32_t bH[4], bL[4];
                const int n = wn + np * 16 + nb + nr;
                const int c = kk * 16 + koff;
                ldsm4(sptr(sWh + n * 40 + c), bH);
                ldsm4(sptr(sWl + n * 40 + c), bL);
#pragma unroll
                for (int mt = 0; mt < 4; ++mt)
#pragma unroll
                    for (int j = 0; j < 2; ++j) {
                        const int nt = np * 2 + j;
                        mma_bf16(acc[mt][nt], aH[mt], bH[2 * j], bH[2 * j + 1]);
                        mma_bf16(acc[mt][nt], aH[mt], bL[2 * j], bL[2 * j + 1]);
                        mma_bf16(acc[mt][nt], aL[mt], bH[2 * j], bH[2 * j + 1]);
                    }
            }
        }
        __syncthreads();
    }
#undef MM_LOAD

#pragma unroll
    for (int mt = 0; mt < 4; ++mt)
#pragma unroll
        for (int nt = 0; nt < 4; ++nt) {
            const float* c = acc[mt][nt];
            const int n = bn + wn + nt * 8 + ((lane & 3) << 1);
#pragma unroll
            for (int hf = 0; hf < 2; ++hf) {
                const int m = bm + wm + mt * 16 + (lane >> 2) + hf * 8;
                const float x0 = c[hf * 2], x1 = c[hf * 2 + 1];
                if (MODE == 0) {
                    *(float2*)(Cf + (size_t)m * D_ + n) = make_float2(x0, x1);
                } else {
                    const int b = m >> 11, s = m & (S_ - 1);
                    const int h = n >> 6, dk = n & (DK_ - 1);
                    const size_t o = (((size_t)(b * H_ + h) * S_ + s) << 6) + dk;
                    __nv_bfloat16 h0 = __float2bfloat16(x0), h1 = __float2bfloat16(x1);
                    __nv_bfloat162 ph; ph.x = h0; ph.y = h1;
                    __nv_bfloat162 pl;
                    pl.x = __float2bfloat16(x0 - __bfloat162float(h0));
                    pl.y = __float2bfloat16(x1 - __bfloat162float(h1));
                    *(__nv_bfloat162*)(Ohi + o) = ph;
                    *(__nv_bfloat162*)(Olo + o) = pl;
                }
            }
        }
}

// ---------------------------------------------------------------------------
// Single-pass attention + fused normalize/zero-fill.
// 256 thr (8 warps), q-tile 256, warp tile 32 q-rows.
// smem: Qh@0 (18432), Ql@18432; stage st @36864+st*18432. 147456 B.
// Epilogue: 1/l stashed in smem, then each CTA scales its own 256 attn rows
// (E -> P) and zero-fills the causal remainder (E data is L2-warm).
// ---------------------------------------------------------------------------
__global__ __launch_bounds__(256, 1) void attn_single(float* __restrict__ attn)
{
    extern __shared__ __nv_bfloat16 sm[];
    __nv_bfloat16* Qh = sm;
    __nv_bfloat16* Ql = sm + 18432;

    const int qt = gridDim.x - 1 - (int)blockIdx.x;   // big tiles first
    const int bh = blockIdx.y;
    const int tid = threadIdx.x, lane = tid & 31, wid = tid >> 5;
    const int q0 = qt * 256;
    const int nkt = 4 * qt + 4;
    const int grp = lane >> 3, koff = (grp & 1) << 3, nb = (grp >> 1) << 3, nr = lane & 7;
    const int wrow = wid * 32;

#pragma unroll
    for (int t = 0; t < 16; ++t) {
        const int idx = tid + t * 256;
        const int buf = idx >> 11;
        const int r = (idx >> 3) & 255, c8 = (idx & 7) << 3;
        const __nv_bfloat16* src = buf ? g_Qlo : g_Qhi;
        __nv_bfloat16* dst = buf ? Ql : Qh;
        *(uint4*)&dst[r * 72 + c8] =
            *(const uint4*)(src + (((size_t)bh * S_ + q0 + r) << 6) + c8);
    }

    const int lrow = lane >> 2;

#define AT_LOADKV(kt, st) do {                                                   \
    __nv_bfloat16* _bb = sm + 36864 + (st) * 18432;                              \
    _Pragma("unroll")                                                            \
    for (int _t = 0; _t < 2; ++_t) {                                             \
        const int _idx = tid + _t * 256;                                         \
        const int _r = _idx >> 3, _c8 = (_idx & 7) << 3;                         \
        const size_t _g = (((size_t)bh * S_ + (kt) * 64 + _r) << 6) + _c8;       \
        const int _so = _r * 72 + _c8;                                           \
        cpa16(sptr(_bb + _so),         g_Khi + _g);                              \
        cpa16(sptr(_bb + 4608 + _so),  g_Klo + _g);                              \
        cpa16(sptr(_bb + 9216 + _so),  g_Vhi + _g);                              \
        cpa16(sptr(_bb + 13824 + _so), g_Vlo + _g);                              \
    } } while (0)

    float accO[2][8][4];
#pragma unroll
    for (int a = 0; a < 2; ++a)
#pragma unroll
        for (int b = 0; b < 8; ++b)
#pragma unroll
            for (int c = 0; c < 4; ++c) accO[a][b][c] = 0.f;
    float lsum[2][2] = {{0.f, 0.f}, {0.f, 0.f}};

    AT_LOADKV(0, 0); CPA_COMMIT();
    for (int kt = 0; kt < nkt; ++kt) {
        if (kt + 1 < nkt) { AT_LOADKV(kt + 1, (kt + 1) & 1); CPA_COMMIT(); CPA_WAIT(1); }
        else              { CPA_WAIT(0); }
        __syncthreads();

        const __nv_bfloat16* Kh = sm + 36864 + (kt & 1) * 18432;
        const __nv_bfloat16* Kl = Kh + 4608;
        const __nv_bfloat16* Vh = Kh + 9216;
        const __nv_bfloat16* Vl = Kh + 13824;

        float acc[2][8][4];
#pragma unroll
        for (int a = 0; a < 2; ++a)
#pragma unroll
            for (int b = 0; b < 8; ++b)
#pragma unroll
                for (int c = 0; c < 4; ++c) acc[a][b][c] = 0.f;

#pragma unroll
        for (int kk = 0; kk < 4; ++kk) {
            uint32_t aH[2][4], aL[2][4];
#pragma unroll
            for (int mt = 0; mt < 2; ++mt) {
                const int r = wrow + mt * 16 + (lane & 15);
                const int c = kk * 16 + ((lane >> 4) << 3);
                ldsm4(sptr(Qh + r * 72 + c), aH[mt]);
                ldsm4(sptr(Ql + r * 72 + c), aL[mt]);
            }
#pragma unroll
            for (int np = 0; np < 4; ++np) {
                uint32_t bH[4], bL[4];
                const int n = np * 16 + nb + nr;
                const int cc = kk * 16 + koff;
                ldsm4(sptr(Kh + n * 72 + cc), bH);
                ldsm4(sptr(Kl + n * 72 + cc), bL);
#pragma unroll
                for (int mt = 0; mt < 2; ++mt)
#pragma unroll
                    for (int j = 0; j < 2; ++j) {
                        const int nt = np * 2 + j;
                        mma_bf16(acc[mt][nt], aH[mt], bH[2 * j], bH[2 * j + 1]);
                        mma_bf16(acc[mt][nt], aH[mt], bL[2 * j], bL[2 * j + 1]);
                        mma_bf16(acc[mt][nt], aL[mt], bH[2 * j], bH[2 * j + 1]);
                    }
            }
        }

#pragma unroll
        for (int t = 0; t < 4; ++t) {
            uint32_t pH[2][4], pL[2][4];
#pragma unroll
            for (int mt = 0; mt < 2; ++mt) {
                const bool need_mask = (kt * 64 + 63) > (q0 + wrow + mt * 16);
#pragma unroll
                for (int g = 0; g < 2; ++g) {
                    const int nt = 2 * t + g;
                    const int kc = kt * 64 + nt * 8 + ((lane & 3) << 1);
#pragma unroll
                    for (int hf = 0; hf < 2; ++hf) {
                        const int qr = q0 + wrow + mt * 16 + lrow + hf * 8;
                        float x0 = acc[mt][nt][hf * 2] * 0.125f;
                        float x1 = acc[mt][nt][hf * 2 + 1] * 0.125f;
                        if (need_mask) {
                            if (kc > qr)     x0 = -1e30f;
                            if (kc + 1 > qr) x1 = -1e30f;
                        }
                        const float e0 = __expf(x0);
                        const float e1 = __expf(x1);
                        lsum[mt][hf] += e0 + e1;
                        float* dst = attn + ((size_t)bh * S_ + qr) * S_ + kc;
                        *(float2*)dst = make_float2(e0, e1);
                        const uint32_t hpk = pack_bf16(e0, e1);
                        __nv_bfloat162 hb = *(__nv_bfloat162*)&hpk;
                        pH[mt][g * 2 + hf] = hpk;
                        pL[mt][g * 2 + hf] = pack_bf16(e0 - __bfloat162float(hb.x),
                                                       e1 - __bfloat162float(hb.y));
                    }
                }
            }
#pragma unroll
            for (int np = 0; np < 4; ++np) {
                uint32_t bH[4], bL[4];
                const int kr = t * 16 + koff + nr;
                const int nc = np * 16 + nb;
                ldsm4t(sptr(Vh + kr * 72 + nc), bH);
                ldsm4t(sptr(Vl + kr * 72 + nc), bL);
#pragma unroll
                for (int mt = 0; mt < 2; ++mt)
#pragma unroll
                    for (int j = 0; j < 2; ++j) {
                        const int nt = np * 2 + j;
                        mma_bf16(accO[mt][nt], pH[mt], bH[2 * j], bH[2 * j + 1]);
                        mma_bf16(accO[mt][nt], pH[mt], bL[2 * j], bL[2 * j + 1]);
                        mma_bf16(accO[mt][nt], pL[mt], bH[2 * j], bH[2 * j + 1]);
                    }
            }
        }
        __syncthreads();
    }
#undef AT_LOADKV

    // merge l across the 4 lanes sharing each row
    float il[2][2];
#pragma unroll
    for (int mt = 0; mt < 2; ++mt)
#pragma unroll
        for (int hf = 0; hf < 2; ++hf) {
            float l = lsum[mt][hf];
#pragma unroll
            for (int off = 1; off <= 2; off <<= 1)
                l += __shfl_xor_sync(0xffffffffu, l, off);
            il[mt][hf] = 1.f / l;
        }

    // stash 1/l per tile-row in (now free) stage smem
    float* sil = (float*)(sm + 36864);
    if ((lane & 3) == 0) {
#pragma unroll
        for (int mt = 0; mt < 2; ++mt)
#pragma unroll
            for (int hf = 0; hf < 2; ++hf)
                sil[wrow + mt * 16 + lrow + hf * 8] = il[mt][hf];
    }

    // ---- write O = accO / l as bf16 hi/lo to g_Chi/g_Clo [B,S,D] ----
    const int b = bh >> 4, h = bh & (H_ - 1);
#pragma unroll
    for (int mt = 0; mt < 2; ++mt)
#pragma unroll
        for (int nt = 0; nt < 8; ++nt) {
            const int d = h * DK_ + nt * 8 + ((lane & 3) << 1);
#pragma unroll
            for (int hf = 0; hf < 2; ++hf) {
                const int s = q0 + wrow + mt * 16 + lrow + hf * 8;
                const float ii = il[mt][hf];
                const float x0 = accO[mt][nt][hf * 2] * ii;
                const float x1 = accO[mt][nt][hf * 2 + 1] * ii;
                const size_t o = ((size_t)b * S_ + s) * D_ + d;
                __nv_bfloat162 phh, pll;
                phh.x = __float2bfloat16(x0); phh.y = __float2bfloat16(x1);
                pll.x = __float2bfloat16(x0 - __bfloat162float(phh.x));
                pll.y = __float2bfloat16(x1 - __bfloat162float(phh.y));
                *(__nv_bfloat162*)(g_Chi + o) = phh;
                *(__nv_bfloat162*)(g_Clo + o) = pll;
            }
        }

    __syncthreads();

    // ---- fused normalize + zero-fill of this CTA's 256 attn rows ----
    const int nvalid4 = (q0 + 256) >> 2;             // valid float4 columns
    for (int r = wid; r < 256; r += 8) {
        const float s = sil[r];
        float* p = attn + ((size_t)bh * S_ + q0 + r) * S_;
        for (int i = lane; i < S_ / 4; i += 32) {
            float4 v;
            if (i < nvalid4) {
                v = ((const float4*)p)[i];
                v.x *= s; v.y *= s; v.z *= s; v.w *= s;
            } else {
                v = make_float4(0.f, 0.f, 0.f, 0.f);
            }
            ((float4*)p)[i] = v;
        }
    }
}

// ---------------------------------------------------------------------------
// Launch (ncu -s 5 -c 1 lands on the merged QKV GEMM)
// ---------------------------------------------------------------------------
extern "C" void kernel_launch(void* const* d_in, const int* in_sizes, int n_in,
                              void* d_out, int out_size)
{
    const float* q = (const float*)d_in[0];
    const float* k = (const float*)d_in[1];
    const float* v = (const float*)d_in[2];
    const float* W[4] = { (const float*)d_in[4], (const float*)d_in[5],
                          (const float*)d_in[6], (const float*)d_in[7] };

    float* out  = (float*)d_out;
    float* attn = out + (size_t)B_ * S_ * D_;

    __nv_bfloat16 *qhi, *qlo, *khi, *klo, *vhi, *vlo, *whi, *wlo;
    __nv_bfloat16 *Qhi, *Qlo, *Khi, *Klo, *Vhi, *Vlo, *Chi, *Clo;
    cudaGetSymbolAddress((void**)&qhi, g_qhi); cudaGetSymbolAddress((void**)&qlo, g_qlo);
    cudaGetSymbolAddress((void**)&khi, g_khi); cudaGetSymbolAddress((void**)&klo, g_klo);
    cudaGetSymbolAddress((void**)&vhi, g_vhi); cudaGetSymbolAddress((void**)&vlo, g_vlo);
    cudaGetSymbolAddress((void**)&whi, g_whi); cudaGetSymbolAddress((void**)&wlo, g_wlo);
    cudaGetSymbolAddress((void**)&Qhi, g_Qhi); cudaGetSymbolAddress((void**)&Qlo, g_Qlo);
    cudaGetSymbolAddress((void**)&Khi, g_Khi); cudaGetSymbolAddress((void**)&Klo, g_Klo);
    cudaGetSymbolAddress((void**)&Vhi, g_Vhi); cudaGetSymbolAddress((void**)&Vlo, g_Vlo);
    cudaGetSymbolAddress((void**)&Chi, g_Chi); cudaGetSymbolAddress((void**)&Clo, g_Clo);

    static bool attr_set = false;
    if (!attr_set) {
        cudaFuncSetAttribute(mm_tc<0>, cudaFuncAttributeMaxDynamicSharedMemorySize, 81920);
        cudaFuncSetAttribute(mm_tc<1>, cudaFuncAttributeMaxDynamicSharedMemorySize, 81920);
        cudaFuncSetAttribute(attn_single, cudaFuncAttributeMaxDynamicSharedMemorySize, 147456);
        attr_set = true;
    }

    const int n4x = MM_ * D_ / 4;
    const int n4w = D_ * D_ / 4;

    // launches 0..2: activation splits
    split_kernel<<<(n4x + 255) / 256, 256>>>(q, qhi, qlo, n4x);
    split_kernel<<<(n4x + 255) / 256, 256>>>(k, khi, klo, n4x);
    split_kernel<<<(n4x + 255) / 256, 256>>>(v, vhi, vlo, n4x);
    // launches 3..4: weight splits (2 weights per launch)
    dim3 gSw((n4w + 255) / 256, 2);
    split_wts2<<<gSw, 256>>>(W[0], W[1], whi, wlo, n4w);
    split_wts2<<<gSw, 256>>>(W[2], W[3], whi + 2 * (size_t)D_ * D_,
                             wlo + 2 * (size_t)D_ * D_, n4w);

    // launch 5: merged QKV projections (profiled)
    dim3 gQKV(24, MM_ / 128);       // (24, 64)
    mm_tc<1><<<gQKV, 256, 81920>>>(qhi, qlo, khi, klo, vhi, vlo, whi, wlo,
                                   nullptr, Qhi, Qlo, Khi, Klo, Vhi, Vlo);

    // launch 6: fused attention (incl. normalize + zero-fill)
    dim3 gA(S_ / 256, B_ * H_);     // (8, 64)
    attn_single<<<gA, 256, 147456>>>(attn);

    // launch 7: output projection
    dim3 gO(8, MM_ / 128);          // (8, 64)
    mm_tc<0><<<gO, 256, 81920>>>(Chi, Clo, nullptr, nullptr, nullptr, nullptr,
                                 whi + 3 * (size_t)D_ * D_, wlo + 3 * (size_t)D_ * D_,
                                 out, nullptr, nullptr, nullptr, nullptr, nullptr, nullptr);
}

// round 10
// speedup vs baseline: 2.8191x; 1.0356x over previous
#include <cuda_runtime.h>
#include <cuda_bf16.h>
#include <cstdint>

#define B_  4
#define S_  2048
#define D_  1024
#define H_  16
#define DK_ 64
#define MM_ (B_ * S_)          // 8192

// ---------------------------------------------------------------------------
// Scratch (device globals)
// ---------------------------------------------------------------------------
__device__ __nv_bfloat16 g_qhi[MM_ * D_], g_qlo[MM_ * D_];
__device__ __nv_bfloat16 g_khi[MM_ * D_], g_klo[MM_ * D_];
__device__ __nv_bfloat16 g_vhi[MM_ * D_], g_vlo[MM_ * D_];
__device__ __nv_bfloat16 g_whi[4][D_ * D_], g_wlo[4][D_ * D_];
__device__ __nv_bfloat16 g_Qhi[MM_ * D_], g_Qlo[MM_ * D_];   // [B,H,S,DK]
__device__ __nv_bfloat16 g_Khi[MM_ * D_], g_Klo[MM_ * D_];
__device__ __nv_bfloat16 g_Vhi[MM_ * D_], g_Vlo[MM_ * D_];
__device__ __nv_bfloat16 g_Chi[MM_ * D_], g_Clo[MM_ * D_];   // [B,S,D]
__device__ float g_linv[B_ * H_ * S_];                        // 1/rowsum

// ---------------------------------------------------------------------------
// PTX helpers
// ---------------------------------------------------------------------------
__device__ __forceinline__ void ldsm4(uint32_t addr, uint32_t* r) {
    asm volatile("ldmatrix.sync.aligned.m8n8.x4.shared.b16 {%0,%1,%2,%3}, [%4];"
        : "=r"(r[0]), "=r"(r[1]), "=r"(r[2]), "=r"(r[3]) : "r"(addr));
}
__device__ __forceinline__ void ldsm4t(uint32_t addr, uint32_t* r) {
    asm volatile("ldmatrix.sync.aligned.m8n8.x4.trans.shared.b16 {%0,%1,%2,%3}, [%4];"
        : "=r"(r[0]), "=r"(r[1]), "=r"(r[2]), "=r"(r[3]) : "r"(addr));
}
__device__ __forceinline__ void mma_bf16(float* c, const uint32_t* a, uint32_t b0, uint32_t b1) {
    asm volatile("mma.sync.aligned.m16n8k16.row.col.f32.bf16.bf16.f32 "
        "{%0,%1,%2,%3}, {%4,%5,%6,%7}, {%8,%9}, {%0,%1,%2,%3};"
        : "+f"(c[0]), "+f"(c[1]), "+f"(c[2]), "+f"(c[3])
        : "r"(a[0]), "r"(a[1]), "r"(a[2]), "r"(a[3]), "r"(b0), "r"(b1));
}
__device__ __forceinline__ uint32_t sptr(const void* p) {
    return (uint32_t)__cvta_generic_to_shared(p);
}
__device__ __forceinline__ void cpa16(uint32_t s, const void* g) {
    asm volatile("cp.async.cg.shared.global [%0], [%1], 16;" :: "r"(s), "l"(g));
}
#define CPA_COMMIT() asm volatile("cp.async.commit_group;" ::: "memory")
#define CPA_WAIT(n)  asm volatile("cp.async.wait_group %0;" :: "n"(n) : "memory")
__device__ __forceinline__ uint32_t pack_bf16(float x, float y) {
    __nv_bfloat162 t; t.x = __float2bfloat16(x); t.y = __float2bfloat16(y);
    return *(uint32_t*)&t;
}

// ---------------------------------------------------------------------------
// Split fp32 -> (hi, lo) bf16
// ---------------------------------------------------------------------------
__device__ __forceinline__ void split4(const float* __restrict__ x,
    __nv_bfloat16* __restrict__ hi, __nv_bfloat16* __restrict__ lo, int i)
{
    float4 v = ((const float4*)x)[i];
    __nv_bfloat16 h0 = __float2bfloat16(v.x), h1 = __float2bfloat16(v.y);
    __nv_bfloat16 h2 = __float2bfloat16(v.z), h3 = __float2bfloat16(v.w);
    __nv_bfloat162 ph0; ph0.x = h0; ph0.y = h1;
    __nv_bfloat162 ph1; ph1.x = h2; ph1.y = h3;
    __nv_bfloat162 pl0; pl0.x = __float2bfloat16(v.x - __bfloat162float(h0));
    pl0.y = __float2bfloat16(v.y - __bfloat162float(h1));
    __nv_bfloat162 pl1; pl1.x = __float2bfloat16(v.z - __bfloat162float(h2));
    pl1.y = __float2bfloat16(v.w - __bfloat162float(h3));
    ((__nv_bfloat162*)hi)[2 * i]     = ph0;
    ((__nv_bfloat162*)hi)[2 * i + 1] = ph1;
    ((__nv_bfloat162*)lo)[2 * i]     = pl0;
    ((__nv_bfloat162*)lo)[2 * i + 1] = pl1;
}

__global__ __launch_bounds__(256) void split_kernel(
    const float* __restrict__ x, __nv_bfloat16* __restrict__ hi,
    __nv_bfloat16* __restrict__ lo, int n4)
{
    int i = blockIdx.x * blockDim.x + threadIdx.x;
    if (i < n4) split4(x, hi, lo, i);
}

__global__ __launch_bounds__(256) void split_wts2(
    const float* wa, const float* wb,
    __nv_bfloat16* hi, __nv_bfloat16* lo, int n4)
{
    int i = blockIdx.x * blockDim.x + threadIdx.x;
    if (i >= n4) return;
    const int z = blockIdx.y;
    split4(z ? wb : wa, hi + (size_t)z * D_ * D_, lo + (size_t)z * D_ * D_, i);
}

// ---------------------------------------------------------------------------
// bf16x3 GEMM, cp.async 2-stage pipeline, 2 CTAs/SM.
// 128x128 tile, BK=32, 256 thr (8 warps, warp tile 64x32), regs capped 128.
// ---------------------------------------------------------------------------
template <int MODE>
__global__ __launch_bounds__(256, 2) void mm_tc(
    const __nv_bfloat16* __restrict__ A0h, const __nv_bfloat16* __restrict__ A0l,
    const __nv_bfloat16* __restrict__ A1h, const __nv_bfloat16* __restrict__ A1l,
    const __nv_bfloat16* __restrict__ A2h, const __nv_bfloat16* __restrict__ A2l,
    const __nv_bfloat16* __restrict__ Wbh, const __nv_bfloat16* __restrict__ Wbl,
    float* __restrict__ Cf,
    __nv_bfloat16* __restrict__ O0h, __nv_bfloat16* __restrict__ O0l,
    __nv_bfloat16* __restrict__ O1h, __nv_bfloat16* __restrict__ O1l,
    __nv_bfloat16* __restrict__ O2h, __nv_bfloat16* __restrict__ O2l)
{
    extern __shared__ __nv_bfloat16 dsm[];

    const int tid = threadIdx.x, lane = tid & 31, wid = tid >> 5;
    const int wsel = (MODE == 1) ? (blockIdx.x >> 3) : 0;
    const int bn = (MODE == 1) ? ((blockIdx.x & 7) * 128) : (blockIdx.x * 128);
    const int bm = blockIdx.y * 128;
    const int wm = (wid >> 2) * 64, wn = (wid & 3) * 32;

    const __nv_bfloat16* Ah = (MODE == 1) ? (wsel == 0 ? A0h : wsel == 1 ? A1h : A2h) : A0h;
    const __nv_bfloat16* Al = (MODE == 1) ? (wsel == 0 ? A0l : wsel == 1 ? A1l : A2l) : A0l;
    const __nv_bfloat16* Whi = Wbh + (size_t)wsel * D_ * D_;
    const __nv_bfloat16* Wlo = Wbl + (size_t)wsel * D_ * D_;
    __nv_bfloat16* Ohi = (wsel == 0) ? O0h : (wsel == 1) ? O1h : O2h;
    __nv_bfloat16* Olo = (wsel == 0) ? O0l : (wsel == 1) ? O1l : O2l;

    float acc[4][4][4];
#pragma unroll
    for (int a = 0; a < 4; ++a)
#pragma unroll
        for (int b = 0; b < 4; ++b)
#pragma unroll
            for (int c = 0; c < 4; ++c) acc[a][b][c] = 0.f;

    const int grp = lane >> 3, koff = (grp & 1) << 3, nb = (grp >> 1) << 3, nr = lane & 7;

#define MM_LOAD(it, st) do {                                                     \
    const int _k0 = (it) * 32;                                                   \
    __nv_bfloat16* _bb = dsm + (st) * 20480;                                     \
    _Pragma("unroll")                                                            \
    for (int _t = 0; _t < 2; ++_t) {                                             \
        const int _idx = tid + _t * 256;                                         \
        const int _row = _idx >> 2, _c8 = (_idx & 3) << 3;                       \
        const int _so = _row * 40 + _c8;                                         \
        cpa16(sptr(_bb + _so),         Ah + (size_t)(bm + _row) * D_ + _k0 + _c8); \
        cpa16(sptr(_bb + 5120 + _so),  Al + (size_t)(bm + _row) * D_ + _k0 + _c8); \
        cpa16(sptr(_bb + 10240 + _so), Whi + (size_t)(bn + _row) * D_ + _k0 + _c8); \
        cpa16(sptr(_bb + 15360 + _so), Wlo + (size_t)(bn + _row) * D_ + _k0 + _c8); \
    } } while (0)

    MM_LOAD(0, 0); CPA_COMMIT();

    for (int it = 0; it < 32; ++it) {
        if (it + 1 < 32) { MM_LOAD(it + 1, (it + 1) & 1); CPA_COMMIT(); CPA_WAIT(1); }
        else             { CPA_WAIT(0); }
        __syncthreads();

        const __nv_bfloat16* sAh = dsm + (it & 1) * 20480;
        const __nv_bfloat16* sAl = sAh + 5120;
        const __nv_bfloat16* sWh = sAh + 10240;
        const __nv_bfloat16* sWl = sAh + 15360;

#pragma unroll
        for (int kk = 0; kk < 2; ++kk) {
            uint32_t aH[4][4], aL[4][4];
#pragma unroll
            for (int mt = 0; mt < 4; ++mt) {
                const int r = wm + mt * 16 + (lane & 15);
                const int c = kk * 16 + ((lane >> 4) << 3);
                ldsm4(sptr(sAh + r * 40 + c), aH[mt]);
                ldsm4(sptr(sAl + r * 40 + c), aL[mt]);
            }
#pragma unroll
            for (int np = 0; np < 2; ++np) {
                uint32_t bH[4], bL[4];
                const int n = wn + np * 16 + nb + nr;
                const int c = kk * 16 + koff;
                ldsm4(sptr(sWh + n * 40 + c), bH);
                ldsm4(sptr(sWl + n * 40 + c), bL);
#pragma unroll
                for (int mt = 0; mt < 4; ++mt)
#pragma unroll
                    for (int j = 0; j < 2; ++j) {
                        const int nt = np * 2 + j;
                        mma_bf16(acc[mt][nt], aH[mt], bH[2 * j], bH[2 * j + 1]);
                        mma_bf16(acc[mt][nt], aH[mt], bL[2 * j], bL[2 * j + 1]);
                        mma_bf16(acc[mt][nt], aL[mt], bH[2 * j], bH[2 * j + 1]);
                    }
            }
        }
        __syncthreads();
    }
#undef MM_LOAD

#pragma unroll
    for (int mt = 0; mt < 4; ++mt)
#pragma unroll
        for (int nt = 0; nt < 4; ++nt) {
            const float* c = acc[mt][nt];
            const int n = bn + wn + nt * 8 + ((lane & 3) << 1);
#pragma unroll
            for (int hf = 0; hf < 2; ++hf) {
                const int m = bm + wm + mt * 16 + (lane >> 2) + hf * 8;
                const float x0 = c[hf * 2], x1 = c[hf * 2 + 1];
                if (MODE == 0) {
                    *(float2*)(Cf + (size_t)m * D_ + n) = make_float2(x0, x1);
                } else {
                    const int b = m >> 11, s = m & (S_ - 1);
                    const int h = n >> 6, dk = n & (DK_ - 1);
                    const size_t o = (((size_t)(b * H_ + h) * S_ + s) << 6) + dk;
                    __nv_bfloat16 h0 = __float2bfloat16(x0), h1 = __float2bfloat16(x1);
                    __nv_bfloat162 ph; ph.x = h0; ph.y = h1;
                    __nv_bfloat162 pl;
                    pl.x = __float2bfloat16(x0 - __bfloat162float(h0));
                    pl.y = __float2bfloat16(x1 - __bfloat162float(h1));
                    *(__nv_bfloat162*)(Ohi + o) = ph;
                    *(__nv_bfloat162*)(Olo + o) = pl;
                }
            }
        }
}

// ---------------------------------------------------------------------------
// Single-pass attention core: writes unnormalized E to attn, 1/l to g_linv,
// normalized O (bf16 hi/lo) to g_Chi/g_Clo. Normalize/zero-fill of attn is
// deferred to scale_zero (overlapped with the output projection).
// ---------------------------------------------------------------------------
__global__ __launch_bounds__(256, 1) void attn_single(float* __restrict__ attn)
{
    extern __shared__ __nv_bfloat16 sm[];
    __nv_bfloat16* Qh = sm;
    __nv_bfloat16* Ql = sm + 18432;

    const int qt = gridDim.x - 1 - (int)blockIdx.x;   // big tiles first
    const int bh = blockIdx.y;
    const int tid = threadIdx.x, lane = tid & 31, wid = tid >> 5;
    const int q0 = qt * 256;
    const int nkt = 4 * qt + 4;
    const int grp = lane >> 3, koff = (grp & 1) << 3, nb = (grp >> 1) << 3, nr = lane & 7;
    const int wrow = wid * 32;

#pragma unroll
    for (int t = 0; t < 16; ++t) {
        const int idx = tid + t * 256;
        const int buf = idx >> 11;
        const int r = (idx >> 3) & 255, c8 = (idx & 7) << 3;
        const __nv_bfloat16* src = buf ? g_Qlo : g_Qhi;
        __nv_bfloat16* dst = buf ? Ql : Qh;
        *(uint4*)&dst[r * 72 + c8] =
            *(const uint4*)(src + (((size_t)bh * S_ + q0 + r) << 6) + c8);
    }

    const int lrow = lane >> 2;

#define AT_LOADKV(kt, st) do {                                                   \
    __nv_bfloat16* _bb = sm + 36864 + (st) * 18432;                              \
    _Pragma("unroll")                                                            \
    for (int _t = 0; _t < 2; ++_t) {                                             \
        const int _idx = tid + _t * 256;                                         \
        const int _r = _idx >> 3, _c8 = (_idx & 7) << 3;                         \
        const size_t _g = (((size_t)bh * S_ + (kt) * 64 + _r) << 6) + _c8;       \
        const int _so = _r * 72 + _c8;                                           \
        cpa16(sptr(_bb + _so),         g_Khi + _g);                              \
        cpa16(sptr(_bb + 4608 + _so),  g_Klo + _g);                              \
        cpa16(sptr(_bb + 9216 + _so),  g_Vhi + _g);                              \
        cpa16(sptr(_bb + 13824 + _so), g_Vlo + _g);                              \
    } } while (0)

    float accO[2][8][4];
#pragma unroll
    for (int a = 0; a < 2; ++a)
#pragma unroll
        for (int b = 0; b < 8; ++b)
#pragma unroll
            for (int c = 0; c < 4; ++c) accO[a][b][c] = 0.f;
    float lsum[2][2] = {{0.f, 0.f}, {0.f, 0.f}};

    AT_LOADKV(0, 0); CPA_COMMIT();
    for (int kt = 0; kt < nkt; ++kt) {
        if (kt + 1 < nkt) { AT_LOADKV(kt + 1, (kt + 1) & 1); CPA_COMMIT(); CPA_WAIT(1); }
        else              { CPA_WAIT(0); }
        __syncthreads();

        const __nv_bfloat16* Kh = sm + 36864 + (kt & 1) * 18432;
        const __nv_bfloat16* Kl = Kh + 4608;
        const __nv_bfloat16* Vh = Kh + 9216;
        const __nv_bfloat16* Vl = Kh + 13824;

        float acc[2][8][4];
#pragma unroll
        for (int a = 0; a < 2; ++a)
#pragma unroll
            for (int b = 0; b < 8; ++b)
#pragma unroll
                for (int c = 0; c < 4; ++c) acc[a][b][c] = 0.f;

#pragma unroll
        for (int kk = 0; kk < 4; ++kk) {
            uint32_t aH[2][4], aL[2][4];
#pragma unroll
            for (int mt = 0; mt < 2; ++mt) {
                const int r = wrow + mt * 16 + (lane & 15);
                const int c = kk * 16 + ((lane >> 4) << 3);
                ldsm4(sptr(Qh + r * 72 + c), aH[mt]);
                ldsm4(sptr(Ql + r * 72 + c), aL[mt]);
            }
#pragma unroll
            for (int np = 0; np < 4; ++np) {
                uint32_t bH[4], bL[4];
                const int n = np * 16 + nb + nr;
                const int cc = kk * 16 + koff;
                ldsm4(sptr(Kh + n * 72 + cc), bH);
                ldsm4(sptr(Kl + n * 72 + cc), bL);
#pragma unroll
                for (int mt = 0; mt < 2; ++mt)
#pragma unroll
                    for (int j = 0; j < 2; ++j) {
                        const int nt = np * 2 + j;
                        mma_bf16(acc[mt][nt], aH[mt], bH[2 * j], bH[2 * j + 1]);
                        mma_bf16(acc[mt][nt], aH[mt], bL[2 * j], bL[2 * j + 1]);
                        mma_bf16(acc[mt][nt], aL[mt], bH[2 * j], bH[2 * j + 1]);
                    }
            }
        }

#pragma unroll
        for (int t = 0; t < 4; ++t) {
            uint32_t pH[2][4], pL[2][4];
#pragma unroll
            for (int mt = 0; mt < 2; ++mt) {
                const bool need_mask = (kt * 64 + 63) > (q0 + wrow + mt * 16);
#pragma unroll
                for (int g = 0; g < 2; ++g) {
                    const int nt = 2 * t + g;
                    const int kc = kt * 64 + nt * 8 + ((lane & 3) << 1);
#pragma unroll
                    for (int hf = 0; hf < 2; ++hf) {
                        const int qr = q0 + wrow + mt * 16 + lrow + hf * 8;
                        float x0 = acc[mt][nt][hf * 2] * 0.125f;
                        float x1 = acc[mt][nt][hf * 2 + 1] * 0.125f;
                        if (need_mask) {
                            if (kc > qr)     x0 = -1e30f;
                            if (kc + 1 > qr) x1 = -1e30f;
                        }
                        const float e0 = __expf(x0);
                        const float e1 = __expf(x1);
                        lsum[mt][hf] += e0 + e1;
                        float* dst = attn + ((size_t)bh * S_ + qr) * S_ + kc;
                        *(float2*)dst = make_float2(e0, e1);
                        const uint32_t hpk = pack_bf16(e0, e1);
                        __nv_bfloat162 hb = *(__nv_bfloat162*)&hpk;
                        pH[mt][g * 2 + hf] = hpk;
                        pL[mt][g * 2 + hf] = pack_bf16(e0 - __bfloat162float(hb.x),
                                                       e1 - __bfloat162float(hb.y));
                    }
                }
            }
#pragma unroll
            for (int np = 0; np < 4; ++np) {
                uint32_t bH[4], bL[4];
                const int kr = t * 16 + koff + nr;
                const int nc = np * 16 + nb;
                ldsm4t(sptr(Vh + kr * 72 + nc), bH);
                ldsm4t(sptr(Vl + kr * 72 + nc), bL);
#pragma unroll
                for (int mt = 0; mt < 2; ++mt)
#pragma unroll
                    for (int j = 0; j < 2; ++j) {
                        const int nt = np * 2 + j;
                        mma_bf16(accO[mt][nt], pH[mt], bH[2 * j], bH[2 * j + 1]);
                        mma_bf16(accO[mt][nt], pH[mt], bL[2 * j], bL[2 * j + 1]);
                        mma_bf16(accO[mt][nt], pL[mt], bH[2 * j], bH[2 * j + 1]);
                    }
            }
        }
        __syncthreads();
    }
#undef AT_LOADKV

    // merge l across the 4 lanes sharing each row
    float il[2][2];
#pragma unroll
    for (int mt = 0; mt < 2; ++mt)
#pragma unroll
        for (int hf = 0; hf < 2; ++hf) {
            float l = lsum[mt][hf];
#pragma unroll
            for (int off = 1; off <= 2; off <<= 1)
                l += __shfl_xor_sync(0xffffffffu, l, off);
            il[mt][hf] = 1.f / l;
        }

    if ((lane & 3) == 0) {
#pragma unroll
        for (int mt = 0; mt < 2; ++mt)
#pragma unroll
            for (int hf = 0; hf < 2; ++hf)
                g_linv[(size_t)bh * S_ + q0 + wrow + mt * 16 + lrow + hf * 8] = il[mt][hf];
    }

    // ---- write O = accO / l as bf16 hi/lo to g_Chi/g_Clo [B,S,D] ----
    const int b = bh >> 4, h = bh & (H_ - 1);
#pragma unroll
    for (int mt = 0; mt < 2; ++mt)
#pragma unroll
        for (int nt = 0; nt < 8; ++nt) {
            const int d = h * DK_ + nt * 8 + ((lane & 3) << 1);
#pragma unroll
            for (int hf = 0; hf < 2; ++hf) {
                const int s = q0 + wrow + mt * 16 + lrow + hf * 8;
                const float ii = il[mt][hf];
                const float x0 = accO[mt][nt][hf * 2] * ii;
                const float x1 = accO[mt][nt][hf * 2 + 1] * ii;
                const size_t o = ((size_t)b * S_ + s) * D_ + d;
                __nv_bfloat162 phh, pll;
                phh.x = __float2bfloat16(x0); phh.y = __float2bfloat16(x1);
                pll.x = __float2bfloat16(x0 - __bfloat162float(phh.x));
                pll.y = __float2bfloat16(x1 - __bfloat162float(phh.y));
                *(__nv_bfloat162*)(g_Chi + o) = phh;
                *(__nv_bfloat162*)(g_Clo + o) = pll;
            }
        }
}

// ---------------------------------------------------------------------------
// Normalize + zero-fill: attn[row, c] = (c <= row) ? E*linv : 0.
// Grid (S_, B*H), 256 thr per row (2 float4 iters). Coalesced.
// ---------------------------------------------------------------------------
__global__ __launch_bounds__(256) void scale_zero(float* __restrict__ attn)
{
    const int row = blockIdx.x, bh = blockIdx.y;
    const float s = g_linv[(size_t)bh * S_ + row];
    float* p = attn + ((size_t)bh * S_ + row) * S_;
    const int tid = threadIdx.x;
    const int qw = row >> 2;

#pragma unroll
    for (int t = 0; t < 2; ++t) {
        const int i = tid + t * 256;
        float4 v;
        if (i < qw) {
            v = ((const float4*)p)[i];
            v.x *= s; v.y *= s; v.z *= s; v.w *= s;
        } else if (i == qw) {
            v = ((const float4*)p)[i];
            const int c = i * 4;
            v.x = (c     <= row) ? v.x * s : 0.f;
            v.y = (c + 1 <= row) ? v.y * s : 0.f;
            v.z = (c + 2 <= row) ? v.z * s : 0.f;
            v.w = (c + 3 <= row) ? v.w * s : 0.f;
        } else {
            v = make_float4(0.f, 0.f, 0.f, 0.f);
        }
        ((float4*)p)[i] = v;
    }
}

// ---------------------------------------------------------------------------
// Launch. Fork/join: scale_zero (DRAM-bound) overlaps out-proj GEMM
// (tensor-bound) on a side stream. Stream/events created on first
// (uncaptured) call; event fork/join is graph-capture legal.
// ---------------------------------------------------------------------------
extern "C" void kernel_launch(void* const* d_in, const int* in_sizes, int n_in,
                              void* d_out, int out_size)
{
    const float* q = (const float*)d_in[0];
    const float* k = (const float*)d_in[1];
    const float* v = (const float*)d_in[2];
    const float* W[4] = { (const float*)d_in[4], (const float*)d_in[5],
                          (const float*)d_in[6], (const float*)d_in[7] };

    float* out  = (float*)d_out;
    float* attn = out + (size_t)B_ * S_ * D_;

    __nv_bfloat16 *qhi, *qlo, *khi, *klo, *vhi, *vlo, *whi, *wlo;
    __nv_bfloat16 *Qhi, *Qlo, *Khi, *Klo, *Vhi, *Vlo, *Chi, *Clo;
    cudaGetSymbolAddress((void**)&qhi, g_qhi); cudaGetSymbolAddress((void**)&qlo, g_qlo);
    cudaGetSymbolAddress((void**)&khi, g_khi); cudaGetSymbolAddress((void**)&klo, g_klo);
    cudaGetSymbolAddress((void**)&vhi, g_vhi); cudaGetSymbolAddress((void**)&vlo, g_vlo);
    cudaGetSymbolAddress((void**)&whi, g_whi); cudaGetSymbolAddress((void**)&wlo, g_wlo);
    cudaGetSymbolAddress((void**)&Qhi, g_Qhi); cudaGetSymbolAddress((void**)&Qlo, g_Qlo);
    cudaGetSymbolAddress((void**)&Khi, g_Khi); cudaGetSymbolAddress((void**)&Klo, g_Klo);
    cudaGetSymbolAddress((void**)&Vhi, g_Vhi); cudaGetSymbolAddress((void**)&Vlo, g_Vlo);
    cudaGetSymbolAddress((void**)&Chi, g_Chi); cudaGetSymbolAddress((void**)&Clo, g_Clo);

    static cudaStream_t s_side = nullptr;
    static cudaEvent_t evFork = nullptr, evJoin = nullptr;
    static bool attr_set = false;
    if (!attr_set) {
        cudaFuncSetAttribute(mm_tc<0>, cudaFuncAttributeMaxDynamicSharedMemorySize, 81920);
        cudaFuncSetAttribute(mm_tc<1>, cudaFuncAttributeMaxDynamicSharedMemorySize, 81920);
        cudaFuncSetAttribute(attn_single, cudaFuncAttributeMaxDynamicSharedMemorySize, 147456);
        cudaStreamCreateWithFlags(&s_side, cudaStreamNonBlocking);
        cudaEventCreateWithFlags(&evFork, cudaEventDisableTiming);
        cudaEventCreateWithFlags(&evJoin, cudaEventDisableTiming);
        attr_set = true;
    }

    const int n4x = MM_ * D_ / 4;
    const int n4w = D_ * D_ / 4;

    split_kernel<<<(n4x + 255) / 256, 256>>>(q, qhi, qlo, n4x);
    split_kernel<<<(n4x + 255) / 256, 256>>>(k, khi, klo, n4x);
    split_kernel<<<(n4x + 255) / 256, 256>>>(v, vhi, vlo, n4x);
    dim3 gSw((n4w + 255) / 256, 2);
    split_wts2<<<gSw, 256>>>(W[0], W[1], whi, wlo, n4w);
    split_wts2<<<gSw, 256>>>(W[2], W[3], whi + 2 * (size_t)D_ * D_,
                             wlo + 2 * (size_t)D_ * D_, n4w);

    dim3 gQKV(24, MM_ / 128);       // (24, 64)
    mm_tc<1><<<gQKV, 256, 81920>>>(qhi, qlo, khi, klo, vhi, vlo, whi, wlo,
                                   nullptr, Qhi, Qlo, Khi, Klo, Vhi, Vlo);

    dim3 gA(S_ / 256, B_ * H_);     // (8, 64)
    attn_single<<<gA, 256, 147456>>>(attn);

    // fork: normalize/zero-fill on side stream, out-proj on main stream
    cudaEventRecord(evFork, 0);
    cudaStreamWaitEvent(s_side, evFork, 0);

    dim3 gZ(S_, B_ * H_);
    scale_zero<<<gZ, 256, 0, s_side>>>(attn);

    dim3 gO(8, MM_ / 128);          // (8, 64)
    mm_tc<0><<<gO, 256, 81920>>>(Chi, Clo, nullptr, nullptr, nullptr, nullptr,
                                 whi + 3 * (size_t)D_ * D_, wlo + 3 * (size_t)D_ * D_,
                                 out, nullptr, nullptr, nullptr, nullptr, nullptr, nullptr);

    // join
    cudaEventRecord(evJoin, s_side);
    cudaStreamWaitEvent(0, evJoin, 0);
}

// round 11
// speedup vs baseline: 2.8569x; 1.0134x over previous
#include <cuda_runtime.h>
#include <cuda_bf16.h>
#include <cstdint>

#define B_  4
#define S_  2048
#define D_  1024
#define H_  16
#define DK_ 64
#define MM_ (B_ * S_)          // 8192

// ---------------------------------------------------------------------------
// Scratch (device globals)
// ---------------------------------------------------------------------------
__device__ __nv_bfloat16 g_qhi[MM_ * D_], g_qlo[MM_ * D_];
__device__ __nv_bfloat16 g_khi[MM_ * D_], g_klo[MM_ * D_];
__device__ __nv_bfloat16 g_vhi[MM_ * D_], g_vlo[MM_ * D_];
__device__ __nv_bfloat16 g_whi[4][D_ * D_], g_wlo[4][D_ * D_];
__device__ __nv_bfloat16 g_Qhi[MM_ * D_], g_Qlo[MM_ * D_];   // [B,H,S,DK]
__device__ __nv_bfloat16 g_Khi[MM_ * D_], g_Klo[MM_ * D_];
__device__ __nv_bfloat16 g_Vhi[MM_ * D_], g_Vlo[MM_ * D_];
__device__ __nv_bfloat16 g_Chi[MM_ * D_], g_Clo[MM_ * D_];   // [B,S,D]
__device__ float g_linv[B_ * H_ * S_];                        // 1/rowsum

// ---------------------------------------------------------------------------
// PTX helpers
// ---------------------------------------------------------------------------
__device__ __forceinline__ void ldsm4(uint32_t addr, uint32_t* r) {
    asm volatile("ldmatrix.sync.aligned.m8n8.x4.shared.b16 {%0,%1,%2,%3}, [%4];"
        : "=r"(r[0]), "=r"(r[1]), "=r"(r[2]), "=r"(r[3]) : "r"(addr));
}
__device__ __forceinline__ void ldsm4t(uint32_t addr, uint32_t* r) {
    asm volatile("ldmatrix.sync.aligned.m8n8.x4.trans.shared.b16 {%0,%1,%2,%3}, [%4];"
        : "=r"(r[0]), "=r"(r[1]), "=r"(r[2]), "=r"(r[3]) : "r"(addr));
}
__device__ __forceinline__ void mma_bf16(float* c, const uint32_t* a, uint32_t b0, uint32_t b1) {
    asm volatile("mma.sync.aligned.m16n8k16.row.col.f32.bf16.bf16.f32 "
        "{%0,%1,%2,%3}, {%4,%5,%6,%7}, {%8,%9}, {%0,%1,%2,%3};"
        : "+f"(c[0]), "+f"(c[1]), "+f"(c[2]), "+f"(c[3])
        : "r"(a[0]), "r"(a[1]), "r"(a[2]), "r"(a[3]), "r"(b0), "r"(b1));
}
__device__ __forceinline__ uint32_t sptr(const void* p) {
    return (uint32_t)__cvta_generic_to_shared(p);
}
__device__ __forceinline__ void cpa16(uint32_t s, const void* g) {
    asm volatile("cp.async.cg.shared.global [%0], [%1], 16;" :: "r"(s), "l"(g));
}
#define CPA_COMMIT() asm volatile("cp.async.commit_group;" ::: "memory")
#define CPA_WAIT(n)  asm volatile("cp.async.wait_group %0;" :: "n"(n) : "memory")
__device__ __forceinline__ uint32_t pack_bf16(float x, float y) {
    __nv_bfloat162 t; t.x = __float2bfloat16(x); t.y = __float2bfloat16(y);
    return *(uint32_t*)&t;
}

// ---------------------------------------------------------------------------
// Split fp32 -> (hi, lo) bf16
// ---------------------------------------------------------------------------
__device__ __forceinline__ void split4(const float* __restrict__ x,
    __nv_bfloat16* __restrict__ hi, __nv_bfloat16* __restrict__ lo, int i)
{
    float4 v = ((const float4*)x)[i];
    __nv_bfloat16 h0 = __float2bfloat16(v.x), h1 = __float2bfloat16(v.y);
    __nv_bfloat16 h2 = __float2bfloat16(v.z), h3 = __float2bfloat16(v.w);
    __nv_bfloat162 ph0; ph0.x = h0; ph0.y = h1;
    __nv_bfloat162 ph1; ph1.x = h2; ph1.y = h3;
    __nv_bfloat162 pl0; pl0.x = __float2bfloat16(v.x - __bfloat162float(h0));
    pl0.y = __float2bfloat16(v.y - __bfloat162float(h1));
    __nv_bfloat162 pl1; pl1.x = __float2bfloat16(v.z - __bfloat162float(h2));
    pl1.y = __float2bfloat16(v.w - __bfloat162float(h3));
    ((__nv_bfloat162*)hi)[2 * i]     = ph0;
    ((__nv_bfloat162*)hi)[2 * i + 1] = ph1;
    ((__nv_bfloat162*)lo)[2 * i]     = pl0;
    ((__nv_bfloat162*)lo)[2 * i + 1] = pl1;
}

__global__ __launch_bounds__(256) void split_acts(
    const float* q, const float* k, const float* v,
    __nv_bfloat16* qh, __nv_bfloat16* ql, __nv_bfloat16* kh, __nv_bfloat16* kl,
    __nv_bfloat16* vh, __nv_bfloat16* vl, int n4)
{
    int i = blockIdx.x * blockDim.x + threadIdx.x;
    if (i >= n4) return;
    const int z = blockIdx.y;
    const float* x = (z == 0) ? q : (z == 1) ? k : v;
    __nv_bfloat16* hi = (z == 0) ? qh : (z == 1) ? kh : vh;
    __nv_bfloat16* lo = (z == 0) ? ql : (z == 1) ? kl : vl;
    split4(x, hi, lo, i);
}

__global__ __launch_bounds__(256) void split_wts4(
    const float* w0, const float* w1, const float* w2, const float* w3,
    __nv_bfloat16* hi, __nv_bfloat16* lo, int n4)
{
    int i = blockIdx.x * blockDim.x + threadIdx.x;
    if (i >= n4) return;
    const int z = blockIdx.y;
    const float* x = (z == 0) ? w0 : (z == 1) ? w1 : (z == 2) ? w2 : w3;
    split4(x, hi + (size_t)z * D_ * D_, lo + (size_t)z * D_ * D_, i);
}

// ---------------------------------------------------------------------------
// bf16x3 GEMM, cp.async 2-stage pipeline, 2 CTAs/SM.
// 128x128 tile, BK=32, 256 thr (8 warps, warp tile 64x32), regs capped 128.
// ---------------------------------------------------------------------------
template <int MODE>
__global__ __launch_bounds__(256, 2) void mm_tc(
    const __nv_bfloat16* __restrict__ A0h, const __nv_bfloat16* __restrict__ A0l,
    const __nv_bfloat16* __restrict__ A1h, const __nv_bfloat16* __restrict__ A1l,
    const __nv_bfloat16* __restrict__ A2h, const __nv_bfloat16* __restrict__ A2l,
    const __nv_bfloat16* __restrict__ Wbh, const __nv_bfloat16* __restrict__ Wbl,
    float* __restrict__ Cf,
    __nv_bfloat16* __restrict__ O0h, __nv_bfloat16* __restrict__ O0l,
    __nv_bfloat16* __restrict__ O1h, __nv_bfloat16* __restrict__ O1l,
    __nv_bfloat16* __restrict__ O2h, __nv_bfloat16* __restrict__ O2l)
{
    extern __shared__ __nv_bfloat16 dsm[];

    const int tid = threadIdx.x, lane = tid & 31, wid = tid >> 5;
    const int wsel = (MODE == 1) ? (blockIdx.x >> 3) : 0;
    const int bn = (MODE == 1) ? ((blockIdx.x & 7) * 128) : (blockIdx.x * 128);
    const int bm = blockIdx.y * 128;
    const int wm = (wid >> 2) * 64, wn = (wid & 3) * 32;

    const __nv_bfloat16* Ah = (MODE == 1) ? (wsel == 0 ? A0h : wsel == 1 ? A1h : A2h) : A0h;
    const __nv_bfloat16* Al = (MODE == 1) ? (wsel == 0 ? A0l : wsel == 1 ? A1l : A2l) : A0l;
    const __nv_bfloat16* Whi = Wbh + (size_t)wsel * D_ * D_;
    const __nv_bfloat16* Wlo = Wbl + (size_t)wsel * D_ * D_;
    __nv_bfloat16* Ohi = (wsel == 0) ? O0h : (wsel == 1) ? O1h : O2h;
    __nv_bfloat16* Olo = (wsel == 0) ? O0l : (wsel == 1) ? O1l : O2l;

    float acc[4][4][4];
#pragma unroll
    for (int a = 0; a < 4; ++a)
#pragma unroll
        for (int b = 0; b < 4; ++b)
#pragma unroll
            for (int c = 0; c < 4; ++c) acc[a][b][c] = 0.f;

    const int grp = lane >> 3, koff = (grp & 1) << 3, nb = (grp >> 1) << 3, nr = lane & 7;

#define MM_LOAD(it, st) do {                                                     \
    const int _k0 = (it) * 32;                                                   \
    __nv_bfloat16* _bb = dsm + (st) * 20480;                                     \
    _Pragma("unroll")                                                            \
    for (int _t = 0; _t < 2; ++_t) {                                             \
        const int _idx = tid + _t * 256;                                         \
        const int _row = _idx >> 2, _c8 = (_idx & 3) << 3;                       \
        const int _so = _row * 40 + _c8;                                         \
        cpa16(sptr(_bb + _so),         Ah + (size_t)(bm + _row) * D_ + _k0 + _c8); \
        cpa16(sptr(_bb + 5120 + _so),  Al + (size_t)(bm + _row) * D_ + _k0 + _c8); \
        cpa16(sptr(_bb + 10240 + _so), Whi + (size_t)(bn + _row) * D_ + _k0 + _c8); \
        cpa16(sptr(_bb + 15360 + _so), Wlo + (size_t)(bn + _row) * D_ + _k0 + _c8); \
    } } while (0)

    MM_LOAD(0, 0); CPA_COMMIT();

    for (int it = 0; it < 32; ++it) {
        if (it + 1 < 32) { MM_LOAD(it + 1, (it + 1) & 1); CPA_COMMIT(); CPA_WAIT(1); }
        else             { CPA_WAIT(0); }
        __syncthreads();

        const __nv_bfloat16* sAh = dsm + (it & 1) * 20480;
        const __nv_bfloat16* sAl = sAh + 5120;
        const __nv_bfloat16* sWh = sAh + 10240;
        const __nv_bfloat16* sWl = sAh + 15360;

#pragma unroll
        for (int kk = 0; kk < 2; ++kk) {
            uint32_t aH[4][4], aL[4][4];
#pragma unroll
            for (int mt = 0; mt < 4; ++mt) {
                const int r = wm + mt * 16 + (lane & 15);
                const int c = kk * 16 + ((lane >> 4) << 3);
                ldsm4(sptr(sAh + r * 40 + c), aH[mt]);
                ldsm4(sptr(sAl + r * 40 + c), aL[mt]);
            }
#pragma unroll
            for (int np = 0; np < 2; ++np) {
                uint32_t bH[4], bL[4];
                const int n = wn + np * 16 + nb + nr;
                const int c = kk * 16 + koff;
                ldsm4(sptr(sWh + n * 40 + c), bH);
                ldsm4(sptr(sWl + n * 40 + c), bL);
#pragma unroll
                for (int mt = 0; mt < 4; ++mt)
#pragma unroll
                    for (int j = 0; j < 2; ++j) {
                        const int nt = np * 2 + j;
                        mma_bf16(acc[mt][nt], aH[mt], bH[2 * j], bH[2 * j + 1]);
                        mma_bf16(acc[mt][nt], aH[mt], bL[2 * j], bL[2 * j + 1]);
                        mma_bf16(acc[mt][nt], aL[mt], bH[2 * j], bH[2 * j + 1]);
                    }
            }
        }
        __syncthreads();
    }
#undef MM_LOAD

#pragma unroll
    for (int mt = 0; mt < 4; ++mt)
#pragma unroll
        for (int nt = 0; nt < 4; ++nt) {
            const float* c = acc[mt][nt];
            const int n = bn + wn + nt * 8 + ((lane & 3) << 1);
#pragma unroll
            for (int hf = 0; hf < 2; ++hf) {
                const int m = bm + wm + mt * 16 + (lane >> 2) + hf * 8;
                const float x0 = c[hf * 2], x1 = c[hf * 2 + 1];
                if (MODE == 0) {
                    *(float2*)(Cf + (size_t)m * D_ + n) = make_float2(x0, x1);
                } else {
                    const int b = m >> 11, s = m & (S_ - 1);
                    const int h = n >> 6, dk = n & (DK_ - 1);
                    const size_t o = (((size_t)(b * H_ + h) * S_ + s) << 6) + dk;
                    __nv_bfloat16 h0 = __float2bfloat16(x0), h1 = __float2bfloat16(x1);
                    __nv_bfloat162 ph; ph.x = h0; ph.y = h1;
                    __nv_bfloat162 pl;
                    pl.x = __float2bfloat16(x0 - __bfloat162float(h0));
                    pl.y = __float2bfloat16(x1 - __bfloat162float(h1));
                    *(__nv_bfloat162*)(Ohi + o) = ph;
                    *(__nv_bfloat162*)(Olo + o) = pl;
                }
            }
        }
}

// ---------------------------------------------------------------------------
// Single-pass attention core (unchanged from R10): E to attn, 1/l to g_linv,
// normalized O (bf16 hi/lo) to g_Chi/g_Clo. Masked in-tile entries are exact 0.
// ---------------------------------------------------------------------------
__global__ __launch_bounds__(256, 1) void attn_single(float* __restrict__ attn)
{
    extern __shared__ __nv_bfloat16 sm[];
    __nv_bfloat16* Qh = sm;
    __nv_bfloat16* Ql = sm + 18432;

    const int qt = gridDim.x - 1 - (int)blockIdx.x;
    const int bh = blockIdx.y;
    const int tid = threadIdx.x, lane = tid & 31, wid = tid >> 5;
    const int q0 = qt * 256;
    const int nkt = 4 * qt + 4;
    const int grp = lane >> 3, koff = (grp & 1) << 3, nb = (grp >> 1) << 3, nr = lane & 7;
    const int wrow = wid * 32;

#pragma unroll
    for (int t = 0; t < 16; ++t) {
        const int idx = tid + t * 256;
        const int buf = idx >> 11;
        const int r = (idx >> 3) & 255, c8 = (idx & 7) << 3;
        const __nv_bfloat16* src = buf ? g_Qlo : g_Qhi;
        __nv_bfloat16* dst = buf ? Ql : Qh;
        *(uint4*)&dst[r * 72 + c8] =
            *(const uint4*)(src + (((size_t)bh * S_ + q0 + r) << 6) + c8);
    }

    const int lrow = lane >> 2;

#define AT_LOADKV(kt, st) do {                                                   \
    __nv_bfloat16* _bb = sm + 36864 + (st) * 18432;                              \
    _Pragma("unroll")                                                            \
    for (int _t = 0; _t < 2; ++_t) {                                             \
        const int _idx = tid + _t * 256;                                         \
        const int _r = _idx >> 3, _c8 = (_idx & 7) << 3;                         \
        const size_t _g = (((size_t)bh * S_ + (kt) * 64 + _r) << 6) + _c8;       \
        const int _so = _r * 72 + _c8;                                           \
        cpa16(sptr(_bb + _so),         g_Khi + _g);                              \
        cpa16(sptr(_bb + 4608 + _so),  g_Klo + _g);                              \
        cpa16(sptr(_bb + 9216 + _so),  g_Vhi + _g);                              \
        cpa16(sptr(_bb + 13824 + _so), g_Vlo + _g);                              \
    } } while (0)

    float accO[2][8][4];
#pragma unroll
    for (int a = 0; a < 2; ++a)
#pragma unroll
        for (int b = 0; b < 8; ++b)
#pragma unroll
            for (int c = 0; c < 4; ++c) accO[a][b][c] = 0.f;
    float lsum[2][2] = {{0.f, 0.f}, {0.f, 0.f}};

    AT_LOADKV(0, 0); CPA_COMMIT();
    for (int kt = 0; kt < nkt; ++kt) {
        if (kt + 1 < nkt) { AT_LOADKV(kt + 1, (kt + 1) & 1); CPA_COMMIT(); CPA_WAIT(1); }
        else              { CPA_WAIT(0); }
        __syncthreads();

        const __nv_bfloat16* Kh = sm + 36864 + (kt & 1) * 18432;
        const __nv_bfloat16* Kl = Kh + 4608;
        const __nv_bfloat16* Vh = Kh + 9216;
        const __nv_bfloat16* Vl = Kh + 13824;

        float acc[2][8][4];
#pragma unroll
        for (int a = 0; a < 2; ++a)
#pragma unroll
            for (int b = 0; b < 8; ++b)
#pragma unroll
                for (int c = 0; c < 4; ++c) acc[a][b][c] = 0.f;

#pragma unroll
        for (int kk = 0; kk < 4; ++kk) {
            uint32_t aH[2][4], aL[2][4];
#pragma unroll
            for (int mt = 0; mt < 2; ++mt) {
                const int r = wrow + mt * 16 + (lane & 15);
                const int c = kk * 16 + ((lane >> 4) << 3);
                ldsm4(sptr(Qh + r * 72 + c), aH[mt]);
                ldsm4(sptr(Ql + r * 72 + c), aL[mt]);
            }
#pragma unroll
            for (int np = 0; np < 4; ++np) {
                uint32_t bH[4], bL[4];
                const int n = np * 16 + nb + nr;
                const int cc = kk * 16 + koff;
                ldsm4(sptr(Kh + n * 72 + cc), bH);
                ldsm4(sptr(Kl + n * 72 + cc), bL);
#pragma unroll
                for (int mt = 0; mt < 2; ++mt)
#pragma unroll
                    for (int j = 0; j < 2; ++j) {
                        const int nt = np * 2 + j;
                        mma_bf16(acc[mt][nt], aH[mt], bH[2 * j], bH[2 * j + 1]);
                        mma_bf16(acc[mt][nt], aH[mt], bL[2 * j], bL[2 * j + 1]);
                        mma_bf16(acc[mt][nt], aL[mt], bH[2 * j], bH[2 * j + 1]);
                    }
            }
        }

#pragma unroll
        for (int t = 0; t < 4; ++t) {
            uint32_t pH[2][4], pL[2][4];
#pragma unroll
            for (int mt = 0; mt < 2; ++mt) {
                const bool need_mask = (kt * 64 + 63) > (q0 + wrow + mt * 16);
#pragma unroll
                for (int g = 0; g < 2; ++g) {
                    const int nt = 2 * t + g;
                    const int kc = kt * 64 + nt * 8 + ((lane & 3) << 1);
#pragma unroll
                    for (int hf = 0; hf < 2; ++hf) {
                        const int qr = q0 + wrow + mt * 16 + lrow + hf * 8;
                        float x0 = acc[mt][nt][hf * 2] * 0.125f;
                        float x1 = acc[mt][nt][hf * 2 + 1] * 0.125f;
                        if (need_mask) {
                            if (kc > qr)     x0 = -1e30f;
                            if (kc + 1 > qr) x1 = -1e30f;
                        }
                        const float e0 = __expf(x0);
                        const float e1 = __expf(x1);
                        lsum[mt][hf] += e0 + e1;
                        float* dst = attn + ((size_t)bh * S_ + qr) * S_ + kc;
                        *(float2*)dst = make_float2(e0, e1);
                        const uint32_t hpk = pack_bf16(e0, e1);
                        __nv_bfloat162 hb = *(__nv_bfloat162*)&hpk;
                        pH[mt][g * 2 + hf] = hpk;
                        pL[mt][g * 2 + hf] = pack_bf16(e0 - __bfloat162float(hb.x),
                                                       e1 - __bfloat162float(hb.y));
                    }
                }
            }
#pragma unroll
            for (int np = 0; np < 4; ++np) {
                uint32_t bH[4], bL[4];
                const int kr = t * 16 + koff + nr;
                const int nc = np * 16 + nb;
                ldsm4t(sptr(Vh + kr * 72 + nc), bH);
                ldsm4t(sptr(Vl + kr * 72 + nc), bL);
#pragma unroll
                for (int mt = 0; mt < 2; ++mt)
#pragma unroll
                    for (int j = 0; j < 2; ++j) {
                        const int nt = np * 2 + j;
                        mma_bf16(accO[mt][nt], pH[mt], bH[2 * j], bH[2 * j + 1]);
                        mma_bf16(accO[mt][nt], pH[mt], bL[2 * j], bL[2 * j + 1]);
                        mma_bf16(accO[mt][nt], pL[mt], bH[2 * j], bH[2 * j + 1]);
                    }
            }
        }
        __syncthreads();
    }
#undef AT_LOADKV

    float il[2][2];
#pragma unroll
    for (int mt = 0; mt < 2; ++mt)
#pragma unroll
        for (int hf = 0; hf < 2; ++hf) {
            float l = lsum[mt][hf];
#pragma unroll
            for (int off = 1; off <= 2; off <<= 1)
                l += __shfl_xor_sync(0xffffffffu, l, off);
            il[mt][hf] = 1.f / l;
        }

    if ((lane & 3) == 0) {
#pragma unroll
        for (int mt = 0; mt < 2; ++mt)
#pragma unroll
            for (int hf = 0; hf < 2; ++hf)
                g_linv[(size_t)bh * S_ + q0 + wrow + mt * 16 + lrow + hf * 8] = il[mt][hf];
    }

    const int b = bh >> 4, h = bh & (H_ - 1);
#pragma unroll
    for (int mt = 0; mt < 2; ++mt)
#pragma unroll
        for (int nt = 0; nt < 8; ++nt) {
            const int d = h * DK_ + nt * 8 + ((lane & 3) << 1);
#pragma unroll
            for (int hf = 0; hf < 2; ++hf) {
                const int s = q0 + wrow + mt * 16 + lrow + hf * 8;
                const float ii = il[mt][hf];
                const float x0 = accO[mt][nt][hf * 2] * ii;
                const float x1 = accO[mt][nt][hf * 2 + 1] * ii;
                const size_t o = ((size_t)b * S_ + s) * D_ + d;
                __nv_bfloat162 phh, pll;
                phh.x = __float2bfloat16(x0); phh.y = __float2bfloat16(x1);
                pll.x = __float2bfloat16(x0 - __bfloat162float(phh.x));
                pll.y = __float2bfloat16(x1 - __bfloat162float(phh.y));
                *(__nv_bfloat162*)(g_Chi + o) = phh;
                *(__nv_bfloat162*)(g_Clo + o) = pll;
            }
        }
}

// ---------------------------------------------------------------------------
// zero_fill: attn[row, c] = 0 for c >= (qt+1)*256 (region never written by
// attn_single). No dependencies — runs at the start on the side stream.
// Grid (7*256 rows, B*H): tile 7 rows have no zero region.
// ---------------------------------------------------------------------------
__global__ __launch_bounds__(256) void zero_fill(float* __restrict__ attn)
{
    const int row = blockIdx.x;                  // 0..1791 (tiles 0..6)
    const int bh = blockIdx.y;
    const int c0 = ((row >> 8) + 1) * 256;       // first zero column
    float* p = attn + ((size_t)bh * S_ + row) * S_;
    const int tid = threadIdx.x;
    const float4 z = make_float4(0.f, 0.f, 0.f, 0.f);
    for (int i = (c0 >> 2) + tid; i < S_ / 4; i += 256)
        ((float4*)p)[i] = z;
}

// ---------------------------------------------------------------------------
// scale_rows: attn[row, c] *= linv for c < (qt+1)*256 (the written region;
// masked entries inside are already exact 0). Overlaps out-proj GEMM.
// ---------------------------------------------------------------------------
__global__ __launch_bounds__(256) void scale_rows(float* __restrict__ attn)
{
    const int row = blockIdx.x, bh = blockIdx.y;
    const float s = g_linv[(size_t)bh * S_ + row];
    float* p = attn + ((size_t)bh * S_ + row) * S_;
    const int n4 = ((row >> 8) + 1) * 64;        // (qt+1)*256 / 4
    const int tid = threadIdx.x;
    for (int i = tid; i < n4; i += 256) {
        float4 v = ((const float4*)p)[i];
        v.x *= s; v.y *= s; v.z *= s; v.w *= s;
        ((float4*)p)[i] = v;
    }
}

// ---------------------------------------------------------------------------
// Launch. Side stream: zero_fill from the start (no deps), scale_rows after
// attention — both overlap tensor-bound main-stream work.
// ---------------------------------------------------------------------------
extern "C" void kernel_launch(void* const* d_in, const int* in_sizes, int n_in,
                              void* d_out, int out_size)
{
    const float* q = (const float*)d_in[0];
    const float* k = (const float*)d_in[1];
    const float* v = (const float*)d_in[2];
    const float* W[4] = { (const float*)d_in[4], (const float*)d_in[5],
                          (const float*)d_in[6], (const float*)d_in[7] };

    float* out  = (float*)d_out;
    float* attn = out + (size_t)B_ * S_ * D_;

    __nv_bfloat16 *qhi, *qlo, *khi, *klo, *vhi, *vlo, *whi, *wlo;
    __nv_bfloat16 *Qhi, *Qlo, *Khi, *Klo, *Vhi, *Vlo, *Chi, *Clo;
    cudaGetSymbolAddress((void**)&qhi, g_qhi); cudaGetSymbolAddress((void**)&qlo, g_qlo);
    cudaGetSymbolAddress((void**)&khi, g_khi); cudaGetSymbolAddress((void**)&klo, g_klo);
    cudaGetSymbolAddress((void**)&vhi, g_vhi); cudaGetSymbolAddress((void**)&vlo, g_vlo);
    cudaGetSymbolAddress((void**)&whi, g_whi); cudaGetSymbolAddress((void**)&wlo, g_wlo);
    cudaGetSymbolAddress((void**)&Qhi, g_Qhi); cudaGetSymbolAddress((void**)&Qlo, g_Qlo);
    cudaGetSymbolAddress((void**)&Khi, g_Khi); cudaGetSymbolAddress((void**)&Klo, g_Klo);
    cudaGetSymbolAddress((void**)&Vhi, g_Vhi); cudaGetSymbolAddress((void**)&Vlo, g_Vlo);
    cudaGetSymbolAddress((void**)&Chi, g_Chi); cudaGetSymbolAddress((void**)&Clo, g_Clo);

    static cudaStream_t s_side = nullptr;
    static cudaEvent_t evFork0 = nullptr, evFork1 = nullptr, evJoin = nullptr;
    static bool attr_set = false;
    if (!attr_set) {
        cudaFuncSetAttribute(mm_tc<0>, cudaFuncAttributeMaxDynamicSharedMemorySize, 81920);
        cudaFuncSetAttribute(mm_tc<1>, cudaFuncAttributeMaxDynamicSharedMemorySize, 81920);
        cudaFuncSetAttribute(attn_single, cudaFuncAttributeMaxDynamicSharedMemorySize, 147456);
        cudaStreamCreateWithFlags(&s_side, cudaStreamNonBlocking);
        cudaEventCreateWithFlags(&evFork0, cudaEventDisableTiming);
        cudaEventCreateWithFlags(&evFork1, cudaEventDisableTiming);
        cudaEventCreateWithFlags(&evJoin, cudaEventDisableTiming);
        attr_set = true;
    }

    const int n4x = MM_ * D_ / 4;
    const int n4w = D_ * D_ / 4;

    // fork 0: zero-fill (no data deps) runs under the whole front of the pipe
    cudaEventRecord(evFork0, 0);
    cudaStreamWaitEvent(s_side, evFork0, 0);
    dim3 gZF(7 * 256, B_ * H_);
    zero_fill<<<gZF, 256, 0, s_side>>>(attn);

    dim3 gSa((n4x + 255) / 256, 3);
    split_acts<<<gSa, 256>>>(q, k, v, qhi, qlo, khi, klo, vhi, vlo, n4x);
    dim3 gSw((n4w + 255) / 256, 4);
    split_wts4<<<gSw, 256>>>(W[0], W[1], W[2], W[3], whi, wlo, n4w);

    dim3 gQKV(24, MM_ / 128);       // (24, 64)
    mm_tc<1><<<gQKV, 256, 81920>>>(qhi, qlo, khi, klo, vhi, vlo, whi, wlo,
                                   nullptr, Qhi, Qlo, Khi, Klo, Vhi, Vlo);

    dim3 gA(S_ / 256, B_ * H_);     // (8, 64)
    attn_single<<<gA, 256, 147456>>>(attn);

    // fork 1: scale E->P on side stream, out-proj on main stream
    cudaEventRecord(evFork1, 0);
    cudaStreamWaitEvent(s_side, evFork1, 0);
    dim3 gSR(S_, B_ * H_);
    scale_rows<<<gSR, 256, 0, s_side>>>(attn);

    dim3 gO(8, MM_ / 128);          // (8, 64)
    mm_tc<0><<<gO, 256, 81920>>>(Chi, Clo, nullptr, nullptr, nullptr, nullptr,
                                 whi + 3 * (size_t)D_ * D_, wlo + 3 * (size_t)D_ * D_,
                                 out, nullptr, nullptr, nullptr, nullptr, nullptr, nullptr);

    // join
    cudaEventRecord(evJoin, s_side);
    cudaStreamWaitEvent(0, evJoin, 0);
}

// round 12
// speedup vs baseline: 2.9216x; 1.0227x over previous
#include <cuda_runtime.h>
#include <cuda_bf16.h>
#include <cstdint>

#define B_  4
#define S_  2048
#define D_  1024
#define H_  16
#define DK_ 64
#define MM_ (B_ * S_)          // 8192

// ---------------------------------------------------------------------------
// Scratch (device globals)
// ---------------------------------------------------------------------------
__device__ __nv_bfloat16 g_qhi[MM_ * D_], g_qlo[MM_ * D_];
__device__ __nv_bfloat16 g_khi[MM_ * D_], g_klo[MM_ * D_];
__device__ __nv_bfloat16 g_vhi[MM_ * D_], g_vlo[MM_ * D_];
__device__ __nv_bfloat16 g_whi[4][D_ * D_], g_wlo[4][D_ * D_];
__device__ __nv_bfloat16 g_Qhi[MM_ * D_], g_Qlo[MM_ * D_];   // [B,H,S,DK]
__device__ __nv_bfloat16 g_Khi[MM_ * D_], g_Klo[MM_ * D_];
__device__ __nv_bfloat16 g_Vhi[MM_ * D_], g_Vlo[MM_ * D_];
__device__ __nv_bfloat16 g_Chi[MM_ * D_], g_Clo[MM_ * D_];   // [B,S,D]
__device__ float g_linv[B_ * H_ * S_];                        // 1/rowsum

// ---------------------------------------------------------------------------
// PTX helpers
// ---------------------------------------------------------------------------
__device__ __forceinline__ void ldsm4(uint32_t addr, uint32_t* r) {
    asm volatile("ldmatrix.sync.aligned.m8n8.x4.shared.b16 {%0,%1,%2,%3}, [%4];"
        : "=r"(r[0]), "=r"(r[1]), "=r"(r[2]), "=r"(r[3]) : "r"(addr));
}
__device__ __forceinline__ void ldsm4t(uint32_t addr, uint32_t* r) {
    asm volatile("ldmatrix.sync.aligned.m8n8.x4.trans.shared.b16 {%0,%1,%2,%3}, [%4];"
        : "=r"(r[0]), "=r"(r[1]), "=r"(r[2]), "=r"(r[3]) : "r"(addr));
}
__device__ __forceinline__ void mma_bf16(float* c, const uint32_t* a, uint32_t b0, uint32_t b1) {
    asm volatile("mma.sync.aligned.m16n8k16.row.col.f32.bf16.bf16.f32 "
        "{%0,%1,%2,%3}, {%4,%5,%6,%7}, {%8,%9}, {%0,%1,%2,%3};"
        : "+f"(c[0]), "+f"(c[1]), "+f"(c[2]), "+f"(c[3])
        : "r"(a[0]), "r"(a[1]), "r"(a[2]), "r"(a[3]), "r"(b0), "r"(b1));
}
__device__ __forceinline__ uint32_t sptr(const void* p) {
    return (uint32_t)__cvta_generic_to_shared(p);
}
__device__ __forceinline__ void cpa16(uint32_t s, const void* g) {
    asm volatile("cp.async.cg.shared.global [%0], [%1], 16;" :: "r"(s), "l"(g));
}
#define CPA_COMMIT() asm volatile("cp.async.commit_group;" ::: "memory")
#define CPA_WAIT(n)  asm volatile("cp.async.wait_group %0;" :: "n"(n) : "memory")
__device__ __forceinline__ uint32_t pack_bf16(float x, float y) {
    __nv_bfloat162 t; t.x = __float2bfloat16(x); t.y = __float2bfloat16(y);
    return *(uint32_t*)&t;
}

// ---------------------------------------------------------------------------
// Split fp32 -> (hi, lo) bf16
// ---------------------------------------------------------------------------
__device__ __forceinline__ void split4(const float* __restrict__ x,
    __nv_bfloat16* __restrict__ hi, __nv_bfloat16* __restrict__ lo, int i)
{
    float4 v = ((const float4*)x)[i];
    __nv_bfloat16 h0 = __float2bfloat16(v.x), h1 = __float2bfloat16(v.y);
    __nv_bfloat16 h2 = __float2bfloat16(v.z), h3 = __float2bfloat16(v.w);
    __nv_bfloat162 ph0; ph0.x = h0; ph0.y = h1;
    __nv_bfloat162 ph1; ph1.x = h2; ph1.y = h3;
    __nv_bfloat162 pl0; pl0.x = __float2bfloat16(v.x - __bfloat162float(h0));
    pl0.y = __float2bfloat16(v.y - __bfloat162float(h1));
    __nv_bfloat162 pl1; pl1.x = __float2bfloat16(v.z - __bfloat162float(h2));
    pl1.y = __float2bfloat16(v.w - __bfloat162float(h3));
    ((__nv_bfloat162*)hi)[2 * i]     = ph0;
    ((__nv_bfloat162*)hi)[2 * i + 1] = ph1;
    ((__nv_bfloat162*)lo)[2 * i]     = pl0;
    ((__nv_bfloat162*)lo)[2 * i + 1] = pl1;
}

__global__ __launch_bounds__(256) void split_acts(
    const float* q, const float* k, const float* v,
    __nv_bfloat16* qh, __nv_bfloat16* ql, __nv_bfloat16* kh, __nv_bfloat16* kl,
    __nv_bfloat16* vh, __nv_bfloat16* vl, int n4)
{
    int i = blockIdx.x * blockDim.x + threadIdx.x;
    if (i >= n4) return;
    const int z = blockIdx.y;
    const float* x = (z == 0) ? q : (z == 1) ? k : v;
    __nv_bfloat16* hi = (z == 0) ? qh : (z == 1) ? kh : vh;
    __nv_bfloat16* lo = (z == 0) ? ql : (z == 1) ? kl : vl;
    split4(x, hi, lo, i);
}

__global__ __launch_bounds__(256) void split_wts4(
    const float* w0, const float* w1, const float* w2, const float* w3,
    __nv_bfloat16* hi, __nv_bfloat16* lo, int n4)
{
    int i = blockIdx.x * blockDim.x + threadIdx.x;
    if (i >= n4) return;
    const int z = blockIdx.y;
    const float* x = (z == 0) ? w0 : (z == 1) ? w1 : (z == 2) ? w2 : w3;
    split4(x, hi + (size_t)z * D_ * D_, lo + (size_t)z * D_ * D_, i);
}

// ---------------------------------------------------------------------------
// bf16x3 GEMM, cp.async 2-stage pipeline, 2 CTAs/SM (unchanged from R11).
// ---------------------------------------------------------------------------
template <int MODE>
__global__ __launch_bounds__(256, 2) void mm_tc(
    const __nv_bfloat16* __restrict__ A0h, const __nv_bfloat16* __restrict__ A0l,
    const __nv_bfloat16* __restrict__ A1h, const __nv_bfloat16* __restrict__ A1l,
    const __nv_bfloat16* __restrict__ A2h, const __nv_bfloat16* __restrict__ A2l,
    const __nv_bfloat16* __restrict__ Wbh, const __nv_bfloat16* __restrict__ Wbl,
    float* __restrict__ Cf,
    __nv_bfloat16* __restrict__ O0h, __nv_bfloat16* __restrict__ O0l,
    __nv_bfloat16* __restrict__ O1h, __nv_bfloat16* __restrict__ O1l,
    __nv_bfloat16* __restrict__ O2h, __nv_bfloat16* __restrict__ O2l)
{
    extern __shared__ __nv_bfloat16 dsm[];

    const int tid = threadIdx.x, lane = tid & 31, wid = tid >> 5;
    const int wsel = (MODE == 1) ? (blockIdx.x >> 3) : 0;
    const int bn = (MODE == 1) ? ((blockIdx.x & 7) * 128) : (blockIdx.x * 128);
    const int bm = blockIdx.y * 128;
    const int wm = (wid >> 2) * 64, wn = (wid & 3) * 32;

    const __nv_bfloat16* Ah = (MODE == 1) ? (wsel == 0 ? A0h : wsel == 1 ? A1h : A2h) : A0h;
    const __nv_bfloat16* Al = (MODE == 1) ? (wsel == 0 ? A0l : wsel == 1 ? A1l : A2l) : A0l;
    const __nv_bfloat16* Whi = Wbh + (size_t)wsel * D_ * D_;
    const __nv_bfloat16* Wlo = Wbl + (size_t)wsel * D_ * D_;
    __nv_bfloat16* Ohi = (wsel == 0) ? O0h : (wsel == 1) ? O1h : O2h;
    __nv_bfloat16* Olo = (wsel == 0) ? O0l : (wsel == 1) ? O1l : O2l;

    float acc[4][4][4];
#pragma unroll
    for (int a = 0; a < 4; ++a)
#pragma unroll
        for (int b = 0; b < 4; ++b)
#pragma unroll
            for (int c = 0; c < 4; ++c) acc[a][b][c] = 0.f;

    const int grp = lane >> 3, koff = (grp & 1) << 3, nb = (grp >> 1) << 3, nr = lane & 7;

#define MM_LOAD(it, st) do {                                                     \
    const int _k0 = (it) * 32;                                                   \
    __nv_bfloat16* _bb = dsm + (st) * 20480;                                     \
    _Pragma("unroll")                                                            \
    for (int _t = 0; _t < 2; ++_t) {                                             \
        const int _idx = tid + _t * 256;                                         \
        const int _row = _idx >> 2, _c8 = (_idx & 3) << 3;                       \
        const int _so = _row * 40 + _c8;                                         \
        cpa16(sptr(_bb + _so),         Ah + (size_t)(bm + _row) * D_ + _k0 + _c8); \
        cpa16(sptr(_bb + 5120 + _so),  Al + (size_t)(bm + _row) * D_ + _k0 + _c8); \
        cpa16(sptr(_bb + 10240 + _so), Whi + (size_t)(bn + _row) * D_ + _k0 + _c8); \
        cpa16(sptr(_bb + 15360 + _so), Wlo + (size_t)(bn + _row) * D_ + _k0 + _c8); \
    } } while (0)

    MM_LOAD(0, 0); CPA_COMMIT();

    for (int it = 0; it < 32; ++it) {
        if (it + 1 < 32) { MM_LOAD(it + 1, (it + 1) & 1); CPA_COMMIT(); CPA_WAIT(1); }
        else             { CPA_WAIT(0); }
        __syncthreads();

        const __nv_bfloat16* sAh = dsm + (it & 1) * 20480;
        const __nv_bfloat16* sAl = sAh + 5120;
        const __nv_bfloat16* sWh = sAh + 10240;
        const __nv_bfloat16* sWl = sAh + 15360;

#pragma unroll
        for (int kk = 0; kk < 2; ++kk) {
            uint32_t aH[4][4], aL[4][4];
#pragma unroll
            for (int mt = 0; mt < 4; ++mt) {
                const int r = wm + mt * 16 + (lane & 15);
                const int c = kk * 16 + ((lane >> 4) << 3);
                ldsm4(sptr(sAh + r * 40 + c), aH[mt]);
                ldsm4(sptr(sAl + r * 40 + c), aL[mt]);
            }
#pragma unroll
            for (int np = 0; np < 2; ++np) {
                uint32_t bH[4], bL[4];
                const int n = wn + np * 16 + nb + nr;
                const int c = kk * 16 + koff;
                ldsm4(sptr(sWh + n * 40 + c), bH);
                ldsm4(sptr(sWl + n * 40 + c), bL);
#pragma unroll
                for (int mt = 0; mt < 4; ++mt)
#pragma unroll
                    for (int j = 0; j < 2; ++j) {
                        const int nt = np * 2 + j;
                        mma_bf16(acc[mt][nt], aH[mt], bH[2 * j], bH[2 * j + 1]);
                        mma_bf16(acc[mt][nt], aH[mt], bL[2 * j], bL[2 * j + 1]);
                        mma_bf16(acc[mt][nt], aL[mt], bH[2 * j], bH[2 * j + 1]);
                    }
            }
        }
        __syncthreads();
    }
#undef MM_LOAD

#pragma unroll
    for (int mt = 0; mt < 4; ++mt)
#pragma unroll
        for (int nt = 0; nt < 4; ++nt) {
            const float* c = acc[mt][nt];
            const int n = bn + wn + nt * 8 + ((lane & 3) << 1);
#pragma unroll
            for (int hf = 0; hf < 2; ++hf) {
                const int m = bm + wm + mt * 16 + (lane >> 2) + hf * 8;
                const float x0 = c[hf * 2], x1 = c[hf * 2 + 1];
                if (MODE == 0) {
                    *(float2*)(Cf + (size_t)m * D_ + n) = make_float2(x0, x1);
                } else {
                    const int b = m >> 11, s = m & (S_ - 1);
                    const int h = n >> 6, dk = n & (DK_ - 1);
                    const size_t o = (((size_t)(b * H_ + h) * S_ + s) << 6) + dk;
                    __nv_bfloat16 h0 = __float2bfloat16(x0), h1 = __float2bfloat16(x1);
                    __nv_bfloat162 ph; ph.x = h0; ph.y = h1;
                    __nv_bfloat162 pl;
                    pl.x = __float2bfloat16(x0 - __bfloat162float(h0));
                    pl.y = __float2bfloat16(x1 - __bfloat162float(h1));
                    *(__nv_bfloat162*)(Ohi + o) = ph;
                    *(__nv_bfloat162*)(Olo + o) = pl;
                }
            }
        }
}

// ---------------------------------------------------------------------------
// Single-pass attention, q-tile 128, 8 warps x 16 q-rows, 2 CTAs/SM.
// smem elems: Qh@0 (9216), Ql@9216; stage st @18432+st*18432:
// Kh+0, Kl+4608, Vh+9216, Vl+13824. Total 55296 elems = 110592 B.
// ---------------------------------------------------------------------------
__global__ __launch_bounds__(256, 2) void attn_single(float* __restrict__ attn)
{
    extern __shared__ __nv_bfloat16 sm[];
    __nv_bfloat16* Qh = sm;
    __nv_bfloat16* Ql = sm + 9216;

    const int qt = gridDim.x - 1 - (int)blockIdx.x;   // big tiles first
    const int bh = blockIdx.y;
    const int tid = threadIdx.x, lane = tid & 31, wid = tid >> 5;
    const int q0 = qt * 128;
    const int nkt = 2 * qt + 2;
    const int grp = lane >> 3, koff = (grp & 1) << 3, nb = (grp >> 1) << 3, nr = lane & 7;
    const int wrow = wid * 16;

    // ---- load Q tile (128 x 64 hi/lo) ----
#pragma unroll
    for (int t = 0; t < 8; ++t) {
        const int idx = tid + t * 256;               // 0..2047 uint4 slots
        const int buf = idx >> 10;
        const int r = (idx >> 3) & 127, c8 = (idx & 7) << 3;
        const __nv_bfloat16* src = buf ? g_Qlo : g_Qhi;
        __nv_bfloat16* dst = buf ? Ql : Qh;
        *(uint4*)&dst[r * 72 + c8] =
            *(const uint4*)(src + (((size_t)bh * S_ + q0 + r) << 6) + c8);
    }

    const int lrow = lane >> 2;

#define AT_LOADKV(kt, st) do {                                                   \
    __nv_bfloat16* _bb = sm + 18432 + (st) * 18432;                              \
    _Pragma("unroll")                                                            \
    for (int _t = 0; _t < 2; ++_t) {                                             \
        const int _idx = tid + _t * 256;                                         \
        const int _r = _idx >> 3, _c8 = (_idx & 7) << 3;                         \
        const size_t _g = (((size_t)bh * S_ + (kt) * 64 + _r) << 6) + _c8;       \
        const int _so = _r * 72 + _c8;                                           \
        cpa16(sptr(_bb + _so),         g_Khi + _g);                              \
        cpa16(sptr(_bb + 4608 + _so),  g_Klo + _g);                              \
        cpa16(sptr(_bb + 9216 + _so),  g_Vhi + _g);                              \
        cpa16(sptr(_bb + 13824 + _so), g_Vlo + _g);                              \
    } } while (0)

    float accO[8][4];
#pragma unroll
    for (int b = 0; b < 8; ++b)
#pragma unroll
        for (int c = 0; c < 4; ++c) accO[b][c] = 0.f;
    float lsum[2] = {0.f, 0.f};

    AT_LOADKV(0, 0); CPA_COMMIT();
    for (int kt = 0; kt < nkt; ++kt) {
        if (kt + 1 < nkt) { AT_LOADKV(kt + 1, (kt + 1) & 1); CPA_COMMIT(); CPA_WAIT(1); }
        else              { CPA_WAIT(0); }
        __syncthreads();

        const __nv_bfloat16* Kh = sm + 18432 + (kt & 1) * 18432;
        const __nv_bfloat16* Kl = Kh + 4608;
        const __nv_bfloat16* Vh = Kh + 9216;
        const __nv_bfloat16* Vl = Kh + 13824;

        // ---- scores: 16x64 per warp ----
        float acc[8][4];
#pragma unroll
        for (int b = 0; b < 8; ++b)
#pragma unroll
            for (int c = 0; c < 4; ++c) acc[b][c] = 0.f;

#pragma unroll
        for (int kk = 0; kk < 4; ++kk) {
            uint32_t aH[4], aL[4];
            {
                const int r = wrow + (lane & 15);
                const int c = kk * 16 + ((lane >> 4) << 3);
                ldsm4(sptr(Qh + r * 72 + c), aH);
                ldsm4(sptr(Ql + r * 72 + c), aL);
            }
#pragma unroll
            for (int np = 0; np < 4; ++np) {
                uint32_t bH[4], bL[4];
                const int n = np * 16 + nb + nr;
                const int cc = kk * 16 + koff;
                ldsm4(sptr(Kh + n * 72 + cc), bH);
                ldsm4(sptr(Kl + n * 72 + cc), bL);
#pragma unroll
                for (int j = 0; j < 2; ++j) {
                    const int nt = np * 2 + j;
                    mma_bf16(acc[nt], aH, bH[2 * j], bH[2 * j + 1]);
                    mma_bf16(acc[nt], aH, bL[2 * j], bL[2 * j + 1]);
                    mma_bf16(acc[nt], aL, bH[2 * j], bH[2 * j + 1]);
                }
            }
        }

        const bool need_mask = (kt * 64 + 63) > (q0 + wrow);

        // ---- exp + E write + l accum + pack + PV MMA ----
#pragma unroll
        for (int t = 0; t < 4; ++t) {
            uint32_t pH[4], pL[4];
#pragma unroll
            for (int g = 0; g < 2; ++g) {
                const int nt = 2 * t + g;
                const int kc = kt * 64 + nt * 8 + ((lane & 3) << 1);
#pragma unroll
                for (int hf = 0; hf < 2; ++hf) {
                    const int qr = q0 + wrow + lrow + hf * 8;
                    float x0 = acc[nt][hf * 2] * 0.125f;
                    float x1 = acc[nt][hf * 2 + 1] * 0.125f;
                    if (need_mask) {
                        if (kc > qr)     x0 = -1e30f;
                        if (kc + 1 > qr) x1 = -1e30f;
                    }
                    const float e0 = __expf(x0);
                    const float e1 = __expf(x1);
                    lsum[hf] += e0 + e1;
                    float* dst = attn + ((size_t)bh * S_ + qr) * S_ + kc;
                    *(float2*)dst = make_float2(e0, e1);
                    const uint32_t hpk = pack_bf16(e0, e1);
                    __nv_bfloat162 hb = *(__nv_bfloat162*)&hpk;
                    pH[g * 2 + hf] = hpk;
                    pL[g * 2 + hf] = pack_bf16(e0 - __bfloat162float(hb.x),
                                               e1 - __bfloat162float(hb.y));
                }
            }
#pragma unroll
            for (int np = 0; np < 4; ++np) {
                uint32_t bH[4], bL[4];
                const int kr = t * 16 + koff + nr;
                const int nc = np * 16 + nb;
                ldsm4t(sptr(Vh + kr * 72 + nc), bH);
                ldsm4t(sptr(Vl + kr * 72 + nc), bL);
#pragma unroll
                for (int j = 0; j < 2; ++j) {
                    const int nt = np * 2 + j;
                    mma_bf16(accO[nt], pH, bH[2 * j], bH[2 * j + 1]);
                    mma_bf16(accO[nt], pH, bL[2 * j], bL[2 * j + 1]);
                    mma_bf16(accO[nt], pL, bH[2 * j], bH[2 * j + 1]);
                }
            }
        }
        __syncthreads();
    }
#undef AT_LOADKV

    // merge l across the 4 lanes sharing each row
    float il[2];
#pragma unroll
    for (int hf = 0; hf < 2; ++hf) {
        float l = lsum[hf];
#pragma unroll
        for (int off = 1; off <= 2; off <<= 1)
            l += __shfl_xor_sync(0xffffffffu, l, off);
        il[hf] = 1.f / l;
    }

    if ((lane & 3) == 0) {
        g_linv[(size_t)bh * S_ + q0 + wrow + lrow]     = il[0];
        g_linv[(size_t)bh * S_ + q0 + wrow + lrow + 8] = il[1];
    }

    // ---- write O = accO / l as bf16 hi/lo to g_Chi/g_Clo [B,S,D] ----
    const int b = bh >> 4, h = bh & (H_ - 1);
#pragma unroll
    for (int nt = 0; nt < 8; ++nt) {
        const int d = h * DK_ + nt * 8 + ((lane & 3) << 1);
#pragma unroll
        for (int hf = 0; hf < 2; ++hf) {
            const int s = q0 + wrow + lrow + hf * 8;
            const float ii = il[hf];
            const float x0 = accO[nt][hf * 2] * ii;
            const float x1 = accO[nt][hf * 2 + 1] * ii;
            const size_t o = ((size_t)b * S_ + s) * D_ + d;
            __nv_bfloat162 phh, pll;
            phh.x = __float2bfloat16(x0); phh.y = __float2bfloat16(x1);
            pll.x = __float2bfloat16(x0 - __bfloat162float(phh.x));
            pll.y = __float2bfloat16(x1 - __bfloat162float(phh.y));
            *(__nv_bfloat162*)(g_Chi + o) = phh;
            *(__nv_bfloat162*)(g_Clo + o) = pll;
        }
    }
}

// ---------------------------------------------------------------------------
// zero_fill: attn[row, c] = 0 for c >= (qt+1)*128 (never written by attn).
// Grid (15*128 rows, B*H): tile 15 rows have no zero region.
// ---------------------------------------------------------------------------
__global__ __launch_bounds__(256) void zero_fill(float* __restrict__ attn)
{
    const int row = blockIdx.x;                  // 0..1919 (tiles 0..14)
    const int bh = blockIdx.y;
    const int c0 = ((row >> 7) + 1) * 128;       // first zero column
    float* p = attn + ((size_t)bh * S_ + row) * S_;
    const int tid = threadIdx.x;
    const float4 z = make_float4(0.f, 0.f, 0.f, 0.f);
    for (int i = (c0 >> 2) + tid; i < S_ / 4; i += 256)
        ((float4*)p)[i] = z;
}

// ---------------------------------------------------------------------------
// scale_rows: attn[row, c] *= linv for c < (qt+1)*128 (the written region).
// ---------------------------------------------------------------------------
__global__ __launch_bounds__(256) void scale_rows(float* __restrict__ attn)
{
    const int row = blockIdx.x, bh = blockIdx.y;
    const float s = g_linv[(size_t)bh * S_ + row];
    float* p = attn + ((size_t)bh * S_ + row) * S_;
    const int n4 = ((row >> 7) + 1) * 32;        // (qt+1)*128 / 4
    const int tid = threadIdx.x;
    for (int i = tid; i < n4; i += 256) {
        float4 v = ((const float4*)p)[i];
        v.x *= s; v.y *= s; v.z *= s; v.w *= s;
        ((float4*)p)[i] = v;
    }
}

// ---------------------------------------------------------------------------
// Launch
// ---------------------------------------------------------------------------
extern "C" void kernel_launch(void* const* d_in, const int* in_sizes, int n_in,
                              void* d_out, int out_size)
{
    const float* q = (const float*)d_in[0];
    const float* k = (const float*)d_in[1];
    const float* v = (const float*)d_in[2];
    const float* W[4] = { (const float*)d_in[4], (const float*)d_in[5],
                          (const float*)d_in[6], (const float*)d_in[7] };

    float* out  = (float*)d_out;
    float* attn = out + (size_t)B_ * S_ * D_;

    __nv_bfloat16 *qhi, *qlo, *khi, *klo, *vhi, *vlo, *whi, *wlo;
    __nv_bfloat16 *Qhi, *Qlo, *Khi, *Klo, *Vhi, *Vlo, *Chi, *Clo;
    cudaGetSymbolAddress((void**)&qhi, g_qhi); cudaGetSymbolAddress((void**)&qlo, g_qlo);
    cudaGetSymbolAddress((void**)&khi, g_khi); cudaGetSymbolAddress((void**)&klo, g_klo);
    cudaGetSymbolAddress((void**)&vhi, g_vhi); cudaGetSymbolAddress((void**)&vlo, g_vlo);
    cudaGetSymbolAddress((void**)&whi, g_whi); cudaGetSymbolAddress((void**)&wlo, g_wlo);
    cudaGetSymbolAddress((void**)&Qhi, g_Qhi); cudaGetSymbolAddress((void**)&Qlo, g_Qlo);
    cudaGetSymbolAddress((void**)&Khi, g_Khi); cudaGetSymbolAddress((void**)&Klo, g_Klo);
    cudaGetSymbolAddress((void**)&Vhi, g_Vhi); cudaGetSymbolAddress((void**)&Vlo, g_Vlo);
    cudaGetSymbolAddress((void**)&Chi, g_Chi); cudaGetSymbolAddress((void**)&Clo, g_Clo);

    static cudaStream_t s_side = nullptr;
    static cudaEvent_t evFork0 = nullptr, evFork1 = nullptr, evJoin = nullptr;
    static bool attr_set = false;
    if (!attr_set) {
        cudaFuncSetAttribute(mm_tc<0>, cudaFuncAttributeMaxDynamicSharedMemorySize, 81920);
        cudaFuncSetAttribute(mm_tc<1>, cudaFuncAttributeMaxDynamicSharedMemorySize, 81920);
        cudaFuncSetAttribute(attn_single, cudaFuncAttributeMaxDynamicSharedMemorySize, 110592);
        cudaStreamCreateWithFlags(&s_side, cudaStreamNonBlocking);
        cudaEventCreateWithFlags(&evFork0, cudaEventDisableTiming);
        cudaEventCreateWithFlags(&evFork1, cudaEventDisableTiming);
        cudaEventCreateWithFlags(&evJoin, cudaEventDisableTiming);
        attr_set = true;
    }

    const int n4x = MM_ * D_ / 4;
    const int n4w = D_ * D_ / 4;

    // fork 0: zero-fill (no data deps) runs under the whole front of the pipe
    cudaEventRecord(evFork0, 0);
    cudaStreamWaitEvent(s_side, evFork0, 0);
    dim3 gZF(15 * 128, B_ * H_);
    zero_fill<<<gZF, 256, 0, s_side>>>(attn);

    dim3 gSa((n4x + 255) / 256, 3);
    split_acts<<<gSa, 256>>>(q, k, v, qhi, qlo, khi, klo, vhi, vlo, n4x);
    dim3 gSw((n4w + 255) / 256, 4);
    split_wts4<<<gSw, 256>>>(W[0], W[1], W[2], W[3], whi, wlo, n4w);

    dim3 gQKV(24, MM_ / 128);       // (24, 64)
    mm_tc<1><<<gQKV, 256, 81920>>>(qhi, qlo, khi, klo, vhi, vlo, whi, wlo,
                                   nullptr, Qhi, Qlo, Khi, Klo, Vhi, Vlo);

    dim3 gA(S_ / 128, B_ * H_);     // (16, 64)
    attn_single<<<gA, 256, 110592>>>(attn);

    // fork 1: scale E->P on side stream, out-proj on main stream
    cudaEventRecord(evFork1, 0);
    cudaStreamWaitEvent(s_side, evFork1, 0);
    dim3 gSR(S_, B_ * H_);
    scale_rows<<<gSR, 256, 0, s_side>>>(attn);

    dim3 gO(8, MM_ / 128);          // (8, 64)
    mm_tc<0><<<gO, 256, 81920>>>(Chi, Clo, nullptr, nullptr, nullptr, nullptr,
                                 whi + 3 * (size_t)D_ * D_, wlo + 3 * (size_t)D_ * D_,
                                 out, nullptr, nullptr, nullptr, nullptr, nullptr, nullptr);

    // join
    cudaEventRecord(evJoin, s_side);
    cudaStreamWaitEvent(0, evJoin, 0);
}

// round 13
// speedup vs baseline: 2.9461x; 1.0084x over previous
#include <cuda_runtime.h>
#include <cuda_bf16.h>
#include <cstdint>

#define B_  4
#define S_  2048
#define D_  1024
#define H_  16
#define DK_ 64
#define MM_ (B_ * S_)          // 8192

// ---------------------------------------------------------------------------
// Scratch (device globals)
// ---------------------------------------------------------------------------
__device__ __nv_bfloat16 g_qhi[MM_ * D_], g_qlo[MM_ * D_];
__device__ __nv_bfloat16 g_khi[MM_ * D_], g_klo[MM_ * D_];
__device__ __nv_bfloat16 g_vhi[MM_ * D_], g_vlo[MM_ * D_];
__device__ __nv_bfloat16 g_whi[4][D_ * D_], g_wlo[4][D_ * D_];
__device__ __nv_bfloat16 g_Qhi[MM_ * D_], g_Qlo[MM_ * D_];   // [B,H,S,DK]
__device__ __nv_bfloat16 g_Khi[MM_ * D_], g_Klo[MM_ * D_];
__device__ __nv_bfloat16 g_Vhi[MM_ * D_], g_Vlo[MM_ * D_];
__device__ __nv_bfloat16 g_Chi[MM_ * D_], g_Clo[MM_ * D_];   // [B,S,D]
__device__ float g_linv[B_ * H_ * S_];                        // 1/rowsum

// ---------------------------------------------------------------------------
// PTX helpers
// ---------------------------------------------------------------------------
__device__ __forceinline__ void ldsm4(uint32_t addr, uint32_t* r) {
    asm volatile("ldmatrix.sync.aligned.m8n8.x4.shared.b16 {%0,%1,%2,%3}, [%4];"
        : "=r"(r[0]), "=r"(r[1]), "=r"(r[2]), "=r"(r[3]) : "r"(addr));
}
__device__ __forceinline__ void ldsm4t(uint32_t addr, uint32_t* r) {
    asm volatile("ldmatrix.sync.aligned.m8n8.x4.trans.shared.b16 {%0,%1,%2,%3}, [%4];"
        : "=r"(r[0]), "=r"(r[1]), "=r"(r[2]), "=r"(r[3]) : "r"(addr));
}
__device__ __forceinline__ void mma_bf16(float* c, const uint32_t* a, uint32_t b0, uint32_t b1) {
    asm volatile("mma.sync.aligned.m16n8k16.row.col.f32.bf16.bf16.f32 "
        "{%0,%1,%2,%3}, {%4,%5,%6,%7}, {%8,%9}, {%0,%1,%2,%3};"
        : "+f"(c[0]), "+f"(c[1]), "+f"(c[2]), "+f"(c[3])
        : "r"(a[0]), "r"(a[1]), "r"(a[2]), "r"(a[3]), "r"(b0), "r"(b1));
}
__device__ __forceinline__ uint32_t sptr(const void* p) {
    return (uint32_t)__cvta_generic_to_shared(p);
}
__device__ __forceinline__ void cpa16(uint32_t s, const void* g) {
    asm volatile("cp.async.cg.shared.global [%0], [%1], 16;" :: "r"(s), "l"(g));
}
#define CPA_COMMIT() asm volatile("cp.async.commit_group;" ::: "memory")
#define CPA_WAIT(n)  asm volatile("cp.async.wait_group %0;" :: "n"(n) : "memory")
__device__ __forceinline__ uint32_t pack_bf16(float x, float y) {
    __nv_bfloat162 t; t.x = __float2bfloat16(x); t.y = __float2bfloat16(y);
    return *(uint32_t*)&t;
}

// ---------------------------------------------------------------------------
// Split fp32 -> (hi, lo) bf16
// ---------------------------------------------------------------------------
__device__ __forceinline__ void split4(const float* __restrict__ x,
    __nv_bfloat16* __restrict__ hi, __nv_bfloat16* __restrict__ lo, int i)
{
    float4 v = ((const float4*)x)[i];
    __nv_bfloat16 h0 = __float2bfloat16(v.x), h1 = __float2bfloat16(v.y);
    __nv_bfloat16 h2 = __float2bfloat16(v.z), h3 = __float2bfloat16(v.w);
    __nv_bfloat162 ph0; ph0.x = h0; ph0.y = h1;
    __nv_bfloat162 ph1; ph1.x = h2; ph1.y = h3;
    __nv_bfloat162 pl0; pl0.x = __float2bfloat16(v.x - __bfloat162float(h0));
    pl0.y = __float2bfloat16(v.y - __bfloat162float(h1));
    __nv_bfloat162 pl1; pl1.x = __float2bfloat16(v.z - __bfloat162float(h2));
    pl1.y = __float2bfloat16(v.w - __bfloat162float(h3));
    ((__nv_bfloat162*)hi)[2 * i]     = ph0;
    ((__nv_bfloat162*)hi)[2 * i + 1] = ph1;
    ((__nv_bfloat162*)lo)[2 * i]     = pl0;
    ((__nv_bfloat162*)lo)[2 * i + 1] = pl1;
}

__global__ __launch_bounds__(256) void split_acts(
    const float* q, const float* k, const float* v,
    __nv_bfloat16* qh, __nv_bfloat16* ql, __nv_bfloat16* kh, __nv_bfloat16* kl,
    __nv_bfloat16* vh, __nv_bfloat16* vl, int n4)
{
    int i = blockIdx.x * blockDim.x + threadIdx.x;
    if (i >= n4) return;
    const int z = blockIdx.y;
    const float* x = (z == 0) ? q : (z == 1) ? k : v;
    __nv_bfloat16* hi = (z == 0) ? qh : (z == 1) ? kh : vh;
    __nv_bfloat16* lo = (z == 0) ? ql : (z == 1) ? kl : vl;
    split4(x, hi, lo, i);
}

__global__ __launch_bounds__(256) void split_wts4(
    const float* w0, const float* w1, const float* w2, const float* w3,
    __nv_bfloat16* hi, __nv_bfloat16* lo, int n4)
{
    int i = blockIdx.x * blockDim.x + threadIdx.x;
    if (i >= n4) return;
    const int z = blockIdx.y;
    const float* x = (z == 0) ? w0 : (z == 1) ? w1 : (z == 2) ? w2 : w3;
    split4(x, hi + (size_t)z * D_ * D_, lo + (size_t)z * D_ * D_, i);
}

// ---------------------------------------------------------------------------
// bf16x3 GEMM, cp.async 2-stage pipeline, 2 CTAs/SM (unchanged).
// ---------------------------------------------------------------------------
template <int MODE>
__global__ __launch_bounds__(256, 2) void mm_tc(
    const __nv_bfloat16* __restrict__ A0h, const __nv_bfloat16* __restrict__ A0l,
    const __nv_bfloat16* __restrict__ A1h, const __nv_bfloat16* __restrict__ A1l,
    const __nv_bfloat16* __restrict__ A2h, const __nv_bfloat16* __restrict__ A2l,
    const __nv_bfloat16* __restrict__ Wbh, const __nv_bfloat16* __restrict__ Wbl,
    float* __restrict__ Cf,
    __nv_bfloat16* __restrict__ O0h, __nv_bfloat16* __restrict__ O0l,
    __nv_bfloat16* __restrict__ O1h, __nv_bfloat16* __restrict__ O1l,
    __nv_bfloat16* __restrict__ O2h, __nv_bfloat16* __restrict__ O2l)
{
    extern __shared__ __nv_bfloat16 dsm[];

    const int tid = threadIdx.x, lane = tid & 31, wid = tid >> 5;
    const int wsel = (MODE == 1) ? (blockIdx.x >> 3) : 0;
    const int bn = (MODE == 1) ? ((blockIdx.x & 7) * 128) : (blockIdx.x * 128);
    const int bm = blockIdx.y * 128;
    const int wm = (wid >> 2) * 64, wn = (wid & 3) * 32;

    const __nv_bfloat16* Ah = (MODE == 1) ? (wsel == 0 ? A0h : wsel == 1 ? A1h : A2h) : A0h;
    const __nv_bfloat16* Al = (MODE == 1) ? (wsel == 0 ? A0l : wsel == 1 ? A1l : A2l) : A0l;
    const __nv_bfloat16* Whi = Wbh + (size_t)wsel * D_ * D_;
    const __nv_bfloat16* Wlo = Wbl + (size_t)wsel * D_ * D_;
    __nv_bfloat16* Ohi = (wsel == 0) ? O0h : (wsel == 1) ? O1h : O2h;
    __nv_bfloat16* Olo = (wsel == 0) ? O0l : (wsel == 1) ? O1l : O2l;

    float acc[4][4][4];
#pragma unroll
    for (int a = 0; a < 4; ++a)
#pragma unroll
        for (int b = 0; b < 4; ++b)
#pragma unroll
            for (int c = 0; c < 4; ++c) acc[a][b][c] = 0.f;

    const int grp = lane >> 3, koff = (grp & 1) << 3, nb = (grp >> 1) << 3, nr = lane & 7;

#define MM_LOAD(it, st) do {                                                     \
    const int _k0 = (it) * 32;                                                   \
    __nv_bfloat16* _bb = dsm + (st) * 20480;                                     \
    _Pragma("unroll")                                                            \
    for (int _t = 0; _t < 2; ++_t) {                                             \
        const int _idx = tid + _t * 256;                                         \
        const int _row = _idx >> 2, _c8 = (_idx & 3) << 3;                       \
        const int _so = _row * 40 + _c8;                                         \
        cpa16(sptr(_bb + _so),         Ah + (size_t)(bm + _row) * D_ + _k0 + _c8); \
        cpa16(sptr(_bb + 5120 + _so),  Al + (size_t)(bm + _row) * D_ + _k0 + _c8); \
        cpa16(sptr(_bb + 10240 + _so), Whi + (size_t)(bn + _row) * D_ + _k0 + _c8); \
        cpa16(sptr(_bb + 15360 + _so), Wlo + (size_t)(bn + _row) * D_ + _k0 + _c8); \
    } } while (0)

    MM_LOAD(0, 0); CPA_COMMIT();

    for (int it = 0; it < 32; ++it) {
        if (it + 1 < 32) { MM_LOAD(it + 1, (it + 1) & 1); CPA_COMMIT(); CPA_WAIT(1); }
        else             { CPA_WAIT(0); }
        __syncthreads();

        const __nv_bfloat16* sAh = dsm + (it & 1) * 20480;
        const __nv_bfloat16* sAl = sAh + 5120;
        const __nv_bfloat16* sWh = sAh + 10240;
        const __nv_bfloat16* sWl = sAh + 15360;

#pragma unroll
        for (int kk = 0; kk < 2; ++kk) {
            uint32_t aH[4][4], aL[4][4];
#pragma unroll
            for (int mt = 0; mt < 4; ++mt) {
                const int r = wm + mt * 16 + (lane & 15);
                const int c = kk * 16 + ((lane >> 4) << 3);
                ldsm4(sptr(sAh + r * 40 + c), aH[mt]);
                ldsm4(sptr(sAl + r * 40 + c), aL[mt]);
            }
#pragma unroll
            for (int np = 0; np < 2; ++np) {
                uint32_t bH[4], bL[4];
                const int n = wn + np * 16 + nb + nr;
                const int c = kk * 16 + koff;
                ldsm4(sptr(sWh + n * 40 + c), bH);
                ldsm4(sptr(sWl + n * 40 + c), bL);
#pragma unroll
                for (int mt = 0; mt < 4; ++mt)
#pragma unroll
                    for (int j = 0; j < 2; ++j) {
                        const int nt = np * 2 + j;
                        mma_bf16(acc[mt][nt], aH[mt], bH[2 * j], bH[2 * j + 1]);
                        mma_bf16(acc[mt][nt], aH[mt], bL[2 * j], bL[2 * j + 1]);
                        mma_bf16(acc[mt][nt], aL[mt], bH[2 * j], bH[2 * j + 1]);
                    }
            }
        }
        __syncthreads();
    }
#undef MM_LOAD

#pragma unroll
    for (int mt = 0; mt < 4; ++mt)
#pragma unroll
        for (int nt = 0; nt < 4; ++nt) {
            const float* c = acc[mt][nt];
            const int n = bn + wn + nt * 8 + ((lane & 3) << 1);
#pragma unroll
            for (int hf = 0; hf < 2; ++hf) {
                const int m = bm + wm + mt * 16 + (lane >> 2) + hf * 8;
                const float x0 = c[hf * 2], x1 = c[hf * 2 + 1];
                if (MODE == 0) {
                    *(float2*)(Cf + (size_t)m * D_ + n) = make_float2(x0, x1);
                } else {
                    const int b = m >> 11, s = m & (S_ - 1);
                    const int h = n >> 6, dk = n & (DK_ - 1);
                    const size_t o = (((size_t)(b * H_ + h) * S_ + s) << 6) + dk;
                    __nv_bfloat16 h0 = __float2bfloat16(x0), h1 = __float2bfloat16(x1);
                    __nv_bfloat162 ph; ph.x = h0; ph.y = h1;
                    __nv_bfloat162 pl;
                    pl.x = __float2bfloat16(x0 - __bfloat162float(h0));
                    pl.y = __float2bfloat16(x1 - __bfloat162float(h1));
                    *(__nv_bfloat162*)(Ohi + o) = ph;
                    *(__nv_bfloat162*)(Olo + o) = pl;
                }
            }
        }
}

// ---------------------------------------------------------------------------
// Single-pass attention, q-tile 128, 2 CTAs/SM. qt = qt_base + reversed bx.
// ---------------------------------------------------------------------------
__global__ __launch_bounds__(256, 2) void attn_single(float* __restrict__ attn,
                                                      int qt_base)
{
    extern __shared__ __nv_bfloat16 sm[];
    __nv_bfloat16* Qh = sm;
    __nv_bfloat16* Ql = sm + 9216;

    const int qt = qt_base + (int)gridDim.x - 1 - (int)blockIdx.x;  // big first
    const int bh = blockIdx.y;
    const int tid = threadIdx.x, lane = tid & 31, wid = tid >> 5;
    const int q0 = qt * 128;
    const int nkt = 2 * qt + 2;
    const int grp = lane >> 3, koff = (grp & 1) << 3, nb = (grp >> 1) << 3, nr = lane & 7;
    const int wrow = wid * 16;

#pragma unroll
    for (int t = 0; t < 8; ++t) {
        const int idx = tid + t * 256;
        const int buf = idx >> 10;
        const int r = (idx >> 3) & 127, c8 = (idx & 7) << 3;
        const __nv_bfloat16* src = buf ? g_Qlo : g_Qhi;
        __nv_bfloat16* dst = buf ? Ql : Qh;
        *(uint4*)&dst[r * 72 + c8] =
            *(const uint4*)(src + (((size_t)bh * S_ + q0 + r) << 6) + c8);
    }

    const int lrow = lane >> 2;

#define AT_LOADKV(kt, st) do {                                                   \
    __nv_bfloat16* _bb = sm + 18432 + (st) * 18432;                              \
    _Pragma("unroll")                                                            \
    for (int _t = 0; _t < 2; ++_t) {                                             \
        const int _idx = tid + _t * 256;                                         \
        const int _r = _idx >> 3, _c8 = (_idx & 7) << 3;                         \
        const size_t _g = (((size_t)bh * S_ + (kt) * 64 + _r) << 6) + _c8;       \
        const int _so = _r * 72 + _c8;                                           \
        cpa16(sptr(_bb + _so),         g_Khi + _g);                              \
        cpa16(sptr(_bb + 4608 + _so),  g_Klo + _g);                              \
        cpa16(sptr(_bb + 9216 + _so),  g_Vhi + _g);                              \
        cpa16(sptr(_bb + 13824 + _so), g_Vlo + _g);                              \
    } } while (0)

    float accO[8][4];
#pragma unroll
    for (int b = 0; b < 8; ++b)
#pragma unroll
        for (int c = 0; c < 4; ++c) accO[b][c] = 0.f;
    float lsum[2] = {0.f, 0.f};

    AT_LOADKV(0, 0); CPA_COMMIT();
    for (int kt = 0; kt < nkt; ++kt) {
        if (kt + 1 < nkt) { AT_LOADKV(kt + 1, (kt + 1) & 1); CPA_COMMIT(); CPA_WAIT(1); }
        else              { CPA_WAIT(0); }
        __syncthreads();

        const __nv_bfloat16* Kh = sm + 18432 + (kt & 1) * 18432;
        const __nv_bfloat16* Kl = Kh + 4608;
        const __nv_bfloat16* Vh = Kh + 9216;
        const __nv_bfloat16* Vl = Kh + 13824;

        float acc[8][4];
#pragma unroll
        for (int b = 0; b < 8; ++b)
#pragma unroll
            for (int c = 0; c < 4; ++c) acc[b][c] = 0.f;

#pragma unroll
        for (int kk = 0; kk < 4; ++kk) {
            uint32_t aH[4], aL[4];
            {
                const int r = wrow + (lane & 15);
                const int c = kk * 16 + ((lane >> 4) << 3);
                ldsm4(sptr(Qh + r * 72 + c), aH);
                ldsm4(sptr(Ql + r * 72 + c), aL);
            }
#pragma unroll
            for (int np = 0; np < 4; ++np) {
                uint32_t bH[4], bL[4];
                const int n = np * 16 + nb + nr;
                const int cc = kk * 16 + koff;
                ldsm4(sptr(Kh + n * 72 + cc), bH);
                ldsm4(sptr(Kl + n * 72 + cc), bL);
#pragma unroll
                for (int j = 0; j < 2; ++j) {
                    const int nt = np * 2 + j;
                    mma_bf16(acc[nt], aH, bH[2 * j], bH[2 * j + 1]);
                    mma_bf16(acc[nt], aH, bL[2 * j], bL[2 * j + 1]);
                    mma_bf16(acc[nt], aL, bH[2 * j], bH[2 * j + 1]);
                }
            }
        }

        const bool need_mask = (kt * 64 + 63) > (q0 + wrow);

#pragma unroll
        for (int t = 0; t < 4; ++t) {
            uint32_t pH[4], pL[4];
#pragma unroll
            for (int g = 0; g < 2; ++g) {
                const int nt = 2 * t + g;
                const int kc = kt * 64 + nt * 8 + ((lane & 3) << 1);
#pragma unroll
                for (int hf = 0; hf < 2; ++hf) {
                    const int qr = q0 + wrow + lrow + hf * 8;
                    float x0 = acc[nt][hf * 2] * 0.125f;
                    float x1 = acc[nt][hf * 2 + 1] * 0.125f;
                    if (need_mask) {
                        if (kc > qr)     x0 = -1e30f;
                        if (kc + 1 > qr) x1 = -1e30f;
                    }
                    const float e0 = __expf(x0);
                    const float e1 = __expf(x1);
                    lsum[hf] += e0 + e1;
                    float* dst = attn + ((size_t)bh * S_ + qr) * S_ + kc;
                    *(float2*)dst = make_float2(e0, e1);
                    const uint32_t hpk = pack_bf16(e0, e1);
                    __nv_bfloat162 hb = *(__nv_bfloat162*)&hpk;
                    pH[g * 2 + hf] = hpk;
                    pL[g * 2 + hf] = pack_bf16(e0 - __bfloat162float(hb.x),
                                               e1 - __bfloat162float(hb.y));
                }
            }
#pragma unroll
            for (int np = 0; np < 4; ++np) {
                uint32_t bH[4], bL[4];
                const int kr = t * 16 + koff + nr;
                const int nc = np * 16 + nb;
                ldsm4t(sptr(Vh + kr * 72 + nc), bH);
                ldsm4t(sptr(Vl + kr * 72 + nc), bL);
#pragma unroll
                for (int j = 0; j < 2; ++j) {
                    const int nt = np * 2 + j;
                    mma_bf16(accO[nt], pH, bH[2 * j], bH[2 * j + 1]);
                    mma_bf16(accO[nt], pH, bL[2 * j], bL[2 * j + 1]);
                    mma_bf16(accO[nt], pL, bH[2 * j], bH[2 * j + 1]);
                }
            }
        }
        __syncthreads();
    }
#undef AT_LOADKV

    float il[2];
#pragma unroll
    for (int hf = 0; hf < 2; ++hf) {
        float l = lsum[hf];
#pragma unroll
        for (int off = 1; off <= 2; off <<= 1)
            l += __shfl_xor_sync(0xffffffffu, l, off);
        il[hf] = 1.f / l;
    }

    if ((lane & 3) == 0) {
        g_linv[(size_t)bh * S_ + q0 + wrow + lrow]     = il[0];
        g_linv[(size_t)bh * S_ + q0 + wrow + lrow + 8] = il[1];
    }

    const int b = bh >> 4, h = bh & (H_ - 1);
#pragma unroll
    for (int nt = 0; nt < 8; ++nt) {
        const int d = h * DK_ + nt * 8 + ((lane & 3) << 1);
#pragma unroll
        for (int hf = 0; hf < 2; ++hf) {
            const int s = q0 + wrow + lrow + hf * 8;
            const float ii = il[hf];
            const float x0 = accO[nt][hf * 2] * ii;
            const float x1 = accO[nt][hf * 2 + 1] * ii;
            const size_t o = ((size_t)b * S_ + s) * D_ + d;
            __nv_bfloat162 phh, pll;
            phh.x = __float2bfloat16(x0); phh.y = __float2bfloat16(x1);
            pll.x = __float2bfloat16(x0 - __bfloat162float(phh.x));
            pll.y = __float2bfloat16(x1 - __bfloat162float(phh.y));
            *(__nv_bfloat162*)(g_Chi + o) = phh;
            *(__nv_bfloat162*)(g_Clo + o) = pll;
        }
    }
}

// ---------------------------------------------------------------------------
// zero_fill: attn[row, c] = 0 for c >= (qt+1)*128. No data deps.
// ---------------------------------------------------------------------------
__global__ __launch_bounds__(256) void zero_fill(float* __restrict__ attn)
{
    const int row = blockIdx.x;                  // 0..1919 (tiles 0..14)
    const int bh = blockIdx.y;
    const int c0 = ((row >> 7) + 1) * 128;
    float* p = attn + ((size_t)bh * S_ + row) * S_;
    const int tid = threadIdx.x;
    const float4 z = make_float4(0.f, 0.f, 0.f, 0.f);
    for (int i = (c0 >> 2) + tid; i < S_ / 4; i += 256)
        ((float4*)p)[i] = z;
}

// ---------------------------------------------------------------------------
// scale_rows: attn[row, c] *= linv for c < (qt+1)*128. row = row_off + bx.
// ---------------------------------------------------------------------------
__global__ __launch_bounds__(256) void scale_rows(float* __restrict__ attn,
                                                  int row_off)
{
    const int row = row_off + blockIdx.x;
    const int bh = blockIdx.y;
    const float s = g_linv[(size_t)bh * S_ + row];
    float* p = attn + ((size_t)bh * S_ + row) * S_;
    const int n4 = ((row >> 7) + 1) * 32;
    const int tid = threadIdx.x;
    for (int i = tid; i < n4; i += 256) {
        float4 v = ((const float4*)p)[i];
        v.x *= s; v.y *= s; v.z *= s; v.w *= s;
        ((float4*)p)[i] = v;
    }
}

// ---------------------------------------------------------------------------
// Launch. Pipeline: attn split big/small; scale of big rows overlaps small-tile
// attention; scale of small rows overlaps out-proj; zero_fill from t=0.
// ---------------------------------------------------------------------------
extern "C" void kernel_launch(void* const* d_in, const int* in_sizes, int n_in,
                              void* d_out, int out_size)
{
    const float* q = (const float*)d_in[0];
    const float* k = (const float*)d_in[1];
    const float* v = (const float*)d_in[2];
    const float* W[4] = { (const float*)d_in[4], (const float*)d_in[5],
                          (const float*)d_in[6], (const float*)d_in[7] };

    float* out  = (float*)d_out;
    float* attn = out + (size_t)B_ * S_ * D_;

    __nv_bfloat16 *qhi, *qlo, *khi, *klo, *vhi, *vlo, *whi, *wlo;
    __nv_bfloat16 *Qhi, *Qlo, *Khi, *Klo, *Vhi, *Vlo, *Chi, *Clo;
    cudaGetSymbolAddress((void**)&qhi, g_qhi); cudaGetSymbolAddress((void**)&qlo, g_qlo);
    cudaGetSymbolAddress((void**)&khi, g_khi); cudaGetSymbolAddress((void**)&klo, g_klo);
    cudaGetSymbolAddress((void**)&vhi, g_vhi); cudaGetSymbolAddress((void**)&vlo, g_vlo);
    cudaGetSymbolAddress((void**)&whi, g_whi); cudaGetSymbolAddress((void**)&wlo, g_wlo);
    cudaGetSymbolAddress((void**)&Qhi, g_Qhi); cudaGetSymbolAddress((void**)&Qlo, g_Qlo);
    cudaGetSymbolAddress((void**)&Khi, g_Khi); cudaGetSymbolAddress((void**)&Klo, g_Klo);
    cudaGetSymbolAddress((void**)&Vhi, g_Vhi); cudaGetSymbolAddress((void**)&Vlo, g_Vlo);
    cudaGetSymbolAddress((void**)&Chi, g_Chi); cudaGetSymbolAddress((void**)&Clo, g_Clo);

    static cudaStream_t s_side = nullptr;
    static cudaEvent_t evFork0 = nullptr, evFork1 = nullptr, evFork2 = nullptr,
                       evJoin = nullptr;
    static bool attr_set = false;
    if (!attr_set) {
        cudaFuncSetAttribute(mm_tc<0>, cudaFuncAttributeMaxDynamicSharedMemorySize, 81920);
        cudaFuncSetAttribute(mm_tc<1>, cudaFuncAttributeMaxDynamicSharedMemorySize, 81920);
        cudaFuncSetAttribute(attn_single, cudaFuncAttributeMaxDynamicSharedMemorySize, 110592);
        cudaStreamCreateWithFlags(&s_side, cudaStreamNonBlocking);
        cudaEventCreateWithFlags(&evFork0, cudaEventDisableTiming);
        cudaEventCreateWithFlags(&evFork1, cudaEventDisableTiming);
        cudaEventCreateWithFlags(&evFork2, cudaEventDisableTiming);
        cudaEventCreateWithFlags(&evJoin, cudaEventDisableTiming);
        attr_set = true;
    }

    const int n4x = MM_ * D_ / 4;
    const int n4w = D_ * D_ / 4;

    // fork 0: zero-fill (no data deps) on side stream from t=0
    cudaEventRecord(evFork0, 0);
    cudaStreamWaitEvent(s_side, evFork0, 0);
    dim3 gZF(15 * 128, B_ * H_);
    zero_fill<<<gZF, 256, 0, s_side>>>(attn);

    dim3 gSa((n4x + 255) / 256, 3);
    split_acts<<<gSa, 256>>>(q, k, v, qhi, qlo, khi, klo, vhi, vlo, n4x);
    dim3 gSw((n4w + 255) / 256, 4);
    split_wts4<<<gSw, 256>>>(W[0], W[1], W[2], W[3], whi, wlo, n4w);

    dim3 gQKV(24, MM_ / 128);       // (24, 64)
    mm_tc<1><<<gQKV, 256, 81920>>>(qhi, qlo, khi, klo, vhi, vlo, whi, wlo,
                                   nullptr, Qhi, Qlo, Khi, Klo, Vhi, Vlo);

    // attention part A: big tiles qt 8..15 (3/4 of MMA work, rows 1024..2047)
    dim3 gA(8, B_ * H_);
    attn_single<<<gA, 256, 110592>>>(attn, 8);

    // fork 1: scale rows 1024..2047 on side while small tiles run on main
    cudaEventRecord(evFork1, 0);
    cudaStreamWaitEvent(s_side, evFork1, 0);
    dim3 gSRa(1024, B_ * H_);
    scale_rows<<<gSRa, 256, 0, s_side>>>(attn, 1024);

    // attention part B: small tiles qt 0..7
    attn_single<<<gA, 256, 110592>>>(attn, 0);

    // fork 2: scale rows 0..1023 on side while out-proj runs on main
    cudaEventRecord(evFork2, 0);
    cudaStreamWaitEvent(s_side, evFork2, 0);
    dim3 gSRb(1024, B_ * H_);
    scale_rows<<<gSRb, 256, 0, s_side>>>(attn, 0);

    dim3 gO(8, MM_ / 128);          // (8, 64)
    mm_tc<0><<<gO, 256, 81920>>>(Chi, Clo, nullptr, nullptr, nullptr, nullptr,
                                 whi + 3 * (size_t)D_ * D_, wlo + 3 * (size_t)D_ * D_,
                                 out, nullptr, nullptr, nullptr, nullptr, nullptr, nullptr);

    // join
    cudaEventRecord(evJoin, s_side);
    cudaStreamWaitEvent(0, evJoin, 0);
}

// round 14
// speedup vs baseline: 3.4192x; 1.1606x over previous
#include <cuda_runtime.h>
#include <cuda_bf16.h>
#include <cuda_fp16.h>
#include <cstdint>

#define B_  4
#define S_  2048
#define D_  1024
#define H_  16
#define DK_ 64
#define MM_ (B_ * S_)          // 8192

// ---------------------------------------------------------------------------
// Scratch (device globals)
// ---------------------------------------------------------------------------
__device__ __half g_q16[MM_ * D_], g_k16[MM_ * D_], g_v16[MM_ * D_];
__device__ __half g_w16h[4][D_ * D_], g_w16l[4][D_ * D_];
__device__ __half g_C16[MM_ * D_];                            // context [B,S,D]
__device__ __nv_bfloat16 g_Qhi[MM_ * D_], g_Qlo[MM_ * D_];    // [B,H,S,DK]
__device__ __nv_bfloat16 g_Khi[MM_ * D_], g_Klo[MM_ * D_];
__device__ __nv_bfloat16 g_Vhi[MM_ * D_], g_Vlo[MM_ * D_];
__device__ float g_linv[B_ * H_ * S_];                        // 1/rowsum

// ---------------------------------------------------------------------------
// PTX helpers
// ---------------------------------------------------------------------------
__device__ __forceinline__ void ldsm4(uint32_t addr, uint32_t* r) {
    asm volatile("ldmatrix.sync.aligned.m8n8.x4.shared.b16 {%0,%1,%2,%3}, [%4];"
        : "=r"(r[0]), "=r"(r[1]), "=r"(r[2]), "=r"(r[3]) : "r"(addr));
}
__device__ __forceinline__ void ldsm4t(uint32_t addr, uint32_t* r) {
    asm volatile("ldmatrix.sync.aligned.m8n8.x4.trans.shared.b16 {%0,%1,%2,%3}, [%4];"
        : "=r"(r[0]), "=r"(r[1]), "=r"(r[2]), "=r"(r[3]) : "r"(addr));
}
__device__ __forceinline__ void mma_bf16(float* c, const uint32_t* a, uint32_t b0, uint32_t b1) {
    asm volatile("mma.sync.aligned.m16n8k16.row.col.f32.bf16.bf16.f32 "
        "{%0,%1,%2,%3}, {%4,%5,%6,%7}, {%8,%9}, {%0,%1,%2,%3};"
        : "+f"(c[0]), "+f"(c[1]), "+f"(c[2]), "+f"(c[3])
        : "r"(a[0]), "r"(a[1]), "r"(a[2]), "r"(a[3]), "r"(b0), "r"(b1));
}
__device__ __forceinline__ void mma_f16(float* c, const uint32_t* a, uint32_t b0, uint32_t b1) {
    asm volatile("mma.sync.aligned.m16n8k16.row.col.f32.f16.f16.f32 "
        "{%0,%1,%2,%3}, {%4,%5,%6,%7}, {%8,%9}, {%0,%1,%2,%3};"
        : "+f"(c[0]), "+f"(c[1]), "+f"(c[2]), "+f"(c[3])
        : "r"(a[0]), "r"(a[1]), "r"(a[2]), "r"(a[3]), "r"(b0), "r"(b1));
}
__device__ __forceinline__ uint32_t sptr(const void* p) {
    return (uint32_t)__cvta_generic_to_shared(p);
}
__device__ __forceinline__ void cpa16(uint32_t s, const void* g) {
    asm volatile("cp.async.cg.shared.global [%0], [%1], 16;" :: "r"(s), "l"(g));
}
#define CPA_COMMIT() asm volatile("cp.async.commit_group;" ::: "memory")
#define CPA_WAIT(n)  asm volatile("cp.async.wait_group %0;" :: "n"(n) : "memory")
__device__ __forceinline__ uint32_t pack_bf16(float x, float y) {
    __nv_bfloat162 t; t.x = __float2bfloat16(x); t.y = __float2bfloat16(y);
    return *(uint32_t*)&t;
}

// ---------------------------------------------------------------------------
// Splits
// ---------------------------------------------------------------------------
__global__ __launch_bounds__(256) void split_a16(
    const float* q, const float* k, const float* v,
    __half* q16, __half* k16, __half* v16, int n4)
{
    int i = blockIdx.x * blockDim.x + threadIdx.x;
    if (i >= n4) return;
    const int z = blockIdx.y;
    const float* x = (z == 0) ? q : (z == 1) ? k : v;
    __half* o = (z == 0) ? q16 : (z == 1) ? k16 : v16;
    float4 val = ((const float4*)x)[i];
    ((__half2*)o)[2 * i]     = __floats2half2_rn(val.x, val.y);
    ((__half2*)o)[2 * i + 1] = __floats2half2_rn(val.z, val.w);
}

__global__ __launch_bounds__(256) void split_w16(
    const float* w0, const float* w1, const float* w2, const float* w3,
    __half* hi, __half* lo, int n4)
{
    int i = blockIdx.x * blockDim.x + threadIdx.x;
    if (i >= n4) return;
    const int z = blockIdx.y;
    const float* x = (z == 0) ? w0 : (z == 1) ? w1 : (z == 2) ? w2 : w3;
    __half* ho = hi + (size_t)z * D_ * D_;
    __half* lo_ = lo + (size_t)z * D_ * D_;
    float4 v = ((const float4*)x)[i];
    __half h0 = __float2half_rn(v.x), h1 = __float2half_rn(v.y);
    __half h2 = __float2half_rn(v.z), h3 = __float2half_rn(v.w);
    __half2 ph0; ph0.x = h0; ph0.y = h1;
    __half2 ph1; ph1.x = h2; ph1.y = h3;
    __half2 pl0, pl1;
    pl0.x = __float2half_rn(v.x - __half2float(h0));
    pl0.y = __float2half_rn(v.y - __half2float(h1));
    pl1.x = __float2half_rn(v.z - __half2float(h2));
    pl1.y = __float2half_rn(v.w - __half2float(h3));
    ((__half2*)ho)[2 * i]      = ph0;
    ((__half2*)ho)[2 * i + 1]  = ph1;
    ((__half2*)lo_)[2 * i]     = pl0;
    ((__half2*)lo_)[2 * i + 1] = pl1;
}

// ---------------------------------------------------------------------------
// fp16 2-product GEMM: C = A @ W^T, A single fp16, W = Wh + Wl fp16.
// 128x128 tile, BK=32, 256 thr, 2 CTAs/SM.
// smem/stage: A 5120, Wh 5120, Wl 5120 halves; 2 stages = 61440 B.
// MODE 1: merged QKV (grid.x=24); out = bf16 hi/lo split-head (for attention).
// MODE 0: out-proj; out fp32 row-major.
// ---------------------------------------------------------------------------
template <int MODE>
__global__ __launch_bounds__(256, 2) void mm_tc(
    const __half* __restrict__ A0, const __half* __restrict__ A1,
    const __half* __restrict__ A2,
    const __half* __restrict__ Wbh, const __half* __restrict__ Wbl,
    float* __restrict__ Cf,
    __nv_bfloat16* __restrict__ O0h, __nv_bfloat16* __restrict__ O0l,
    __nv_bfloat16* __restrict__ O1h, __nv_bfloat16* __restrict__ O1l,
    __nv_bfloat16* __restrict__ O2h, __nv_bfloat16* __restrict__ O2l)
{
    extern __shared__ __half dsm[];

    const int tid = threadIdx.x, lane = tid & 31, wid = tid >> 5;
    const int wsel = (MODE == 1) ? (blockIdx.x >> 3) : 0;
    const int bn = (MODE == 1) ? ((blockIdx.x & 7) * 128) : (blockIdx.x * 128);
    const int bm = blockIdx.y * 128;
    const int wm = (wid >> 2) * 64, wn = (wid & 3) * 32;

    const __half* A = (wsel == 0) ? A0 : (wsel == 1) ? A1 : A2;
    const __half* Whi = Wbh + (size_t)wsel * D_ * D_;
    const __half* Wlo = Wbl + (size_t)wsel * D_ * D_;
    __nv_bfloat16* Ohi = (wsel == 0) ? O0h : (wsel == 1) ? O1h : O2h;
    __nv_bfloat16* Olo = (wsel == 0) ? O0l : (wsel == 1) ? O1l : O2l;

    float acc[4][4][4];
#pragma unroll
    for (int a = 0; a < 4; ++a)
#pragma unroll
        for (int b = 0; b < 4; ++b)
#pragma unroll
            for (int c = 0; c < 4; ++c) acc[a][b][c] = 0.f;

    const int grp = lane >> 3, koff = (grp & 1) << 3, nb = (grp >> 1) << 3, nr = lane & 7;

#define MM_LOAD(it, st) do {                                                     \
    const int _k0 = (it) * 32;                                                   \
    __half* _bb = dsm + (st) * 15360;                                            \
    _Pragma("unroll")                                                            \
    for (int _t = 0; _t < 2; ++_t) {                                             \
        const int _idx = tid + _t * 256;                                         \
        const int _row = _idx >> 2, _c8 = (_idx & 3) << 3;                       \
        const int _so = _row * 40 + _c8;                                         \
        cpa16(sptr(_bb + _so),         A   + (size_t)(bm + _row) * D_ + _k0 + _c8); \
        cpa16(sptr(_bb + 5120 + _so),  Whi + (size_t)(bn + _row) * D_ + _k0 + _c8); \
        cpa16(sptr(_bb + 10240 + _so), Wlo + (size_t)(bn + _row) * D_ + _k0 + _c8); \
    } } while (0)

    MM_LOAD(0, 0); CPA_COMMIT();

    for (int it = 0; it < 32; ++it) {
        if (it + 1 < 32) { MM_LOAD(it + 1, (it + 1) & 1); CPA_COMMIT(); CPA_WAIT(1); }
        else             { CPA_WAIT(0); }
        __syncthreads();

        const __half* sA  = dsm + (it & 1) * 15360;
        const __half* sWh = sA + 5120;
        const __half* sWl = sA + 10240;

#pragma unroll
        for (int kk = 0; kk < 2; ++kk) {
            uint32_t aF[4][4];
#pragma unroll
            for (int mt = 0; mt < 4; ++mt) {
                const int r = wm + mt * 16 + (lane & 15);
                const int c = kk * 16 + ((lane >> 4) << 3);
                ldsm4(sptr(sA + r * 40 + c), aF[mt]);
            }
#pragma unroll
            for (int np = 0; np < 2; ++np) {
                uint32_t bH[4], bL[4];
                const int n = wn + np * 16 + nb + nr;
                const int c = kk * 16 + koff;
                ldsm4(sptr(sWh + n * 40 + c), bH);
                ldsm4(sptr(sWl + n * 40 + c), bL);
#pragma unroll
                for (int mt = 0; mt < 4; ++mt)
#pragma unroll
                    for (int j = 0; j < 2; ++j) {
                        const int nt = np * 2 + j;
                        mma_f16(acc[mt][nt], aF[mt], bH[2 * j], bH[2 * j + 1]);
                        mma_f16(acc[mt][nt], aF[mt], bL[2 * j], bL[2 * j + 1]);
                    }
            }
        }
        __syncthreads();
    }
#undef MM_LOAD

#pragma unroll
    for (int mt = 0; mt < 4; ++mt)
#pragma unroll
        for (int nt = 0; nt < 4; ++nt) {
            const float* c = acc[mt][nt];
            const int n = bn + wn + nt * 8 + ((lane & 3) << 1);
#pragma unroll
            for (int hf = 0; hf < 2; ++hf) {
                const int m = bm + wm + mt * 16 + (lane >> 2) + hf * 8;
                const float x0 = c[hf * 2], x1 = c[hf * 2 + 1];
                if (MODE == 0) {
                    *(float2*)(Cf + (size_t)m * D_ + n) = make_float2(x0, x1);
                } else {
                    const int b = m >> 11, s = m & (S_ - 1);
                    const int h = n >> 6, dk = n & (DK_ - 1);
                    const size_t o = (((size_t)(b * H_ + h) * S_ + s) << 6) + dk;
                    __nv_bfloat16 h0 = __float2bfloat16(x0), h1 = __float2bfloat16(x1);
                    __nv_bfloat162 ph; ph.x = h0; ph.y = h1;
                    __nv_bfloat162 pl;
                    pl.x = __float2bfloat16(x0 - __bfloat162float(h0));
                    pl.y = __float2bfloat16(x1 - __bfloat162float(h1));
                    *(__nv_bfloat162*)(Ohi + o) = ph;
                    *(__nv_bfloat162*)(Olo + o) = pl;
                }
            }
        }
}

// ---------------------------------------------------------------------------
// Single-pass attention (bf16x3, unchanged math), q-tile 128, 2 CTAs/SM.
// Context written as SINGLE fp16 to g_C16 (out-proj is 2-product fp16).
// ---------------------------------------------------------------------------
__global__ __launch_bounds__(256, 2) void attn_single(float* __restrict__ attn,
                                                      int qt_base)
{
    extern __shared__ __nv_bfloat16 sm[];
    __nv_bfloat16* Qh = sm;
    __nv_bfloat16* Ql = sm + 9216;

    const int qt = qt_base + (int)gridDim.x - 1 - (int)blockIdx.x;
    const int bh = blockIdx.y;
    const int tid = threadIdx.x, lane = tid & 31, wid = tid >> 5;
    const int q0 = qt * 128;
    const int nkt = 2 * qt + 2;
    const int grp = lane >> 3, koff = (grp & 1) << 3, nb = (grp >> 1) << 3, nr = lane & 7;
    const int wrow = wid * 16;

#pragma unroll
    for (int t = 0; t < 8; ++t) {
        const int idx = tid + t * 256;
        const int buf = idx >> 10;
        const int r = (idx >> 3) & 127, c8 = (idx & 7) << 3;
        const __nv_bfloat16* src = buf ? g_Qlo : g_Qhi;
        __nv_bfloat16* dst = buf ? Ql : Qh;
        *(uint4*)&dst[r * 72 + c8] =
            *(const uint4*)(src + (((size_t)bh * S_ + q0 + r) << 6) + c8);
    }

    const int lrow = lane >> 2;

#define AT_LOADKV(kt, st) do {                                                   \
    __nv_bfloat16* _bb = sm + 18432 + (st) * 18432;                              \
    _Pragma("unroll")                                                            \
    for (int _t = 0; _t < 2; ++_t) {                                             \
        const int _idx = tid + _t * 256;                                         \
        const int _r = _idx >> 3, _c8 = (_idx & 7) << 3;                         \
        const size_t _g = (((size_t)bh * S_ + (kt) * 64 + _r) << 6) + _c8;       \
        const int _so = _r * 72 + _c8;                                           \
        cpa16(sptr(_bb + _so),         g_Khi + _g);                              \
        cpa16(sptr(_bb + 4608 + _so),  g_Klo + _g);                              \
        cpa16(sptr(_bb + 9216 + _so),  g_Vhi + _g);                              \
        cpa16(sptr(_bb + 13824 + _so), g_Vlo + _g);                              \
    } } while (0)

    float accO[8][4];
#pragma unroll
    for (int b = 0; b < 8; ++b)
#pragma unroll
        for (int c = 0; c < 4; ++c) accO[b][c] = 0.f;
    float lsum[2] = {0.f, 0.f};

    AT_LOADKV(0, 0); CPA_COMMIT();
    for (int kt = 0; kt < nkt; ++kt) {
        if (kt + 1 < nkt) { AT_LOADKV(kt + 1, (kt + 1) & 1); CPA_COMMIT(); CPA_WAIT(1); }
        else              { CPA_WAIT(0); }
        __syncthreads();

        const __nv_bfloat16* Kh = sm + 18432 + (kt & 1) * 18432;
        const __nv_bfloat16* Kl = Kh + 4608;
        const __nv_bfloat16* Vh = Kh + 9216;
        const __nv_bfloat16* Vl = Kh + 13824;

        float acc[8][4];
#pragma unroll
        for (int b = 0; b < 8; ++b)
#pragma unroll
            for (int c = 0; c < 4; ++c) acc[b][c] = 0.f;

#pragma unroll
        for (int kk = 0; kk < 4; ++kk) {
            uint32_t aH[4], aL[4];
            {
                const int r = wrow + (lane & 15);
                const int c = kk * 16 + ((lane >> 4) << 3);
                ldsm4(sptr(Qh + r * 72 + c), aH);
                ldsm4(sptr(Ql + r * 72 + c), aL);
            }
#pragma unroll
            for (int np = 0; np < 4; ++np) {
                uint32_t bH[4], bL[4];
                const int n = np * 16 + nb + nr;
                const int cc = kk * 16 + koff;
                ldsm4(sptr(Kh + n * 72 + cc), bH);
                ldsm4(sptr(Kl + n * 72 + cc), bL);
#pragma unroll
                for (int j = 0; j < 2; ++j) {
                    const int nt = np * 2 + j;
                    mma_bf16(acc[nt], aH, bH[2 * j], bH[2 * j + 1]);
                    mma_bf16(acc[nt], aH, bL[2 * j], bL[2 * j + 1]);
                    mma_bf16(acc[nt], aL, bH[2 * j], bH[2 * j + 1]);
                }
            }
        }

        const bool need_mask = (kt * 64 + 63) > (q0 + wrow);

#pragma unroll
        for (int t = 0; t < 4; ++t) {
            uint32_t pH[4], pL[4];
#pragma unroll
            for (int g = 0; g < 2; ++g) {
                const int nt = 2 * t + g;
                const int kc = kt * 64 + nt * 8 + ((lane & 3) << 1);
#pragma unroll
                for (int hf = 0; hf < 2; ++hf) {
                    const int qr = q0 + wrow + lrow + hf * 8;
                    float x0 = acc[nt][hf * 2] * 0.125f;
                    float x1 = acc[nt][hf * 2 + 1] * 0.125f;
                    if (need_mask) {
                        if (kc > qr)     x0 = -1e30f;
                        if (kc + 1 > qr) x1 = -1e30f;
                    }
                    const float e0 = __expf(x0);
                    const float e1 = __expf(x1);
                    lsum[hf] += e0 + e1;
                    float* dst = attn + ((size_t)bh * S_ + qr) * S_ + kc;
                    *(float2*)dst = make_float2(e0, e1);
                    const uint32_t hpk = pack_bf16(e0, e1);
                    __nv_bfloat162 hb = *(__nv_bfloat162*)&hpk;
                    pH[g * 2 + hf] = hpk;
                    pL[g * 2 + hf] = pack_bf16(e0 - __bfloat162float(hb.x),
                                               e1 - __bfloat162float(hb.y));
                }
            }
#pragma unroll
            for (int np = 0; np < 4; ++np) {
                uint32_t bH[4], bL[4];
                const int kr = t * 16 + koff + nr;
                const int nc = np * 16 + nb;
                ldsm4t(sptr(Vh + kr * 72 + nc), bH);
                ldsm4t(sptr(Vl + kr * 72 + nc), bL);
#pragma unroll
                for (int j = 0; j < 2; ++j) {
                    const int nt = np * 2 + j;
                    mma_bf16(accO[nt], pH, bH[2 * j], bH[2 * j + 1]);
                    mma_bf16(accO[nt], pH, bL[2 * j], bL[2 * j + 1]);
                    mma_bf16(accO[nt], pL, bH[2 * j], bH[2 * j + 1]);
                }
            }
        }
        __syncthreads();
    }
#undef AT_LOADKV

    float il[2];
#pragma unroll
    for (int hf = 0; hf < 2; ++hf) {
        float l = lsum[hf];
#pragma unroll
        for (int off = 1; off <= 2; off <<= 1)
            l += __shfl_xor_sync(0xffffffffu, l, off);
        il[hf] = 1.f / l;
    }

    if ((lane & 3) == 0) {
        g_linv[(size_t)bh * S_ + q0 + wrow + lrow]     = il[0];
        g_linv[(size_t)bh * S_ + q0 + wrow + lrow + 8] = il[1];
    }

    // ---- write O = accO / l as single fp16 to g_C16 [B,S,D] ----
    const int b = bh >> 4, h = bh & (H_ - 1);
#pragma unroll
    for (int nt = 0; nt < 8; ++nt) {
        const int d = h * DK_ + nt * 8 + ((lane & 3) << 1);
#pragma unroll
        for (int hf = 0; hf < 2; ++hf) {
            const int s = q0 + wrow + lrow + hf * 8;
            const float ii = il[hf];
            const size_t o = ((size_t)b * S_ + s) * D_ + d;
            *(__half2*)(g_C16 + o) =
                __floats2half2_rn(accO[nt][hf * 2] * ii, accO[nt][hf * 2 + 1] * ii);
        }
    }
}

// ---------------------------------------------------------------------------
// zero_fill: attn[row, c] = 0 for c >= (qt+1)*128. No data deps.
// ---------------------------------------------------------------------------
__global__ __launch_bounds__(256) void zero_fill(float* __restrict__ attn)
{
    const int row = blockIdx.x;                  // 0..1919 (tiles 0..14)
    const int bh = blockIdx.y;
    const int c0 = ((row >> 7) + 1) * 128;
    float* p = attn + ((size_t)bh * S_ + row) * S_;
    const int tid = threadIdx.x;
    const float4 z = make_float4(0.f, 0.f, 0.f, 0.f);
    for (int i = (c0 >> 2) + tid; i < S_ / 4; i += 256)
        ((float4*)p)[i] = z;
}

// ---------------------------------------------------------------------------
// scale_rows: attn[row, c] *= linv for c < (qt+1)*128. row = row_off + bx.
// ---------------------------------------------------------------------------
__global__ __launch_bounds__(256) void scale_rows(float* __restrict__ attn,
                                                  int row_off)
{
    const int row = row_off + blockIdx.x;
    const int bh = blockIdx.y;
    const float s = g_linv[(size_t)bh * S_ + row];
    float* p = attn + ((size_t)bh * S_ + row) * S_;
    const int n4 = ((row >> 7) + 1) * 32;
    const int tid = threadIdx.x;
    for (int i = tid; i < n4; i += 256) {
        float4 v = ((const float4*)p)[i];
        v.x *= s; v.y *= s; v.z *= s; v.w *= s;
        ((float4*)p)[i] = v;
    }
}

// ---------------------------------------------------------------------------
// Launch (pipeline structure unchanged from R13)
// ---------------------------------------------------------------------------
extern "C" void kernel_launch(void* const* d_in, const int* in_sizes, int n_in,
                              void* d_out, int out_size)
{
    const float* q = (const float*)d_in[0];
    const float* k = (const float*)d_in[1];
    const float* v = (const float*)d_in[2];
    const float* W[4] = { (const float*)d_in[4], (const float*)d_in[5],
                          (const float*)d_in[6], (const float*)d_in[7] };

    float* out  = (float*)d_out;
    float* attn = out + (size_t)B_ * S_ * D_;

    __half *q16, *k16, *v16, *w16h, *w16l, *C16;
    __nv_bfloat16 *Qhi, *Qlo, *Khi, *Klo, *Vhi, *Vlo;
    cudaGetSymbolAddress((void**)&q16, g_q16);
    cudaGetSymbolAddress((void**)&k16, g_k16);
    cudaGetSymbolAddress((void**)&v16, g_v16);
    cudaGetSymbolAddress((void**)&w16h, g_w16h);
    cudaGetSymbolAddress((void**)&w16l, g_w16l);
    cudaGetSymbolAddress((void**)&C16, g_C16);
    cudaGetSymbolAddress((void**)&Qhi, g_Qhi); cudaGetSymbolAddress((void**)&Qlo, g_Qlo);
    cudaGetSymbolAddress((void**)&Khi, g_Khi); cudaGetSymbolAddress((void**)&Klo, g_Klo);
    cudaGetSymbolAddress((void**)&Vhi, g_Vhi); cudaGetSymbolAddress((void**)&Vlo, g_Vlo);

    static cudaStream_t s_side = nullptr;
    static cudaEvent_t evFork0 = nullptr, evFork1 = nullptr, evFork2 = nullptr,
                       evJoin = nullptr;
    static bool attr_set = false;
    if (!attr_set) {
        cudaFuncSetAttribute(mm_tc<0>, cudaFuncAttributeMaxDynamicSharedMemorySize, 61440);
        cudaFuncSetAttribute(mm_tc<1>, cudaFuncAttributeMaxDynamicSharedMemorySize, 61440);
        cudaFuncSetAttribute(attn_single, cudaFuncAttributeMaxDynamicSharedMemorySize, 110592);
        cudaStreamCreateWithFlags(&s_side, cudaStreamNonBlocking);
        cudaEventCreateWithFlags(&evFork0, cudaEventDisableTiming);
        cudaEventCreateWithFlags(&evFork1, cudaEventDisableTiming);
        cudaEventCreateWithFlags(&evFork2, cudaEventDisableTiming);
        cudaEventCreateWithFlags(&evJoin, cudaEventDisableTiming);
        attr_set = true;
    }

    const int n4x = MM_ * D_ / 4;
    const int n4w = D_ * D_ / 4;

    // fork 0: zero-fill (no data deps) on side stream from t=0
    cudaEventRecord(evFork0, 0);
    cudaStreamWaitEvent(s_side, evFork0, 0);
    dim3 gZF(15 * 128, B_ * H_);
    zero_fill<<<gZF, 256, 0, s_side>>>(attn);

    dim3 gSa((n4x + 255) / 256, 3);
    split_a16<<<gSa, 256>>>(q, k, v, q16, k16, v16, n4x);
    dim3 gSw((n4w + 255) / 256, 4);
    split_w16<<<gSw, 256>>>(W[0], W[1], W[2], W[3], w16h, w16l, n4w);

    dim3 gQKV(24, MM_ / 128);       // (24, 64)
    mm_tc<1><<<gQKV, 256, 61440>>>(q16, k16, v16, w16h, w16l,
                                   nullptr, Qhi, Qlo, Khi, Klo, Vhi, Vlo);

    // attention part A: big tiles qt 8..15
    dim3 gA(8, B_ * H_);
    attn_single<<<gA, 256, 110592>>>(attn, 8);

    // fork 1: scale rows 1024..2047 on side while small tiles run on main
    cudaEventRecord(evFork1, 0);
    cudaStreamWaitEvent(s_side, evFork1, 0);
    dim3 gSRa(1024, B_ * H_);
    scale_rows<<<gSRa, 256, 0, s_side>>>(attn, 1024);

    // attention part B: small tiles qt 0..7
    attn_single<<<gA, 256, 110592>>>(attn, 0);

    // fork 2: scale rows 0..1023 on side while out-proj runs on main
    cudaEventRecord(evFork2, 0);
    cudaStreamWaitEvent(s_side, evFork2, 0);
    dim3 gSRb(1024, B_ * H_);
    scale_rows<<<gSRb, 256, 0, s_side>>>(attn, 0);

    dim3 gO(8, MM_ / 128);          // (8, 64)
    mm_tc<0><<<gO, 256, 61440>>>(C16, nullptr, nullptr,
                                 w16h + 3 * (size_t)D_ * D_, w16l + 3 * (size_t)D_ * D_,
                                 out, nullptr, nullptr, nullptr, nullptr, nullptr, nullptr);

    // join
    cudaEventRecord(evJoin, s_side);
    cudaStreamWaitEvent(0, evJoin, 0);
}

// round 16
// speedup vs baseline: 3.7726x; 1.1033x over previous
#include <cuda_runtime.h>
#include <cuda_bf16.h>
#include <cuda_fp16.h>
#include <cstdint>

#define B_  4
#define S_  2048
#define D_  1024
#define H_  16
#define DK_ 64
#define MM_ (B_ * S_)          // 8192

// ---------------------------------------------------------------------------
// Scratch (device globals)
// ---------------------------------------------------------------------------
__device__ __half g_q16[MM_ * D_], g_k16[MM_ * D_], g_v16[MM_ * D_];
__device__ __half g_w16h[4][D_ * D_], g_w16l[4][D_ * D_];
__device__ __half g_C16[MM_ * D_];                            // context [B,S,D]
__device__ __half g_Q16[MM_ * D_];                            // [B,H,S,DK] single
__device__ __half g_K16h[MM_ * D_], g_K16l[MM_ * D_];         // [B,H,S,DK] hi/lo
__device__ __half g_V16h[MM_ * D_], g_V16l[MM_ * D_];
__device__ float g_linv[B_ * H_ * S_];                        // 1/rowsum

// ---------------------------------------------------------------------------
// PTX helpers
// ---------------------------------------------------------------------------
__device__ __forceinline__ void ldsm4(uint32_t addr, uint32_t* r) {
    asm volatile("ldmatrix.sync.aligned.m8n8.x4.shared.b16 {%0,%1,%2,%3}, [%4];"
        : "=r"(r[0]), "=r"(r[1]), "=r"(r[2]), "=r"(r[3]) : "r"(addr));
}
__device__ __forceinline__ void ldsm4t(uint32_t addr, uint32_t* r) {
    asm volatile("ldmatrix.sync.aligned.m8n8.x4.trans.shared.b16 {%0,%1,%2,%3}, [%4];"
        : "=r"(r[0]), "=r"(r[1]), "=r"(r[2]), "=r"(r[3]) : "r"(addr));
}
__device__ __forceinline__ void mma_f16(float* c, const uint32_t* a, uint32_t b0, uint32_t b1) {
    asm volatile("mma.sync.aligned.m16n8k16.row.col.f32.f16.f16.f32 "
        "{%0,%1,%2,%3}, {%4,%5,%6,%7}, {%8,%9}, {%0,%1,%2,%3};"
        : "+f"(c[0]), "+f"(c[1]), "+f"(c[2]), "+f"(c[3])
        : "r"(a[0]), "r"(a[1]), "r"(a[2]), "r"(a[3]), "r"(b0), "r"(b1));
}
__device__ __forceinline__ uint32_t sptr(const void* p) {
    return (uint32_t)__cvta_generic_to_shared(p);
}
__device__ __forceinline__ void cpa16(uint32_t s, const void* g) {
    asm volatile("cp.async.cg.shared.global [%0], [%1], 16;" :: "r"(s), "l"(g));
}
#define CPA_COMMIT() asm volatile("cp.async.commit_group;" ::: "memory")
#define CPA_WAIT(n)  asm volatile("cp.async.wait_group %0;" :: "n"(n) : "memory")

// ---------------------------------------------------------------------------
// Splits
// ---------------------------------------------------------------------------
__global__ __launch_bounds__(256) void split_a16(
    const float* q, const float* k, const float* v,
    __half* q16, __half* k16, __half* v16, int n4)
{
    int i = blockIdx.x * blockDim.x + threadIdx.x;
    if (i >= n4) return;
    const int z = blockIdx.y;
    const float* x = (z == 0) ? q : (z == 1) ? k : v;
    __half* o = (z == 0) ? q16 : (z == 1) ? k16 : v16;
    float4 val = ((const float4*)x)[i];
    ((__half2*)o)[2 * i]     = __floats2half2_rn(val.x, val.y);
    ((__half2*)o)[2 * i + 1] = __floats2half2_rn(val.z, val.w);
}

__global__ __launch_bounds__(256) void split_w16(
    const float* w0, const float* w1, const float* w2, const float* w3,
    __half* hi, __half* lo, int n4)
{
    int i = blockIdx.x * blockDim.x + threadIdx.x;
    if (i >= n4) return;
    const int z = blockIdx.y;
    const float* x = (z == 0) ? w0 : (z == 1) ? w1 : (z == 2) ? w2 : w3;
    __half* ho = hi + (size_t)z * D_ * D_;
    __half* lo_ = lo + (size_t)z * D_ * D_;
    float4 v = ((const float4*)x)[i];
    __half h0 = __float2half_rn(v.x), h1 = __float2half_rn(v.y);
    __half h2 = __float2half_rn(v.z), h3 = __float2half_rn(v.w);
    __half2 ph0; ph0.x = h0; ph0.y = h1;
    __half2 ph1; ph1.x = h2; ph1.y = h3;
    __half2 pl0, pl1;
    pl0.x = __float2half_rn(v.x - __half2float(h0));
    pl0.y = __float2half_rn(v.y - __half2float(h1));
    pl1.x = __float2half_rn(v.z - __half2float(h2));
    pl1.y = __float2half_rn(v.w - __half2float(h3));
    ((__half2*)ho)[2 * i]      = ph0;
    ((__half2*)ho)[2 * i + 1]  = ph1;
    ((__half2*)lo_)[2 * i]     = pl0;
    ((__half2*)lo_)[2 * i + 1] = pl1;
}

// ---------------------------------------------------------------------------
// fp16 2-product GEMM: C = A @ W^T, A single fp16, W = Wh + Wl fp16.
// 128x128 tile, BK=32, 256 thr, 2 CTAs/SM. smem 61440 B.
// MODE 1: merged QKV. wsel 0 (Q): single fp16 out. wsel 1/2 (K/V): hi/lo out.
// MODE 0: out-proj; fp32 row-major out.
// ---------------------------------------------------------------------------
template <int MODE>
__global__ __launch_bounds__(256, 2) void mm_tc(
    const __half* __restrict__ A0, const __half* __restrict__ A1,
    const __half* __restrict__ A2,
    const __half* __restrict__ Wbh, const __half* __restrict__ Wbl,
    float* __restrict__ Cf,
    __half* __restrict__ Oq,
    __half* __restrict__ Okh, __half* __restrict__ Okl,
    __half* __restrict__ Ovh, __half* __restrict__ Ovl)
{
    extern __shared__ __half dsm[];

    const int tid = threadIdx.x, lane = tid & 31, wid = tid >> 5;
    const int wsel = (MODE == 1) ? (blockIdx.x >> 3) : 0;
    const int bn = (MODE == 1) ? ((blockIdx.x & 7) * 128) : (blockIdx.x * 128);
    const int bm = blockIdx.y * 128;
    const int wm = (wid >> 2) * 64, wn = (wid & 3) * 32;

    const __half* A = (wsel == 0) ? A0 : (wsel == 1) ? A1 : A2;
    const __half* Whi = Wbh + (size_t)wsel * D_ * D_;
    const __half* Wlo = Wbl + (size_t)wsel * D_ * D_;
    __half* Ohi = (wsel == 1) ? Okh : Ovh;
    __half* Olo = (wsel == 1) ? Okl : Ovl;

    float acc[4][4][4];
#pragma unroll
    for (int a = 0; a < 4; ++a)
#pragma unroll
        for (int b = 0; b < 4; ++b)
#pragma unroll
            for (int c = 0; c < 4; ++c) acc[a][b][c] = 0.f;

    const int grp = lane >> 3, koff = (grp & 1) << 3, nb = (grp >> 1) << 3, nr = lane & 7;

#define MM_LOAD(it, st) do {                                                     \
    const int _k0 = (it) * 32;                                                   \
    __half* _bb = dsm + (st) * 15360;                                            \
    _Pragma("unroll")                                                            \
    for (int _t = 0; _t < 2; ++_t) {                                             \
        const int _idx = tid + _t * 256;                                         \
        const int _row = _idx >> 2, _c8 = (_idx & 3) << 3;                       \
        const int _so = _row * 40 + _c8;                                         \
        cpa16(sptr(_bb + _so),         A   + (size_t)(bm + _row) * D_ + _k0 + _c8); \
        cpa16(sptr(_bb + 5120 + _so),  Whi + (size_t)(bn + _row) * D_ + _k0 + _c8); \
        cpa16(sptr(_bb + 10240 + _so), Wlo + (size_t)(bn + _row) * D_ + _k0 + _c8); \
    } } while (0)

    MM_LOAD(0, 0); CPA_COMMIT();

    for (int it = 0; it < 32; ++it) {
        if (it + 1 < 32) { MM_LOAD(it + 1, (it + 1) & 1); CPA_COMMIT(); CPA_WAIT(1); }
        else             { CPA_WAIT(0); }
        __syncthreads();

        const __half* sA  = dsm + (it & 1) * 15360;
        const __half* sWh = sA + 5120;
        const __half* sWl = sA + 10240;

#pragma unroll
        for (int kk = 0; kk < 2; ++kk) {
            uint32_t aF[4][4];
#pragma unroll
            for (int mt = 0; mt < 4; ++mt) {
                const int r = wm + mt * 16 + (lane & 15);
                const int c = kk * 16 + ((lane >> 4) << 3);
                ldsm4(sptr(sA + r * 40 + c), aF[mt]);
            }
#pragma unroll
            for (int np = 0; np < 2; ++np) {
                uint32_t bH[4], bL[4];
                const int n = wn + np * 16 + nb + nr;
                const int c = kk * 16 + koff;
                ldsm4(sptr(sWh + n * 40 + c), bH);
                ldsm4(sptr(sWl + n * 40 + c), bL);
#pragma unroll
                for (int mt = 0; mt < 4; ++mt)
#pragma unroll
                    for (int j = 0; j < 2; ++j) {
                        const int nt = np * 2 + j;
                        mma_f16(acc[mt][nt], aF[mt], bH[2 * j], bH[2 * j + 1]);
                        mma_f16(acc[mt][nt], aF[mt], bL[2 * j], bL[2 * j + 1]);
                    }
            }
        }
        __syncthreads();
    }
#undef MM_LOAD

#pragma unroll
    for (int mt = 0; mt < 4; ++mt)
#pragma unroll
        for (int nt = 0; nt < 4; ++nt) {
            const float* c = acc[mt][nt];
            const int n = bn + wn + nt * 8 + ((lane & 3) << 1);
#pragma unroll
            for (int hf = 0; hf < 2; ++hf) {
                const int m = bm + wm + mt * 16 + (lane >> 2) + hf * 8;
                const float x0 = c[hf * 2], x1 = c[hf * 2 + 1];
                if (MODE == 0) {
                    *(float2*)(Cf + (size_t)m * D_ + n) = make_float2(x0, x1);
                } else {
                    const int b = m >> 11, s = m & (S_ - 1);
                    const int h = n >> 6, dk = n & (DK_ - 1);
                    const size_t o = (((size_t)(b * H_ + h) * S_ + s) << 6) + dk;
                    if (wsel == 0) {
                        *(__half2*)(Oq + o) = __floats2half2_rn(x0, x1);
                    } else {
                        __half h0 = __float2half_rn(x0), h1 = __float2half_rn(x1);
                        __half2 ph; ph.x = h0; ph.y = h1;
                        __half2 pl;
                        pl.x = __float2half_rn(x0 - __half2float(h0));
                        pl.y = __float2half_rn(x1 - __half2float(h1));
                        *(__half2*)(Ohi + o) = ph;
                        *(__half2*)(Olo + o) = pl;
                    }
                }
            }
        }
}

// ---------------------------------------------------------------------------
// Single-pass attention, fp16 2-product: scores = Q16 x (Kh+Kl),
// O = E16 x (Vh+Vl). q-tile 128, 2 CTAs/SM.
// smem halves: Q@0 (9216); stage st @9216+st*18432: Kh+0, Kl+4608,
// Vh+9216, Vl+13824. Total 46080 halves = 92160 B.
// ---------------------------------------------------------------------------
__global__ __launch_bounds__(256, 2) void attn_single(float* __restrict__ attn,
                                                      int qt_base)
{
    extern __shared__ __half sm[];
    __half* Qs = sm;

    const int qt = qt_base + (int)gridDim.x - 1 - (int)blockIdx.x;
    const int bh = blockIdx.y;
    const int tid = threadIdx.x, lane = tid & 31, wid = tid >> 5;
    const int q0 = qt * 128;
    const int nkt = 2 * qt + 2;
    const int grp = lane >> 3, koff = (grp & 1) << 3, nb = (grp >> 1) << 3, nr = lane & 7;
    const int wrow = wid * 16;

    // ---- load Q tile (128 x 64 single fp16) ----
#pragma unroll
    for (int t = 0; t < 4; ++t) {
        const int idx = tid + t * 256;               // 0..1023 uint4 slots
        const int r = idx >> 3, c8 = (idx & 7) << 3;
        *(uint4*)&Qs[r * 72 + c8] =
            *(const uint4*)(g_Q16 + (((size_t)bh * S_ + q0 + r) << 6) + c8);
    }

    const int lrow = lane >> 2;

#define AT_LOADKV(kt, st) do {                                                   \
    __half* _bb = sm + 9216 + (st) * 18432;                                      \
    _Pragma("unroll")                                                            \
    for (int _t = 0; _t < 2; ++_t) {                                             \
        const int _idx = tid + _t * 256;                                         \
        const int _r = _idx >> 3, _c8 = (_idx & 7) << 3;                         \
        const size_t _g = (((size_t)bh * S_ + (kt) * 64 + _r) << 6) + _c8;       \
        const int _so = _r * 72 + _c8;                                           \
        cpa16(sptr(_bb + _so),         g_K16h + _g);                             \
        cpa16(sptr(_bb + 4608 + _so),  g_K16l + _g);                             \
        cpa16(sptr(_bb + 9216 + _so),  g_V16h + _g);                             \
        cpa16(sptr(_bb + 13824 + _so), g_V16l + _g);                             \
    } } while (0)

    float accO[8][4];
#pragma unroll
    for (int b = 0; b < 8; ++b)
#pragma unroll
        for (int c = 0; c < 4; ++c) accO[b][c] = 0.f;
    float lsum[2] = {0.f, 0.f};

    AT_LOADKV(0, 0); CPA_COMMIT();
    for (int kt = 0; kt < nkt; ++kt) {
        if (kt + 1 < nkt) { AT_LOADKV(kt + 1, (kt + 1) & 1); CPA_COMMIT(); CPA_WAIT(1); }
        else              { CPA_WAIT(0); }
        __syncthreads();

        const __half* Kh = sm + 9216 + (kt & 1) * 18432;
        const __half* Kl = Kh + 4608;
        const __half* Vh = Kh + 9216;
        const __half* Vl = Kh + 13824;

        // ---- scores: 16x64 per warp, 2-product ----
        float acc[8][4];
#pragma unroll
        for (int b = 0; b < 8; ++b)
#pragma unroll
            for (int c = 0; c < 4; ++c) acc[b][c] = 0.f;

#pragma unroll
        for (int kk = 0; kk < 4; ++kk) {
            uint32_t aF[4];
            {
                const int r = wrow + (lane & 15);
                const int c = kk * 16 + ((lane >> 4) << 3);
                ldsm4(sptr(Qs + r * 72 + c), aF);
            }
#pragma unroll
            for (int np = 0; np < 4; ++np) {
                uint32_t bH[4], bL[4];
                const int n = np * 16 + nb + nr;
                const int cc = kk * 16 + koff;
                ldsm4(sptr(Kh + n * 72 + cc), bH);
                ldsm4(sptr(Kl + n * 72 + cc), bL);
#pragma unroll
                for (int j = 0; j < 2; ++j) {
                    const int nt = np * 2 + j;
                    mma_f16(acc[nt], aF, bH[2 * j], bH[2 * j + 1]);
                    mma_f16(acc[nt], aF, bL[2 * j], bL[2 * j + 1]);
                }
            }
        }

        const bool need_mask = (kt * 64 + 63) > (q0 + wrow);

        // ---- exp + E write + l accum + pack(single fp16) + PV (2-product) ----
#pragma unroll
        for (int t = 0; t < 4; ++t) {
            uint32_t pE[4];
#pragma unroll
            for (int g = 0; g < 2; ++g) {
                const int nt = 2 * t + g;
                const int kc = kt * 64 + nt * 8 + ((lane & 3) << 1);
#pragma unroll
                for (int hf = 0; hf < 2; ++hf) {
                    const int qr = q0 + wrow + lrow + hf * 8;
                    float x0 = acc[nt][hf * 2] * 0.125f;
                    float x1 = acc[nt][hf * 2 + 1] * 0.125f;
                    if (need_mask) {
                        if (kc > qr)     x0 = -1e30f;
                        if (kc + 1 > qr) x1 = -1e30f;
                    }
                    const float e0 = __expf(x0);
                    const float e1 = __expf(x1);
                    lsum[hf] += e0 + e1;
                    float* dst = attn + ((size_t)bh * S_ + qr) * S_ + kc;
                    *(float2*)dst = make_float2(e0, e1);
                    __half2 hp = __floats2half2_rn(e0, e1);
                    pE[g * 2 + hf] = *(uint32_t*)&hp;
                }
            }
#pragma unroll
            for (int np = 0; np < 4; ++np) {
                uint32_t bH[4], bL[4];
                const int kr = t * 16 + koff + nr;
                const int nc = np * 16 + nb;
                ldsm4t(sptr(Vh + kr * 72 + nc), bH);
                ldsm4t(sptr(Vl + kr * 72 + nc), bL);
#pragma unroll
                for (int j = 0; j < 2; ++j) {
                    const int nt = np * 2 + j;
                    mma_f16(accO[nt], pE, bH[2 * j], bH[2 * j + 1]);
                    mma_f16(accO[nt], pE, bL[2 * j], bL[2 * j + 1]);
                }
            }
        }
        __syncthreads();
    }
#undef AT_LOADKV

    float il[2];
#pragma unroll
    for (int hf = 0; hf < 2; ++hf) {
        float l = lsum[hf];
#pragma unroll
        for (int off = 1; off <= 2; off <<= 1)
            l += __shfl_xor_sync(0xffffffffu, l, off);
        il[hf] = 1.f / l;
    }

    if ((lane & 3) == 0) {
        g_linv[(size_t)bh * S_ + q0 + wrow + lrow]     = il[0];
        g_linv[(size_t)bh * S_ + q0 + wrow + lrow + 8] = il[1];
    }

    // ---- write O = accO / l as single fp16 to g_C16 [B,S,D] ----
    const int b = bh >> 4, h = bh & (H_ - 1);
#pragma unroll
    for (int nt = 0; nt < 8; ++nt) {
        const int d = h * DK_ + nt * 8 + ((lane & 3) << 1);
#pragma unroll
        for (int hf = 0; hf < 2; ++hf) {
            const int s = q0 + wrow + lrow + hf * 8;
            const float ii = il[hf];
            const size_t o = ((size_t)b * S_ + s) * D_ + d;
            *(__half2*)(g_C16 + o) =
                __floats2half2_rn(accO[nt][hf * 2] * ii, accO[nt][hf * 2 + 1] * ii);
        }
    }
}

// ---------------------------------------------------------------------------
// zero_fill: attn[row, c] = 0 for c >= (qt+1)*128. No data deps.
// ---------------------------------------------------------------------------
__global__ __launch_bounds__(256) void zero_fill(float* __restrict__ attn)
{
    const int row = blockIdx.x;                  // 0..1919 (tiles 0..14)
    const int bh = blockIdx.y;
    const int c0 = ((row >> 7) + 1) * 128;
    float* p = attn + ((size_t)bh * S_ + row) * S_;
    const int tid = threadIdx.x;
    const float4 z = make_float4(0.f, 0.f, 0.f, 0.f);
    for (int i = (c0 >> 2) + tid; i < S_ / 4; i += 256)
        ((float4*)p)[i] = z;
}

// ---------------------------------------------------------------------------
// scale_rows: attn[row, c] *= linv for c < (qt+1)*128. row = row_off + bx.
// ---------------------------------------------------------------------------
__global__ __launch_bounds__(256) void scale_rows(float* __restrict__ attn,
                                                  int row_off)
{
    const int row = row_off + blockIdx.x;
    const int bh = blockIdx.y;
    const float s = g_linv[(size_t)bh * S_ + row];
    float* p = attn + ((size_t)bh * S_ + row) * S_;
    const int n4 = ((row >> 7) + 1) * 32;
    const int tid = threadIdx.x;
    for (int i = tid; i < n4; i += 256) {
        float4 v = ((const float4*)p)[i];
        v.x *= s; v.y *= s; v.z *= s; v.w *= s;
        ((float4*)p)[i] = v;
    }
}

// ---------------------------------------------------------------------------
// Launch (pipeline structure unchanged from R14)
// ---------------------------------------------------------------------------
extern "C" void kernel_launch(void* const* d_in, const int* in_sizes, int n_in,
                              void* d_out, int out_size)
{
    const float* q = (const float*)d_in[0];
    const float* k = (const float*)d_in[1];
    const float* v = (const float*)d_in[2];
    const float* W[4] = { (const float*)d_in[4], (const float*)d_in[5],
                          (const float*)d_in[6], (const float*)d_in[7] };

    float* out  = (float*)d_out;
    float* attn = out + (size_t)B_ * S_ * D_;

    __half *q16, *k16, *v16, *w16h, *w16l, *C16;
    __half *Q16, *K16h, *K16l, *V16h, *V16l;
    cudaGetSymbolAddress((void**)&q16, g_q16);
    cudaGetSymbolAddress((void**)&k16, g_k16);
    cudaGetSymbolAddress((void**)&v16, g_v16);
    cudaGetSymbolAddress((void**)&w16h, g_w16h);
    cudaGetSymbolAddress((void**)&w16l, g_w16l);
    cudaGetSymbolAddress((void**)&C16, g_C16);
    cudaGetSymbolAddress((void**)&Q16, g_Q16);
    cudaGetSymbolAddress((void**)&K16h, g_K16h);
    cudaGetSymbolAddress((void**)&K16l, g_K16l);
    cudaGetSymbolAddress((void**)&V16h, g_V16h);
    cudaGetSymbolAddress((void**)&V16l, g_V16l);

    static cudaStream_t s_side = nullptr;
    static cudaEvent_t evFork0 = nullptr, evFork1 = nullptr, evFork2 = nullptr,
                       evJoin = nullptr;
    static bool attr_set = false;
    if (!attr_set) {
        cudaFuncSetAttribute(mm_tc<0>, cudaFuncAttributeMaxDynamicSharedMemorySize, 61440);
        cudaFuncSetAttribute(mm_tc<1>, cudaFuncAttributeMaxDynamicSharedMemorySize, 61440);
        cudaFuncSetAttribute(attn_single, cudaFuncAttributeMaxDynamicSharedMemorySize, 92160);
        cudaStreamCreateWithFlags(&s_side, cudaStreamNonBlocking);
        cudaEventCreateWithFlags(&evFork0, cudaEventDisableTiming);
        cudaEventCreateWithFlags(&evFork1, cudaEventDisableTiming);
        cudaEventCreateWithFlags(&evFork2, cudaEventDisableTiming);
        cudaEventCreateWithFlags(&evJoin, cudaEventDisableTiming);
        attr_set = true;
    }

    const int n4x = MM_ * D_ / 4;
    const int n4w = D_ * D_ / 4;

    // fork 0: zero-fill (no data deps) on side stream from t=0
    cudaEventRecord(evFork0, 0);
    cudaStreamWaitEvent(s_side, evFork0, 0);
    dim3 gZF(15 * 128, B_ * H_);
    zero_fill<<<gZF, 256, 0, s_side>>>(attn);

    dim3 gSa((n4x + 255) / 256, 3);
    split_a16<<<gSa, 256>>>(q, k, v, q16, k16, v16, n4x);
    dim3 gSw((n4w + 255) / 256, 4);
    split_w16<<<gSw, 256>>>(W[0], W[1], W[2], W[3], w16h, w16l, n4w);

    dim3 gQKV(24, MM_ / 128);       // (24, 64)
    mm_tc<1><<<gQKV, 256, 61440>>>(q16, k16, v16, w16h, w16l,
                                   nullptr, Q16, K16h, K16l, V16h, V16l);

    // attention part A: big tiles qt 8..15
    dim3 gA(8, B_ * H_);
    attn_single<<<gA, 256, 92160>>>(attn, 8);

    // fork 1: scale rows 1024..2047 on side while small tiles run on main
    cudaEventRecord(evFork1, 0);
    cudaStreamWaitEvent(s_side, evFork1, 0);
    dim3 gSRa(1024, B_ * H_);
    scale_rows<<<gSRa, 256, 0, s_side>>>(attn, 1024);

    // attention part B: small tiles qt 0..7
    attn_single<<<gA, 256, 92160>>>(attn, 0);

    // fork 2: scale rows 0..1023 on side while out-proj runs on main
    cudaEventRecord(evFork2, 0);
    cudaStreamWaitEvent(s_side, evFork2, 0);
    dim3 gSRb(1024, B_ * H_);
    scale_rows<<<gSRb, 256, 0, s_side>>>(attn, 0);

    dim3 gO(8, MM_ / 128);          // (8, 64)
    mm_tc<0><<<gO, 256, 61440>>>(C16, nullptr, nullptr,
                                 w16h + 3 * (size_t)D_ * D_, w16l + 3 * (size_t)D_ * D_,
                                 out, nullptr, nullptr, nullptr, nullptr, nullptr);

    // join
    cudaEventRecord(evJoin, s_side);
    cudaStreamWaitEvent(0, evJoin, 0);
}

// round 17
// speedup vs baseline: 4.1200x; 1.0921x over previous
#include <cuda_runtime.h>
#include <cuda_bf16.h>
#include <cuda_fp16.h>
#include <cstdint>

#define B_  4
#define S_  2048
#define D_  1024
#define H_  16
#define DK_ 64
#define MM_ (B_ * S_)          // 8192

// ---------------------------------------------------------------------------
// Scratch (device globals)
// ---------------------------------------------------------------------------
__device__ __half g_q16[MM_ * D_], g_k16[MM_ * D_], g_v16[MM_ * D_];
__device__ __half g_w16h[4][D_ * D_], g_w16l[4][D_ * D_];
__device__ __half g_C16[MM_ * D_];                            // context [B,S,D]
__device__ __half g_Q16[MM_ * D_];                            // [B,H,S,DK] single
__device__ __half g_K16[MM_ * D_];                            // single
__device__ __half g_V16[MM_ * D_];                            // single
__device__ float g_linv[B_ * H_ * S_];                        // 1/rowsum

// ---------------------------------------------------------------------------
// PTX helpers
// ---------------------------------------------------------------------------
__device__ __forceinline__ void ldsm4(uint32_t addr, uint32_t* r) {
    asm volatile("ldmatrix.sync.aligned.m8n8.x4.shared.b16 {%0,%1,%2,%3}, [%4];"
        : "=r"(r[0]), "=r"(r[1]), "=r"(r[2]), "=r"(r[3]) : "r"(addr));
}
__device__ __forceinline__ void ldsm4t(uint32_t addr, uint32_t* r) {
    asm volatile("ldmatrix.sync.aligned.m8n8.x4.trans.shared.b16 {%0,%1,%2,%3}, [%4];"
        : "=r"(r[0]), "=r"(r[1]), "=r"(r[2]), "=r"(r[3]) : "r"(addr));
}
__device__ __forceinline__ void mma_f16(float* c, const uint32_t* a, uint32_t b0, uint32_t b1) {
    asm volatile("mma.sync.aligned.m16n8k16.row.col.f32.f16.f16.f32 "
        "{%0,%1,%2,%3}, {%4,%5,%6,%7}, {%8,%9}, {%0,%1,%2,%3};"
        : "+f"(c[0]), "+f"(c[1]), "+f"(c[2]), "+f"(c[3])
        : "r"(a[0]), "r"(a[1]), "r"(a[2]), "r"(a[3]), "r"(b0), "r"(b1));
}
__device__ __forceinline__ uint32_t sptr(const void* p) {
    return (uint32_t)__cvta_generic_to_shared(p);
}
__device__ __forceinline__ void cpa16(uint32_t s, const void* g) {
    asm volatile("cp.async.cg.shared.global [%0], [%1], 16;" :: "r"(s), "l"(g));
}
#define CPA_COMMIT() asm volatile("cp.async.commit_group;" ::: "memory")
#define CPA_WAIT(n)  asm volatile("cp.async.wait_group %0;" :: "n"(n) : "memory")

// ---------------------------------------------------------------------------
// Splits
// ---------------------------------------------------------------------------
__global__ __launch_bounds__(256) void split_a16(
    const float* q, const float* k, const float* v,
    __half* q16, __half* k16, __half* v16, int n4)
{
    int i = blockIdx.x * blockDim.x + threadIdx.x;
    if (i >= n4) return;
    const int z = blockIdx.y;
    const float* x = (z == 0) ? q : (z == 1) ? k : v;
    __half* o = (z == 0) ? q16 : (z == 1) ? k16 : v16;
    float4 val = ((const float4*)x)[i];
    ((__half2*)o)[2 * i]     = __floats2half2_rn(val.x, val.y);
    ((__half2*)o)[2 * i + 1] = __floats2half2_rn(val.z, val.w);
}

__global__ __launch_bounds__(256) void split_w16(
    const float* w0, const float* w1, const float* w2, const float* w3,
    __half* hi, __half* lo, int n4)
{
    int i = blockIdx.x * blockDim.x + threadIdx.x;
    if (i >= n4) return;
    const int z = blockIdx.y;
    const float* x = (z == 0) ? w0 : (z == 1) ? w1 : (z == 2) ? w2 : w3;
    __half* ho = hi + (size_t)z * D_ * D_;
    __half* lo_ = lo + (size_t)z * D_ * D_;
    float4 v = ((const float4*)x)[i];
    __half h0 = __float2half_rn(v.x), h1 = __float2half_rn(v.y);
    __half h2 = __float2half_rn(v.z), h3 = __float2half_rn(v.w);
    __half2 ph0; ph0.x = h0; ph0.y = h1;
    __half2 ph1; ph1.x = h2; ph1.y = h3;
    __half2 pl0, pl1;
    pl0.x = __float2half_rn(v.x - __half2float(h0));
    pl0.y = __float2half_rn(v.y - __half2float(h1));
    pl1.x = __float2half_rn(v.z - __half2float(h2));
    pl1.y = __float2half_rn(v.w - __half2float(h3));
    ((__half2*)ho)[2 * i]      = ph0;
    ((__half2*)ho)[2 * i + 1]  = ph1;
    ((__half2*)lo_)[2 * i]     = pl0;
    ((__half2*)lo_)[2 * i + 1] = pl1;
}

// ---------------------------------------------------------------------------
// fp16 2-product GEMM: C = A @ W^T, A single fp16, W = Wh + Wl fp16.
// 128x128 tile, BK=32, 256 thr, 2 CTAs/SM. smem 61440 B.
// MODE 1: merged QKV; single fp16 out at [B,H,S,DK].
// MODE 0: out-proj; fp32 row-major out.
// ---------------------------------------------------------------------------
template <int MODE>
__global__ __launch_bounds__(256, 2) void mm_tc(
    const __half* __restrict__ A0, const __half* __restrict__ A1,
    const __half* __restrict__ A2,
    const __half* __restrict__ Wbh, const __half* __restrict__ Wbl,
    float* __restrict__ Cf,
    __half* __restrict__ Oq, __half* __restrict__ Ok, __half* __restrict__ Ov)
{
    extern __shared__ __half dsm[];

    const int tid = threadIdx.x, lane = tid & 31, wid = tid >> 5;
    const int wsel = (MODE == 1) ? (blockIdx.x >> 3) : 0;
    const int bn = (MODE == 1) ? ((blockIdx.x & 7) * 128) : (blockIdx.x * 128);
    const int bm = blockIdx.y * 128;
    const int wm = (wid >> 2) * 64, wn = (wid & 3) * 32;

    const __half* A = (wsel == 0) ? A0 : (wsel == 1) ? A1 : A2;
    const __half* Whi = Wbh + (size_t)wsel * D_ * D_;
    const __half* Wlo = Wbl + (size_t)wsel * D_ * D_;
    __half* Oo = (wsel == 0) ? Oq : (wsel == 1) ? Ok : Ov;

    float acc[4][4][4];
#pragma unroll
    for (int a = 0; a < 4; ++a)
#pragma unroll
        for (int b = 0; b < 4; ++b)
#pragma unroll
            for (int c = 0; c < 4; ++c) acc[a][b][c] = 0.f;

    const int grp = lane >> 3, koff = (grp & 1) << 3, nb = (grp >> 1) << 3, nr = lane & 7;

#define MM_LOAD(it, st) do {                                                     \
    const int _k0 = (it) * 32;                                                   \
    __half* _bb = dsm + (st) * 15360;                                            \
    _Pragma("unroll")                                                            \
    for (int _t = 0; _t < 2; ++_t) {                                             \
        const int _idx = tid + _t * 256;                                         \
        const int _row = _idx >> 2, _c8 = (_idx & 3) << 3;                       \
        const int _so = _row * 40 + _c8;                                         \
        cpa16(sptr(_bb + _so),         A   + (size_t)(bm + _row) * D_ + _k0 + _c8); \
        cpa16(sptr(_bb + 5120 + _so),  Whi + (size_t)(bn + _row) * D_ + _k0 + _c8); \
        cpa16(sptr(_bb + 10240 + _so), Wlo + (size_t)(bn + _row) * D_ + _k0 + _c8); \
    } } while (0)

    MM_LOAD(0, 0); CPA_COMMIT();

    for (int it = 0; it < 32; ++it) {
        if (it + 1 < 32) { MM_LOAD(it + 1, (it + 1) & 1); CPA_COMMIT(); CPA_WAIT(1); }
        else             { CPA_WAIT(0); }
        __syncthreads();

        const __half* sA  = dsm + (it & 1) * 15360;
        const __half* sWh = sA + 5120;
        const __half* sWl = sA + 10240;

#pragma unroll
        for (int kk = 0; kk < 2; ++kk) {
            uint32_t aF[4][4];
#pragma unroll
            for (int mt = 0; mt < 4; ++mt) {
                const int r = wm + mt * 16 + (lane & 15);
                const int c = kk * 16 + ((lane >> 4) << 3);
                ldsm4(sptr(sA + r * 40 + c), aF[mt]);
            }
#pragma unroll
            for (int np = 0; np < 2; ++np) {
                uint32_t bH[4], bL[4];
                const int n = wn + np * 16 + nb + nr;
                const int c = kk * 16 + koff;
                ldsm4(sptr(sWh + n * 40 + c), bH);
                ldsm4(sptr(sWl + n * 40 + c), bL);
#pragma unroll
                for (int mt = 0; mt < 4; ++mt)
#pragma unroll
                    for (int j = 0; j < 2; ++j) {
                        const int nt = np * 2 + j;
                        mma_f16(acc[mt][nt], aF[mt], bH[2 * j], bH[2 * j + 1]);
                        mma_f16(acc[mt][nt], aF[mt], bL[2 * j], bL[2 * j + 1]);
                    }
            }
        }
        __syncthreads();
    }
#undef MM_LOAD

#pragma unroll
    for (int mt = 0; mt < 4; ++mt)
#pragma unroll
        for (int nt = 0; nt < 4; ++nt) {
            const float* c = acc[mt][nt];
            const int n = bn + wn + nt * 8 + ((lane & 3) << 1);
#pragma unroll
            for (int hf = 0; hf < 2; ++hf) {
                const int m = bm + wm + mt * 16 + (lane >> 2) + hf * 8;
                const float x0 = c[hf * 2], x1 = c[hf * 2 + 1];
                if (MODE == 0) {
                    *(float2*)(Cf + (size_t)m * D_ + n) = make_float2(x0, x1);
                } else {
                    const int b = m >> 11, s = m & (S_ - 1);
                    const int h = n >> 6, dk = n & (DK_ - 1);
                    const size_t o = (((size_t)(b * H_ + h) * S_ + s) << 6) + dk;
                    *(__half2*)(Oo + o) = __floats2half2_rn(x0, x1);
                }
            }
        }
}

// ---------------------------------------------------------------------------
// Single-pass attention, all-single fp16: scores = Q16 x K16, O = E16 x V16.
// q-tile 128, 2 CTAs/SM.
// smem halves: Q@0 (9216); stage st @9216+st*9216: K+0, V+4608.
// Total 27648 halves = 55296 B.
// ---------------------------------------------------------------------------
__global__ __launch_bounds__(256, 2) void attn_single(float* __restrict__ attn,
                                                      int qt_base)
{
    extern __shared__ __half sm[];
    __half* Qs = sm;

    const int qt = qt_base + (int)gridDim.x - 1 - (int)blockIdx.x;
    const int bh = blockIdx.y;
    const int tid = threadIdx.x, lane = tid & 31, wid = tid >> 5;
    const int q0 = qt * 128;
    const int nkt = 2 * qt + 2;
    const int grp = lane >> 3, koff = (grp & 1) << 3, nb = (grp >> 1) << 3, nr = lane & 7;
    const int wrow = wid * 16;

    // ---- load Q tile (128 x 64 single fp16) ----
#pragma unroll
    for (int t = 0; t < 4; ++t) {
        const int idx = tid + t * 256;               // 0..1023 uint4 slots
        const int r = idx >> 3, c8 = (idx & 7) << 3;
        *(uint4*)&Qs[r * 72 + c8] =
            *(const uint4*)(g_Q16 + (((size_t)bh * S_ + q0 + r) << 6) + c8);
    }

    const int lrow = lane >> 2;

#define AT_LOADKV(kt, st) do {                                                   \
    __half* _bb = sm + 9216 + (st) * 9216;                                       \
    _Pragma("unroll")                                                            \
    for (int _t = 0; _t < 2; ++_t) {                                             \
        const int _idx = tid + _t * 256;                                         \
        const int _r = _idx >> 3, _c8 = (_idx & 7) << 3;                         \
        const size_t _g = (((size_t)bh * S_ + (kt) * 64 + _r) << 6) + _c8;       \
        const int _so = _r * 72 + _c8;                                           \
        cpa16(sptr(_bb + _so),        g_K16 + _g);                               \
        cpa16(sptr(_bb + 4608 + _so), g_V16 + _g);                               \
    } } while (0)

    float accO[8][4];
#pragma unroll
    for (int b = 0; b < 8; ++b)
#pragma unroll
        for (int c = 0; c < 4; ++c) accO[b][c] = 0.f;
    float lsum[2] = {0.f, 0.f};

    AT_LOADKV(0, 0); CPA_COMMIT();
    for (int kt = 0; kt < nkt; ++kt) {
        if (kt + 1 < nkt) { AT_LOADKV(kt + 1, (kt + 1) & 1); CPA_COMMIT(); CPA_WAIT(1); }
        else              { CPA_WAIT(0); }
        __syncthreads();

        const __half* Ks = sm + 9216 + (kt & 1) * 9216;
        const __half* Vs = Ks + 4608;

        // ---- scores: 16x64 per warp, single product ----
        float acc[8][4];
#pragma unroll
        for (int b = 0; b < 8; ++b)
#pragma unroll
            for (int c = 0; c < 4; ++c) acc[b][c] = 0.f;

#pragma unroll
        for (int kk = 0; kk < 4; ++kk) {
            uint32_t aF[4];
            {
                const int r = wrow + (lane & 15);
                const int c = kk * 16 + ((lane >> 4) << 3);
                ldsm4(sptr(Qs + r * 72 + c), aF);
            }
#pragma unroll
            for (int np = 0; np < 4; ++np) {
                uint32_t bF[4];
                const int n = np * 16 + nb + nr;
                const int cc = kk * 16 + koff;
                ldsm4(sptr(Ks + n * 72 + cc), bF);
#pragma unroll
                for (int j = 0; j < 2; ++j)
                    mma_f16(acc[np * 2 + j], aF, bF[2 * j], bF[2 * j + 1]);
            }
        }

        const bool need_mask = (kt * 64 + 63) > (q0 + wrow);

        // ---- exp + E write + l accum + pack + PV (single product) ----
#pragma unroll
        for (int t = 0; t < 4; ++t) {
            uint32_t pE[4];
#pragma unroll
            for (int g = 0; g < 2; ++g) {
                const int nt = 2 * t + g;
                const int kc = kt * 64 + nt * 8 + ((lane & 3) << 1);
#pragma unroll
                for (int hf = 0; hf < 2; ++hf) {
                    const int qr = q0 + wrow + lrow + hf * 8;
                    float x0 = acc[nt][hf * 2] * 0.125f;
                    float x1 = acc[nt][hf * 2 + 1] * 0.125f;
                    if (need_mask) {
                        if (kc > qr)     x0 = -1e30f;
                        if (kc + 1 > qr) x1 = -1e30f;
                    }
                    const float e0 = __expf(x0);
                    const float e1 = __expf(x1);
                    lsum[hf] += e0 + e1;
                    float* dst = attn + ((size_t)bh * S_ + qr) * S_ + kc;
                    *(float2*)dst = make_float2(e0, e1);
                    __half2 hp = __floats2half2_rn(e0, e1);
                    pE[g * 2 + hf] = *(uint32_t*)&hp;
                }
            }
#pragma unroll
            for (int np = 0; np < 4; ++np) {
                uint32_t bF[4];
                const int kr = t * 16 + koff + nr;
                const int nc = np * 16 + nb;
                ldsm4t(sptr(Vs + kr * 72 + nc), bF);
#pragma unroll
                for (int j = 0; j < 2; ++j)
                    mma_f16(accO[np * 2 + j], pE, bF[2 * j], bF[2 * j + 1]);
            }
        }
        __syncthreads();
    }
#undef AT_LOADKV

    float il[2];
#pragma unroll
    for (int hf = 0; hf < 2; ++hf) {
        float l = lsum[hf];
#pragma unroll
        for (int off = 1; off <= 2; off <<= 1)
            l += __shfl_xor_sync(0xffffffffu, l, off);
        il[hf] = 1.f / l;
    }

    if ((lane & 3) == 0) {
        g_linv[(size_t)bh * S_ + q0 + wrow + lrow]     = il[0];
        g_linv[(size_t)bh * S_ + q0 + wrow + lrow + 8] = il[1];
    }

    // ---- write O = accO / l as single fp16 to g_C16 [B,S,D] ----
    const int b = bh >> 4, h = bh & (H_ - 1);
#pragma unroll
    for (int nt = 0; nt < 8; ++nt) {
        const int d = h * DK_ + nt * 8 + ((lane & 3) << 1);
#pragma unroll
        for (int hf = 0; hf < 2; ++hf) {
            const int s = q0 + wrow + lrow + hf * 8;
            const float ii = il[hf];
            const size_t o = ((size_t)b * S_ + s) * D_ + d;
            *(__half2*)(g_C16 + o) =
                __floats2half2_rn(accO[nt][hf * 2] * ii, accO[nt][hf * 2 + 1] * ii);
        }
    }
}

// ---------------------------------------------------------------------------
// zero_fill: attn[row, c] = 0 for c >= (qt+1)*128. No data deps.
// ---------------------------------------------------------------------------
__global__ __launch_bounds__(256) void zero_fill(float* __restrict__ attn)
{
    const int row = blockIdx.x;                  // 0..1919 (tiles 0..14)
    const int bh = blockIdx.y;
    const int c0 = ((row >> 7) + 1) * 128;
    float* p = attn + ((size_t)bh * S_ + row) * S_;
    const int tid = threadIdx.x;
    const float4 z = make_float4(0.f, 0.f, 0.f, 0.f);
    for (int i = (c0 >> 2) + tid; i < S_ / 4; i += 256)
        ((float4*)p)[i] = z;
}

// ---------------------------------------------------------------------------
// scale_rows: attn[row, c] *= linv for c < (qt+1)*128. row = row_off + bx.
// ---------------------------------------------------------------------------
__global__ __launch_bounds__(256) void scale_rows(float* __restrict__ attn,
                                                  int row_off)
{
    const int row = row_off + blockIdx.x;
    const int bh = blockIdx.y;
    const float s = g_linv[(size_t)bh * S_ + row];
    float* p = attn + ((size_t)bh * S_ + row) * S_;
    const int n4 = ((row >> 7) + 1) * 32;
    const int tid = threadIdx.x;
    for (int i = tid; i < n4; i += 256) {
        float4 v = ((const float4*)p)[i];
        v.x *= s; v.y *= s; v.z *= s; v.w *= s;
        ((float4*)p)[i] = v;
    }
}

// ---------------------------------------------------------------------------
// Launch (pipeline structure unchanged)
// ---------------------------------------------------------------------------
extern "C" void kernel_launch(void* const* d_in, const int* in_sizes, int n_in,
                              void* d_out, int out_size)
{
    const float* q = (const float*)d_in[0];
    const float* k = (const float*)d_in[1];
    const float* v = (const float*)d_in[2];
    const float* W[4] = { (const float*)d_in[4], (const float*)d_in[5],
                          (const float*)d_in[6], (const float*)d_in[7] };

    float* out  = (float*)d_out;
    float* attn = out + (size_t)B_ * S_ * D_;

    __half *q16, *k16, *v16, *w16h, *w16l, *C16, *Q16, *K16, *V16;
    cudaGetSymbolAddress((void**)&q16, g_q16);
    cudaGetSymbolAddress((void**)&k16, g_k16);
    cudaGetSymbolAddress((void**)&v16, g_v16);
    cudaGetSymbolAddress((void**)&w16h, g_w16h);
    cudaGetSymbolAddress((void**)&w16l, g_w16l);
    cudaGetSymbolAddress((void**)&C16, g_C16);
    cudaGetSymbolAddress((void**)&Q16, g_Q16);
    cudaGetSymbolAddress((void**)&K16, g_K16);
    cudaGetSymbolAddress((void**)&V16, g_V16);

    static cudaStream_t s_side = nullptr;
    static cudaEvent_t evFork0 = nullptr, evFork1 = nullptr, evFork2 = nullptr,
                       evJoin = nullptr;
    static bool attr_set = false;
    if (!attr_set) {
        cudaFuncSetAttribute(mm_tc<0>, cudaFuncAttributeMaxDynamicSharedMemorySize, 61440);
        cudaFuncSetAttribute(mm_tc<1>, cudaFuncAttributeMaxDynamicSharedMemorySize, 61440);
        cudaFuncSetAttribute(attn_single, cudaFuncAttributeMaxDynamicSharedMemorySize, 55296);
        cudaStreamCreateWithFlags(&s_side, cudaStreamNonBlocking);
        cudaEventCreateWithFlags(&evFork0, cudaEventDisableTiming);
        cudaEventCreateWithFlags(&evFork1, cudaEventDisableTiming);
        cudaEventCreateWithFlags(&evFork2, cudaEventDisableTiming);
        cudaEventCreateWithFlags(&evJoin, cudaEventDisableTiming);
        attr_set = true;
    }

    const int n4x = MM_ * D_ / 4;
    const int n4w = D_ * D_ / 4;

    // fork 0: zero-fill (no data deps) on side stream from t=0
    cudaEventRecord(evFork0, 0);
    cudaStreamWaitEvent(s_side, evFork0, 0);
    dim3 gZF(15 * 128, B_ * H_);
    zero_fill<<<gZF, 256, 0, s_side>>>(attn);

    dim3 gSa((n4x + 255) / 256, 3);
    split_a16<<<gSa, 256>>>(q, k, v, q16, k16, v16, n4x);
    dim3 gSw((n4w + 255) / 256, 4);
    split_w16<<<gSw, 256>>>(W[0], W[1], W[2], W[3], w16h, w16l, n4w);

    dim3 gQKV(24, MM_ / 128);       // (24, 64)
    mm_tc<1><<<gQKV, 256, 61440>>>(q16, k16, v16, w16h, w16l,
                                   nullptr, Q16, K16, V16);

    // attention part A: big tiles qt 8..15
    dim3 gA(8, B_ * H_);
    attn_single<<<gA, 256, 55296>>>(attn, 8);

    // fork 1: scale rows 1024..2047 on side while small tiles run on main
    cudaEventRecord(evFork1, 0);
    cudaStreamWaitEvent(s_side, evFork1, 0);
    dim3 gSRa(1024, B_ * H_);
    scale_rows<<<gSRa, 256, 0, s_side>>>(attn, 1024);

    // attention part B: small tiles qt 0..7
    attn_single<<<gA, 256, 55296>>>(attn, 0);

    // fork 2: scale rows 0..1023 on side while out-proj runs on main
    cudaEventRecord(evFork2, 0);
    cudaStreamWaitEvent(s_side, evFork2, 0);
    dim3 gSRb(1024, B_ * H_);
    scale_rows<<<gSRb, 256, 0, s_side>>>(attn, 0);

    dim3 gO(8, MM_ / 128);          // (8, 64)
    mm_tc<0><<<gO, 256, 61440>>>(C16, nullptr, nullptr,
                                 w16h + 3 * (size_t)D_ * D_, w16l + 3 * (size_t)D_ * D_,
                                 out, nullptr, nullptr, nullptr);

    // join
    cudaEventRecord(evJoin, s_side);
    cudaStreamWaitEvent(0, evJoin, 0);
}